// round 1
// baseline (speedup 1.0000x reference)
#include <cuda_runtime.h>
#include <cuda_bf16.h>
#include <math.h>

// ---------------------------------------------------------------------------
// LightGlue forward, fp32. L=9, D=256, H=4, HD=64, N=1024, B=4 (2 pairs).
// ---------------------------------------------------------------------------

#define LGB   4
#define LGN   1024
#define LGD   256
#define LGH   4
#define LGHD  64
#define LGL   9
#define M4    (LGB*LGN)          // 4096 rows
#define BH    (LGB*LGH)          // 16 batched heads
#define NN2   (2*1024*1024)      // scores elements (2 pairs)

// -------------------- scratch (device globals; no allocation) --------------
__device__ float g_x   [M4*LGD];
__device__ float g_qkv [M4*3*LGD];
__device__ float g_vbuf[M4*LGD];
__device__ float g_Q   [BH*LGN*LGHD];
__device__ float g_K   [BH*LGN*LGHD];
__device__ float g_V   [BH*LGN*LGHD];
__device__ float g_S   [(size_t)BH*LGN*LGN];     // 64 MB
__device__ float g_ctxh[BH*LGN*LGHD];
__device__ float g_ctx [M4*LGD];
__device__ float g_msg [M4*LGD];
__device__ float g_cat [M4*2*LGD];
__device__ float g_h1  [M4*2*LGD];
__device__ float g_h2  [M4*2*LGD];
__device__ float g_md  [M4*LGD];
__device__ float g_sim [NN2];
__device__ float g_z   [M4];
__device__ float g_lser[2*LGN];
__device__ float g_lsec[2*LGN];
__device__ int   g_m0  [LGN];
__device__ int   g_m1  [LGN];
__device__ float g_rmax[LGN];

// -------------------- generic tiled fp32 GEMM ------------------------------
// C[m,n] = alpha*( sum_k A[m,k] * (TRANSB ? B[n,k] : B[k,n]) + bias[n] ) + res[m,n]
// batched over blockIdx.z; the B operand batch index is XORed with xorB
// (xorB=4 implements the cross-attention image swap b^1 since bh=b*4+h).
template<bool TRANSB>
__global__ void __launch_bounds__(256) gemm_k(
    const float* __restrict__ A, const float* __restrict__ B, float* C,
    int M, int N, int K,
    long sA, long sB, long sC, int xorB,
    const float* __restrict__ bias, const float* res, float alpha)
{
    int bh = blockIdx.z;
    A += (long)bh * sA;
    B += (long)(bh ^ xorB) * sB;
    C += (long)bh * sC;
    if (res) res += (long)bh * sC;

    __shared__ __align__(16) float As[16][128];
    __shared__ __align__(16) float Bs[16][64];

    const int tid = threadIdx.x;
    const int tx = tid & 15, ty = tid >> 4;
    const int row0 = blockIdx.y * 128;
    const int col0 = blockIdx.x * 64;

    float acc[8][4];
#pragma unroll
    for (int i = 0; i < 8; i++)
#pragma unroll
        for (int j = 0; j < 4; j++) acc[i][j] = 0.0f;

    for (int k0 = 0; k0 < K; k0 += 16) {
        // A tile: 128 rows x 16 k, as As[k][m]
#pragma unroll
        for (int l = 0; l < 2; l++) {
            int v = tid + 256 * l;
            int r = v >> 2;
            int kk = (v & 3) * 4;
            float4 a = *reinterpret_cast<const float4*>(&A[(long)(row0 + r) * K + k0 + kk]);
            As[kk + 0][r] = a.x; As[kk + 1][r] = a.y;
            As[kk + 2][r] = a.z; As[kk + 3][r] = a.w;
        }
        if (TRANSB) {
            int n = tid >> 2;
            int kk = (tid & 3) * 4;
            float4 b = *reinterpret_cast<const float4*>(&B[(long)(col0 + n) * K + k0 + kk]);
            Bs[kk + 0][n] = b.x; Bs[kk + 1][n] = b.y;
            Bs[kk + 2][n] = b.z; Bs[kk + 3][n] = b.w;
        } else {
            int kk = tid >> 4;
            int n4 = (tid & 15) * 4;
            float4 b = *reinterpret_cast<const float4*>(&B[(long)(k0 + kk) * N + col0 + n4]);
            *reinterpret_cast<float4*>(&Bs[kk][n4]) = b;
        }
        __syncthreads();
#pragma unroll
        for (int kk = 0; kk < 16; kk++) {
            float a[8], b[4];
#pragma unroll
            for (int i = 0; i < 8; i++) a[i] = As[kk][ty * 8 + i];
#pragma unroll
            for (int j = 0; j < 4; j++) b[j] = Bs[kk][tx * 4 + j];
#pragma unroll
            for (int i = 0; i < 8; i++)
#pragma unroll
                for (int j = 0; j < 4; j++) acc[i][j] = fmaf(a[i], b[j], acc[i][j]);
        }
        __syncthreads();
    }

#pragma unroll
    for (int i = 0; i < 8; i++) {
        int m = row0 + ty * 8 + i;
#pragma unroll
        for (int j = 0; j < 4; j++) {
            int n = col0 + tx * 4 + j;
            float v = acc[i][j];
            if (bias) v += bias[n];
            v *= alpha;
            if (res) v += res[(long)m * N + n];
            C[(long)m * N + n] = v;
        }
    }
}

// -------------------- elementwise / reduction kernels ----------------------
__global__ void copy_k(float* dst, const float* src, int n) {
    int i = blockIdx.x * blockDim.x + threadIdx.x;
    if (i < n) dst[i] = src[i];
}

// qkv [B,N,768] interleaved (q=3d, k=3d+1, v=3d+2) -> RoPE(q,k) -> [B*H,N,64]
__global__ void rope_split_k(const float* __restrict__ qkv,
                             const float* __restrict__ kpts,
                             const float* __restrict__ Wr,
                             float* __restrict__ Q, float* __restrict__ Kh,
                             float* __restrict__ V)
{
    int t = blockIdx.x * blockDim.x + threadIdx.x;     // B*N*128 pair threads
    if (t >= LGB * LGN * 128) return;
    int p  = t & 127;
    int bn = t >> 7;
    int n  = bn & (LGN - 1);
    int b  = bn >> 10;
    int d0 = 2 * p;
    int f  = p & 31;                                    // (d0 % 64) / 2
    float kx = kpts[bn * 2 + 0], ky = kpts[bn * 2 + 1];
    float pr = kx * Wr[2 * f] + ky * Wr[2 * f + 1];
    float c = cosf(pr), s = sinf(pr);
    const float* q = qkv + (long)bn * 768;
    float q0 = q[3 * d0 + 0], q1 = q[3 * d0 + 3];
    float k0 = q[3 * d0 + 1], k1 = q[3 * d0 + 4];
    float v0 = q[3 * d0 + 2], v1 = q[3 * d0 + 5];
    int h = d0 >> 6, e0 = d0 & 63;
    long base = (((long)b * LGH + h) * LGN + n) * LGHD + e0;
    Q[base]      = c * q0 - s * q1;
    Q[base + 1]  = c * q1 + s * q0;
    Kh[base]     = c * k0 - s * k1;
    Kh[base + 1] = c * k1 + s * k0;
    V[base]      = v0;
    V[base + 1]  = v1;
}

__global__ void split_heads_k(const float* __restrict__ qk,
                              const float* __restrict__ v,
                              float* __restrict__ Q, float* __restrict__ V)
{
    int t = blockIdx.x * blockDim.x + threadIdx.x;
    if (t >= M4 * LGD) return;
    int d  = t & (LGD - 1);
    int bn = t >> 8;
    int n  = bn & (LGN - 1);
    int b  = bn >> 10;
    int h  = d >> 6, e = d & 63;
    long dst = (((long)b * LGH + h) * LGN + n) * LGHD + e;
    Q[dst] = qk[t];
    V[dst] = v[t];
}

__global__ void merge_heads_k(const float* __restrict__ ctxh, float* __restrict__ ctx)
{
    int t = blockIdx.x * blockDim.x + threadIdx.x;
    if (t >= M4 * LGD) return;
    int d  = t & (LGD - 1);
    int bn = t >> 8;
    int n  = bn & (LGN - 1);
    int b  = bn >> 10;
    int h  = d >> 6, e = d & 63;
    ctx[t] = ctxh[(((long)b * LGH + h) * LGN + n) * LGHD + e];
}

__global__ void concat_k(const float* __restrict__ x, const float* __restrict__ m,
                         float* __restrict__ cat)
{
    int t = blockIdx.x * blockDim.x + threadIdx.x;
    if (t >= M4 * 2 * LGD) return;
    int c  = t & (2 * LGD - 1);
    int bn = t >> 9;
    cat[t] = (c < LGD) ? x[(long)bn * LGD + c] : m[(long)bn * LGD + c - LGD];
}

__global__ void softmax_rows_k(float* __restrict__ S, int ncols)
{
    long row = blockIdx.x;
    float* p = S + row * (long)ncols;
    int tid = threadIdx.x;
    __shared__ float red[256];
    float m = -INFINITY;
    for (int j = tid; j < ncols; j += 256) m = fmaxf(m, p[j]);
    red[tid] = m; __syncthreads();
    for (int s = 128; s > 0; s >>= 1) {
        if (tid < s) red[tid] = fmaxf(red[tid], red[tid + s]);
        __syncthreads();
    }
    m = red[0];
    __syncthreads();
    float sum = 0.0f;
    for (int j = tid; j < ncols; j += 256) {
        float e = expf(p[j] - m);
        p[j] = e;
        sum += e;
    }
    red[tid] = sum; __syncthreads();
    for (int s = 128; s > 0; s >>= 1) {
        if (tid < s) red[tid] += red[tid + s];
        __syncthreads();
    }
    float inv = 1.0f / red[0];
    for (int j = tid; j < ncols; j += 256) p[j] *= inv;
}

// LayerNorm(512) + exact GELU
__global__ void lngelu_k(const float* __restrict__ h, const float* __restrict__ g,
                         const float* __restrict__ bb, float* __restrict__ o)
{
    long row = blockIdx.x;
    int tid = threadIdx.x;
    const float* p = h + row * 512;
    float x0 = p[tid], x1 = p[tid + 256];
    __shared__ float red[256];
    red[tid] = x0 + x1; __syncthreads();
    for (int s = 128; s > 0; s >>= 1) { if (tid < s) red[tid] += red[tid + s]; __syncthreads(); }
    float mean = red[0] * (1.0f / 512.0f);
    __syncthreads();
    red[tid] = x0 * x0 + x1 * x1; __syncthreads();
    for (int s = 128; s > 0; s >>= 1) { if (tid < s) red[tid] += red[tid + s]; __syncthreads(); }
    float var = red[0] * (1.0f / 512.0f) - mean * mean;
    float rr = rsqrtf(var + 1e-5f);
    float n0 = (x0 - mean) * rr * g[tid] + bb[tid];
    float n1 = (x1 - mean) * rr * g[tid + 256] + bb[tid + 256];
    o[row * 512 + tid]       = 0.5f * n0 * (1.0f + erff(n0 * 0.70710678118654752f));
    o[row * 512 + tid + 256] = 0.5f * n1 * (1.0f + erff(n1 * 0.70710678118654752f));
}

__global__ void z_k(const float* __restrict__ x, const float* __restrict__ w,
                    const float* __restrict__ b, float* __restrict__ z)
{
    long row = blockIdx.x;
    int tid = threadIdx.x;
    __shared__ float red[256];
    red[tid] = x[row * LGD + tid] * w[tid];
    __syncthreads();
    for (int s = 128; s > 0; s >>= 1) { if (tid < s) red[tid] += red[tid + s]; __syncthreads(); }
    if (tid == 0) z[row] = red[0] + b[0];
}

__global__ void lse_row_k(const float* __restrict__ sim, float* __restrict__ lser)
{
    long r = blockIdx.x;                         // 2048 rows
    const float* p = sim + r * LGN;
    int tid = threadIdx.x;
    __shared__ float red[256];
    float m = -INFINITY;
    for (int j = tid; j < LGN; j += 256) m = fmaxf(m, p[j]);
    red[tid] = m; __syncthreads();
    for (int s = 128; s > 0; s >>= 1) { if (tid < s) red[tid] = fmaxf(red[tid], red[tid + s]); __syncthreads(); }
    m = red[0];
    __syncthreads();
    float sum = 0.0f;
    for (int j = tid; j < LGN; j += 256) sum += expf(p[j] - m);
    red[tid] = sum; __syncthreads();
    for (int s = 128; s > 0; s >>= 1) { if (tid < s) red[tid] += red[tid + s]; __syncthreads(); }
    if (tid == 0) lser[r] = m + logf(red[0]);
}

__global__ void lse_col_k(const float* __restrict__ sim, float* __restrict__ lsec)
{
    int t = blockIdx.x * blockDim.x + threadIdx.x;   // 2048 columns
    if (t >= 2 * LGN) return;
    int p = t >> 10, j = t & (LGN - 1);
    const float* base = sim + (long)p * LGN * LGN + j;
    float m = -INFINITY, s = 0.0f;
    for (int i = 0; i < LGN; i++) {
        float v = base[(long)i * LGN];
        if (v > m) { s = s * expf(m - v) + 1.0f; m = v; }
        else s += expf(v - m);
    }
    lsec[t] = m + logf(s);
}

__device__ __forceinline__ float lsig(float t) {
    return fminf(t, 0.0f) - log1pf(expf(-fabsf(t)));
}

__global__ void scores_k(const float* __restrict__ sim, const float* __restrict__ lser,
                         const float* __restrict__ lsec, const float* __restrict__ z,
                         float* __restrict__ out)
{
    long idx = (long)blockIdx.x * 256 + threadIdx.x;
    if (idx >= (long)NN2) return;
    int j = idx & (LGN - 1);
    long r = idx >> 10;
    int i = (int)(r & (LGN - 1));
    int p = (int)(r >> 10);
    float zq = z[(2 * p) * LGN + i];
    float zk = z[(2 * p + 1) * LGN + j];
    out[idx] = 2.0f * sim[idx] - lser[p * LGN + i] - lsec[p * LGN + j] + lsig(zq) + lsig(zk);
}

__global__ void argmax_row_k(const float* __restrict__ S, float* __restrict__ rmax,
                             int* __restrict__ m0)
{
    long i = blockIdx.x;
    const float* p = S + i * LGN;
    int tid = threadIdx.x;
    float bv = -INFINITY; int bi = 0;
    for (int j = tid; j < LGN; j += 256) {
        float v = p[j];
        if (v > bv) { bv = v; bi = j; }
    }
    __shared__ float sv[256]; __shared__ int si[256];
    sv[tid] = bv; si[tid] = bi; __syncthreads();
    for (int s = 128; s > 0; s >>= 1) {
        if (tid < s) {
            float v2 = sv[tid + s]; int i2 = si[tid + s];
            if (v2 > sv[tid] || (v2 == sv[tid] && i2 < si[tid])) { sv[tid] = v2; si[tid] = i2; }
        }
        __syncthreads();
    }
    if (tid == 0) { rmax[i] = sv[0]; m0[i] = si[0]; }
}

__global__ void argmax_col_k(const float* __restrict__ S, int* __restrict__ m1)
{
    int j = blockIdx.x * blockDim.x + threadIdx.x;
    if (j >= LGN) return;
    float bv = -INFINITY; int bi = 0;
    for (int i = 0; i < LGN; i++) {
        float v = S[(long)i * LGN + j];
        if (v > bv) { bv = v; bi = i; }
    }
    m1[j] = bi;
}

__global__ void filter_k(const int* __restrict__ m0, const int* __restrict__ m1,
                         const float* __restrict__ rmax, float* __restrict__ out)
{
    __shared__ float vals[LGN];
    __shared__ float rv[LGN];
    __shared__ int   ri[LGN];
    int n = threadIdx.x;
    float ms = expf(rmax[n]);
    bool mutual = (m1[m0[n]] == n);
    vals[n] = (mutual && ms > 0.1f) ? ms : 0.0f;
    __syncthreads();
    for (int k = 0; k < 50; k++) {
        rv[n] = vals[n]; ri[n] = n; __syncthreads();
        for (int s = 512; s > 0; s >>= 1) {
            if (n < s) {
                float v2 = rv[n + s]; int i2 = ri[n + s];
                if (v2 > rv[n] || (v2 == rv[n] && i2 < ri[n])) { rv[n] = v2; ri[n] = i2; }
            }
            __syncthreads();
        }
        if (n == 0) {
            int bi = ri[0]; float bv = rv[0];
            out[NN2 + k * 3 + 0] = 0.0f;
            out[NN2 + k * 3 + 1] = (float)bi;
            out[NN2 + k * 3 + 2] = (float)m0[bi];
            out[NN2 + 150 + k]   = bv;
            vals[bi] = -1.0f;
        }
        __syncthreads();
    }
}

// -------------------- host-side launchers ----------------------------------
static void gemm_nt(const float* A, const float* B, float* C, int M, int N, int K,
                    long sA, long sB, long sC, int xorB, int batch,
                    const float* bias, const float* res, float alpha)
{
    dim3 grid(N / 64, M / 128, batch);
    gemm_k<true><<<grid, 256>>>(A, B, C, M, N, K, sA, sB, sC, xorB, bias, res, alpha);
}
static void gemm_nn(const float* A, const float* B, float* C, int M, int N, int K,
                    long sA, long sB, long sC, int xorB, int batch,
                    const float* bias, const float* res, float alpha)
{
    dim3 grid(N / 64, M / 128, batch);
    gemm_k<false><<<grid, 256>>>(A, B, C, M, N, K, sA, sB, sC, xorB, bias, res, alpha);
}

extern "C" void kernel_launch(void* const* d_in, const int* in_sizes, int n_in,
                              void* d_out, int out_size)
{
    (void)in_sizes; (void)n_in; (void)out_size;
    const float* kpts      = (const float*)d_in[0];
    const float* desc      = (const float*)d_in[1];
    const float* posenc_Wr = (const float*)d_in[2];
    const float* sWqkv_w   = (const float*)d_in[3];
    const float* sWqkv_b   = (const float*)d_in[4];
    const float* sOut_w    = (const float*)d_in[5];
    const float* sOut_b    = (const float*)d_in[6];
    const float* sF1_w     = (const float*)d_in[7];
    const float* sF1_b     = (const float*)d_in[8];
    const float* sLN_g     = (const float*)d_in[9];
    const float* sLN_b     = (const float*)d_in[10];
    const float* sF2_w     = (const float*)d_in[11];
    const float* sF2_b     = (const float*)d_in[12];
    const float* cQK_w     = (const float*)d_in[13];
    const float* cQK_b     = (const float*)d_in[14];
    const float* cV_w      = (const float*)d_in[15];
    const float* cV_b      = (const float*)d_in[16];
    const float* cOut_w    = (const float*)d_in[17];
    const float* cOut_b    = (const float*)d_in[18];
    const float* cF1_w     = (const float*)d_in[19];
    const float* cF1_b     = (const float*)d_in[20];
    const float* cLN_g     = (const float*)d_in[21];
    const float* cLN_b     = (const float*)d_in[22];
    const float* cF2_w     = (const float*)d_in[23];
    const float* cF2_b     = (const float*)d_in[24];
    const float* fp_w      = (const float*)d_in[25];
    const float* fp_b      = (const float*)d_in[26];
    const float* match_w   = (const float*)d_in[27];
    const float* match_b   = (const float*)d_in[28];
    float* out = (float*)d_out;

    float *x, *qkv, *vb, *Q, *K, *V, *S, *ctxh, *ctx, *msg, *cat, *h1, *h2, *md, *sim, *z;
    float *lser, *lsec, *rmax;
    int *m0, *m1;
    cudaGetSymbolAddress((void**)&x,    g_x);
    cudaGetSymbolAddress((void**)&qkv,  g_qkv);
    cudaGetSymbolAddress((void**)&vb,   g_vbuf);
    cudaGetSymbolAddress((void**)&Q,    g_Q);
    cudaGetSymbolAddress((void**)&K,    g_K);
    cudaGetSymbolAddress((void**)&V,    g_V);
    cudaGetSymbolAddress((void**)&S,    g_S);
    cudaGetSymbolAddress((void**)&ctxh, g_ctxh);
    cudaGetSymbolAddress((void**)&ctx,  g_ctx);
    cudaGetSymbolAddress((void**)&msg,  g_msg);
    cudaGetSymbolAddress((void**)&cat,  g_cat);
    cudaGetSymbolAddress((void**)&h1,   g_h1);
    cudaGetSymbolAddress((void**)&h2,   g_h2);
    cudaGetSymbolAddress((void**)&md,   g_md);
    cudaGetSymbolAddress((void**)&sim,  g_sim);
    cudaGetSymbolAddress((void**)&z,    g_z);
    cudaGetSymbolAddress((void**)&lser, g_lser);
    cudaGetSymbolAddress((void**)&lsec, g_lsec);
    cudaGetSymbolAddress((void**)&rmax, g_rmax);
    cudaGetSymbolAddress((void**)&m0,   g_m0);
    cudaGetSymbolAddress((void**)&m1,   g_m1);

    const long sQKV = (long)LGN * LGHD;        // per-head stride 65536
    const long sSS  = (long)LGN * LGN;
    const float scale = 0.125f;                // 1/sqrt(64)

    copy_k<<<(M4 * LGD + 255) / 256, 256>>>(x, desc, M4 * LGD);

    for (int i = 0; i < LGL; i++) {
        // ---------------- self attention ----------------
        gemm_nt(x, sWqkv_w + (long)i * 3 * LGD * LGD, qkv, M4, 3 * LGD, LGD,
                0, 0, 0, 0, 1, sWqkv_b + (long)i * 3 * LGD, nullptr, 1.0f);
        rope_split_k<<<(LGB * LGN * 128 + 255) / 256, 256>>>(qkv, kpts, posenc_Wr, Q, K, V);
        gemm_nt(Q, K, S, LGN, LGN, LGHD, sQKV, sQKV, sSS, 0, BH, nullptr, nullptr, scale);
        softmax_rows_k<<<BH * LGN, 256>>>(S, LGN);
        gemm_nn(S, V, ctxh, LGN, LGHD, LGN, sSS, sQKV, sQKV, 0, BH, nullptr, nullptr, 1.0f);
        merge_heads_k<<<(M4 * LGD + 255) / 256, 256>>>(ctxh, ctx);
        gemm_nt(ctx, sOut_w + (long)i * LGD * LGD, msg, M4, LGD, LGD,
                0, 0, 0, 0, 1, sOut_b + (long)i * LGD, nullptr, 1.0f);
        concat_k<<<(M4 * 2 * LGD + 255) / 256, 256>>>(x, msg, cat);
        gemm_nt(cat, sF1_w + (long)i * 4 * LGD * LGD, h1, M4, 2 * LGD, 2 * LGD,
                0, 0, 0, 0, 1, sF1_b + (long)i * 2 * LGD, nullptr, 1.0f);
        lngelu_k<<<M4, 256>>>(h1, sLN_g + (long)i * 2 * LGD, sLN_b + (long)i * 2 * LGD, h2);
        gemm_nt(h2, sF2_w + (long)i * 2 * LGD * LGD, x, M4, LGD, 2 * LGD,
                0, 0, 0, 0, 1, sF2_b + (long)i * LGD, x, 1.0f);

        // ---------------- cross attention ----------------
        gemm_nt(x, cQK_w + (long)i * LGD * LGD, qkv, M4, LGD, LGD,
                0, 0, 0, 0, 1, cQK_b + (long)i * LGD, nullptr, 1.0f);
        gemm_nt(x, cV_w + (long)i * LGD * LGD, vb, M4, LGD, LGD,
                0, 0, 0, 0, 1, cV_b + (long)i * LGD, nullptr, 1.0f);
        split_heads_k<<<(M4 * LGD + 255) / 256, 256>>>(qkv, vb, Q, V);
        // keys/values come from the paired image: batch-head index XOR 4 == b^1
        gemm_nt(Q, Q, S, LGN, LGN, LGHD, sQKV, sQKV, sSS, 4, BH, nullptr, nullptr, scale);
        softmax_rows_k<<<BH * LGN, 256>>>(S, LGN);
        gemm_nn(S, V, ctxh, LGN, LGHD, LGN, sSS, sQKV, sQKV, 4, BH, nullptr, nullptr, 1.0f);
        merge_heads_k<<<(M4 * LGD + 255) / 256, 256>>>(ctxh, ctx);
        gemm_nt(ctx, cOut_w + (long)i * LGD * LGD, msg, M4, LGD, LGD,
                0, 0, 0, 0, 1, cOut_b + (long)i * LGD, nullptr, 1.0f);
        concat_k<<<(M4 * 2 * LGD + 255) / 256, 256>>>(x, msg, cat);
        gemm_nt(cat, cF1_w + (long)i * 4 * LGD * LGD, h1, M4, 2 * LGD, 2 * LGD,
                0, 0, 0, 0, 1, cF1_b + (long)i * 2 * LGD, nullptr, 1.0f);
        lngelu_k<<<M4, 256>>>(h1, cLN_g + (long)i * 2 * LGD, cLN_b + (long)i * 2 * LGD, h2);
        gemm_nt(h2, cF2_w + (long)i * 2 * LGD * LGD, x, M4, LGD, 2 * LGD,
                0, 0, 0, 0, 1, cF2_b + (long)i * LGD, x, 1.0f);
    }

    // ---------------- matching head ----------------
    // md = (x @ fp_w^T + fp_b) / 256^0.25  (= * 0.25)
    gemm_nt(x, fp_w, md, M4, LGD, LGD, 0, 0, 0, 0, 1, fp_b, nullptr, 0.25f);
    // sim[p] = md[2p] @ md[2p+1]^T
    gemm_nt(md, md + (long)LGN * LGD, sim, LGN, LGN, LGD,
            (long)2 * LGN * LGD, (long)2 * LGN * LGD, sSS, 0, 2, nullptr, nullptr, 1.0f);
    z_k<<<M4, 256>>>(x, match_w, match_b, z);
    lse_row_k<<<2 * LGN, 256>>>(sim, lser);
    lse_col_k<<<(2 * LGN + 255) / 256, 256>>>(sim, lsec);
    scores_k<<<(NN2 + 255) / 256, 256>>>(sim, lser, lsec, z, out);

    // ---------------- filter (batch 0 only) ----------------
    argmax_row_k<<<LGN, 256>>>(out, rmax, m0);
    argmax_col_k<<<(LGN + 255) / 256, 256>>>(out, m1);
    filter_k<<<1, 1024>>>(m0, m1, rmax, out);
}

// round 2
// speedup vs baseline: 1.3964x; 1.3964x over previous
#include <cuda_runtime.h>
#include <cuda_bf16.h>
#include <math.h>
#include <stdint.h>

// ---------------------------------------------------------------------------
// LightGlue forward. L=9, D=256, H=4, HD=64, N=1024, B=4 (2 pairs).
// GEMMs run on tensor cores (tf32 mma.sync, fp32 accumulate).
// ---------------------------------------------------------------------------

#define LGB   4
#define LGN   1024
#define LGD   256
#define LGH   4
#define LGHD  64
#define LGL   9
#define M4    (LGB*LGN)          // 4096 rows
#define BH    (LGB*LGH)          // 16 batched heads
#define NN2   (2*1024*1024)      // scores elements (2 pairs)

// -------------------- scratch (device globals; no allocation) --------------
__device__ float g_x   [M4*LGD];
__device__ float g_qkv [M4*3*LGD];
__device__ float g_vbuf[M4*LGD];
__device__ float g_Q   [BH*LGN*LGHD];
__device__ float g_K   [BH*LGN*LGHD];
__device__ float g_V   [BH*LGN*LGHD];
__device__ float g_S   [(size_t)BH*LGN*LGN];     // 64 MB
__device__ float g_ctxh[BH*LGN*LGHD];
__device__ float g_ctx [M4*LGD];
__device__ float g_msg [M4*LGD];
__device__ float g_cat [M4*2*LGD];
__device__ float g_h1  [M4*2*LGD];
__device__ float g_h2  [M4*2*LGD];
__device__ float g_md  [M4*LGD];
__device__ float g_sim [NN2];
__device__ float g_z   [M4];
__device__ float g_lser[2*LGN];
__device__ float g_lsec[2*LGN];
__device__ int   g_m0  [LGN];
__device__ int   g_m1  [LGN];
__device__ float g_rmax[LGN];

// -------------------- tf32 tensor-core GEMM --------------------------------
__device__ __forceinline__ float to_tf32(float x) {
    uint32_t u;
    asm("cvt.rna.tf32.f32 %0, %1;" : "=r"(u) : "f"(x));
    return __uint_as_float(u);
}

__device__ __forceinline__ void mma_tf32(float (&d)[4], const uint32_t (&a)[4],
                                         const uint32_t (&b)[2]) {
    asm volatile(
        "mma.sync.aligned.m16n8k8.row.col.f32.tf32.tf32.f32 "
        "{%0,%1,%2,%3}, {%4,%5,%6,%7}, {%8,%9}, {%0,%1,%2,%3};"
        : "+f"(d[0]), "+f"(d[1]), "+f"(d[2]), "+f"(d[3])
        : "r"(a[0]), "r"(a[1]), "r"(a[2]), "r"(a[3]), "r"(b[0]), "r"(b[1]));
}

// C[m,n] = alpha*( sum_k A[m,k]*(TRANSB ? B[n,k] : B[k,n]) + bias[n] ) + res[m,n]
// Block tile 128 x BN (BN=128 or 64), K-step 16, 8 warps, warp tile 64 x (BN/4).
template<int BN, bool TRANSB>
__global__ void __launch_bounds__(256, 2) tgemm_k(
    const float* __restrict__ A, const float* __restrict__ B, float* C,
    int M, int N, int K,
    long sA, long sB, long sC, int xorB,
    const float* __restrict__ bias, const float* res, float alpha)
{
    constexpr int TN = BN / 4;      // per-warp n extent
    constexpr int NT = TN / 8;      // n8 tiles per warp

    int bh = blockIdx.z;
    A += (long)bh * sA;
    B += (long)(bh ^ xorB) * sB;
    C += (long)bh * sC;
    if (res) res += (long)bh * sC;

    __shared__ float As[16][132];
    __shared__ float Bs[16][BN + 4];

    const int tid  = threadIdx.x;
    const int warp = tid >> 5, lane = tid & 31;
    const int wm = warp >> 2, wn = warp & 3;
    const int gid = lane >> 2, tig = lane & 3;
    const int row0 = blockIdx.y * 128;
    const int col0 = blockIdx.x * BN;

    float acc[4][NT][4];
#pragma unroll
    for (int i = 0; i < 4; i++)
#pragma unroll
        for (int j = 0; j < NT; j++)
#pragma unroll
            for (int q = 0; q < 4; q++) acc[i][j][q] = 0.0f;

    for (int k0 = 0; k0 < K; k0 += 16) {
        // ---- load A tile (128 x 16) as As[k][m], tf32-rounded ----
#pragma unroll
        for (int l = 0; l < 2; l++) {
            int v = tid + 256 * l;
            int r = v >> 2;
            int kk = (v & 3) * 4;
            float4 a = *reinterpret_cast<const float4*>(&A[(long)(row0 + r) * K + k0 + kk]);
            As[kk + 0][r] = to_tf32(a.x);
            As[kk + 1][r] = to_tf32(a.y);
            As[kk + 2][r] = to_tf32(a.z);
            As[kk + 3][r] = to_tf32(a.w);
        }
        // ---- load B tile as Bs[k][n] ----
        if (TRANSB) {
#pragma unroll
            for (int l = 0; l < BN / 64; l++) {
                int v = tid + 256 * l;
                int n = v >> 2;
                int kk = (v & 3) * 4;
                float4 b = *reinterpret_cast<const float4*>(&B[(long)(col0 + n) * K + k0 + kk]);
                Bs[kk + 0][n] = to_tf32(b.x);
                Bs[kk + 1][n] = to_tf32(b.y);
                Bs[kk + 2][n] = to_tf32(b.z);
                Bs[kk + 3][n] = to_tf32(b.w);
            }
        } else {
#pragma unroll
            for (int l = 0; l < BN / 64; l++) {
                int v = tid + 256 * l;
                int kk = v / (BN / 4);
                int n4 = (v % (BN / 4)) * 4;
                float4 b = *reinterpret_cast<const float4*>(&B[(long)(k0 + kk) * N + col0 + n4]);
                Bs[kk][n4 + 0] = to_tf32(b.x);
                Bs[kk][n4 + 1] = to_tf32(b.y);
                Bs[kk][n4 + 2] = to_tf32(b.z);
                Bs[kk][n4 + 3] = to_tf32(b.w);
            }
        }
        __syncthreads();

#pragma unroll
        for (int ks = 0; ks < 16; ks += 8) {
            uint32_t ar[4][4];
#pragma unroll
            for (int tm = 0; tm < 4; tm++) {
                int mrow = wm * 64 + tm * 16 + gid;
                ar[tm][0] = __float_as_uint(As[ks + tig][mrow]);
                ar[tm][1] = __float_as_uint(As[ks + tig][mrow + 8]);
                ar[tm][2] = __float_as_uint(As[ks + tig + 4][mrow]);
                ar[tm][3] = __float_as_uint(As[ks + tig + 4][mrow + 8]);
            }
            uint32_t br[NT][2];
#pragma unroll
            for (int tn = 0; tn < NT; tn++) {
                int ncol = wn * TN + tn * 8 + gid;
                br[tn][0] = __float_as_uint(Bs[ks + tig][ncol]);
                br[tn][1] = __float_as_uint(Bs[ks + tig + 4][ncol]);
            }
#pragma unroll
            for (int tm = 0; tm < 4; tm++)
#pragma unroll
                for (int tn = 0; tn < NT; tn++)
                    mma_tf32(acc[tm][tn], ar[tm], br[tn]);
        }
        __syncthreads();
    }

    // ---- epilogue ----
#pragma unroll
    for (int tm = 0; tm < 4; tm++) {
        int r0 = row0 + wm * 64 + tm * 16 + gid;
#pragma unroll
        for (int tn = 0; tn < NT; tn++) {
            int c = col0 + wn * TN + tn * 8 + tig * 2;
            float b0 = bias ? bias[c] : 0.0f;
            float b1 = bias ? bias[c + 1] : 0.0f;
#pragma unroll
            for (int half = 0; half < 2; half++) {
                int r = r0 + half * 8;
                float v0 = (acc[tm][tn][half * 2 + 0] + b0) * alpha;
                float v1 = (acc[tm][tn][half * 2 + 1] + b1) * alpha;
                if (res) {
                    v0 += res[(long)r * N + c];
                    v1 += res[(long)r * N + c + 1];
                }
                *reinterpret_cast<float2*>(&C[(long)r * N + c]) = make_float2(v0, v1);
            }
        }
    }
}

// -------------------- elementwise / reduction kernels ----------------------
__global__ void copy_k(float* dst, const float* src, int n) {
    int i = blockIdx.x * blockDim.x + threadIdx.x;
    if (i < n) dst[i] = src[i];
}

// qkv [B,N,768] interleaved (q=3d, k=3d+1, v=3d+2) -> RoPE(q,k) -> [B*H,N,64]
__global__ void rope_split_k(const float* __restrict__ qkv,
                             const float* __restrict__ kpts,
                             const float* __restrict__ Wr,
                             float* __restrict__ Q, float* __restrict__ Kh,
                             float* __restrict__ V)
{
    int t = blockIdx.x * blockDim.x + threadIdx.x;     // B*N*128 pair threads
    if (t >= LGB * LGN * 128) return;
    int p  = t & 127;
    int bn = t >> 7;
    int n  = bn & (LGN - 1);
    int b  = bn >> 10;
    int d0 = 2 * p;
    int f  = p & 31;                                    // (d0 % 64) / 2
    float kx = kpts[bn * 2 + 0], ky = kpts[bn * 2 + 1];
    float pr = kx * Wr[2 * f] + ky * Wr[2 * f + 1];
    float c = cosf(pr), s = sinf(pr);
    const float* q = qkv + (long)bn * 768;
    float q0 = q[3 * d0 + 0], q1 = q[3 * d0 + 3];
    float k0 = q[3 * d0 + 1], k1 = q[3 * d0 + 4];
    float v0 = q[3 * d0 + 2], v1 = q[3 * d0 + 5];
    int h = d0 >> 6, e0 = d0 & 63;
    long base = (((long)b * LGH + h) * LGN + n) * LGHD + e0;
    Q[base]      = c * q0 - s * q1;
    Q[base + 1]  = c * q1 + s * q0;
    Kh[base]     = c * k0 - s * k1;
    Kh[base + 1] = c * k1 + s * k0;
    V[base]      = v0;
    V[base + 1]  = v1;
}

__global__ void split_heads_k(const float* __restrict__ qk,
                              const float* __restrict__ v,
                              float* __restrict__ Q, float* __restrict__ V)
{
    int t = blockIdx.x * blockDim.x + threadIdx.x;
    if (t >= M4 * LGD) return;
    int d  = t & (LGD - 1);
    int bn = t >> 8;
    int n  = bn & (LGN - 1);
    int b  = bn >> 10;
    int h  = d >> 6, e = d & 63;
    long dst = (((long)b * LGH + h) * LGN + n) * LGHD + e;
    Q[dst] = qk[t];
    V[dst] = v[t];
}

__global__ void merge_heads_k(const float* __restrict__ ctxh, float* __restrict__ ctx)
{
    int t = blockIdx.x * blockDim.x + threadIdx.x;
    if (t >= M4 * LGD) return;
    int d  = t & (LGD - 1);
    int bn = t >> 8;
    int n  = bn & (LGN - 1);
    int b  = bn >> 10;
    int h  = d >> 6, e = d & 63;
    ctx[t] = ctxh[(((long)b * LGH + h) * LGN + n) * LGHD + e];
}

__global__ void concat_k(const float* __restrict__ x, const float* __restrict__ m,
                         float* __restrict__ cat)
{
    int t = blockIdx.x * blockDim.x + threadIdx.x;
    if (t >= M4 * 2 * LGD) return;
    int c  = t & (2 * LGD - 1);
    int bn = t >> 9;
    cat[t] = (c < LGD) ? x[(long)bn * LGD + c] : m[(long)bn * LGD + c - LGD];
}

// Single-pass register-resident row softmax (row length 1024, 256 threads).
__global__ void softmax_rows_k(float* __restrict__ S)
{
    long row = blockIdx.x;
    float* p = S + row * (long)LGN;
    int tid = threadIdx.x;
    int lane = tid & 31, warp = tid >> 5;
    float4 v = *reinterpret_cast<const float4*>(&p[tid * 4]);

    float m = fmaxf(fmaxf(v.x, v.y), fmaxf(v.z, v.w));
#pragma unroll
    for (int s = 16; s > 0; s >>= 1) m = fmaxf(m, __shfl_xor_sync(0xffffffffu, m, s));
    __shared__ float red[8];
    if (lane == 0) red[warp] = m;
    __syncthreads();
    if (warp == 0) {
        float t = red[lane & 7];
#pragma unroll
        for (int s = 4; s > 0; s >>= 1) t = fmaxf(t, __shfl_xor_sync(0xffffffffu, t, s));
        if (lane == 0) red[0] = t;
    }
    __syncthreads();
    m = red[0];

    v.x = expf(v.x - m); v.y = expf(v.y - m);
    v.z = expf(v.z - m); v.w = expf(v.w - m);
    float sum = v.x + v.y + v.z + v.w;
#pragma unroll
    for (int s = 16; s > 0; s >>= 1) sum += __shfl_xor_sync(0xffffffffu, sum, s);
    __shared__ float red2[8];
    if (lane == 0) red2[warp] = sum;
    __syncthreads();
    if (warp == 0) {
        float t = red2[lane & 7];
#pragma unroll
        for (int s = 4; s > 0; s >>= 1) t += __shfl_xor_sync(0xffffffffu, t, s);
        if (lane == 0) red2[0] = t;
    }
    __syncthreads();
    float inv = 1.0f / red2[0];
    v.x *= inv; v.y *= inv; v.z *= inv; v.w *= inv;
    *reinterpret_cast<float4*>(&p[tid * 4]) = v;
}

// LayerNorm(512) + exact GELU
__global__ void lngelu_k(const float* __restrict__ h, const float* __restrict__ g,
                         const float* __restrict__ bb, float* __restrict__ o)
{
    long row = blockIdx.x;
    int tid = threadIdx.x;
    const float* p = h + row * 512;
    float x0 = p[tid], x1 = p[tid + 256];
    __shared__ float red[256];
    red[tid] = x0 + x1; __syncthreads();
    for (int s = 128; s > 0; s >>= 1) { if (tid < s) red[tid] += red[tid + s]; __syncthreads(); }
    float mean = red[0] * (1.0f / 512.0f);
    __syncthreads();
    red[tid] = x0 * x0 + x1 * x1; __syncthreads();
    for (int s = 128; s > 0; s >>= 1) { if (tid < s) red[tid] += red[tid + s]; __syncthreads(); }
    float var = red[0] * (1.0f / 512.0f) - mean * mean;
    float rr = rsqrtf(var + 1e-5f);
    float n0 = (x0 - mean) * rr * g[tid] + bb[tid];
    float n1 = (x1 - mean) * rr * g[tid + 256] + bb[tid + 256];
    o[row * 512 + tid]       = 0.5f * n0 * (1.0f + erff(n0 * 0.70710678118654752f));
    o[row * 512 + tid + 256] = 0.5f * n1 * (1.0f + erff(n1 * 0.70710678118654752f));
}

__global__ void z_k(const float* __restrict__ x, const float* __restrict__ w,
                    const float* __restrict__ b, float* __restrict__ z)
{
    long row = blockIdx.x;
    int tid = threadIdx.x;
    __shared__ float red[256];
    red[tid] = x[row * LGD + tid] * w[tid];
    __syncthreads();
    for (int s = 128; s > 0; s >>= 1) { if (tid < s) red[tid] += red[tid + s]; __syncthreads(); }
    if (tid == 0) z[row] = red[0] + b[0];
}

__global__ void lse_row_k(const float* __restrict__ sim, float* __restrict__ lser)
{
    long r = blockIdx.x;                         // 2048 rows
    const float* p = sim + r * LGN;
    int tid = threadIdx.x;
    __shared__ float red[256];
    float m = -INFINITY;
    for (int j = tid; j < LGN; j += 256) m = fmaxf(m, p[j]);
    red[tid] = m; __syncthreads();
    for (int s = 128; s > 0; s >>= 1) { if (tid < s) red[tid] = fmaxf(red[tid], red[tid + s]); __syncthreads(); }
    m = red[0];
    __syncthreads();
    float sum = 0.0f;
    for (int j = tid; j < LGN; j += 256) sum += expf(p[j] - m);
    red[tid] = sum; __syncthreads();
    for (int s = 128; s > 0; s >>= 1) { if (tid < s) red[tid] += red[tid + s]; __syncthreads(); }
    if (tid == 0) lser[r] = m + logf(red[0]);
}

// Column LSE, parallel: block = 256 threads = 8 row-groups x 32 cols.
// Grid = 2 pairs * 32 col-groups.
__global__ void lse_col_k(const float* __restrict__ sim, float* __restrict__ lsec)
{
    int cg = blockIdx.x & 31;
    int p  = blockIdx.x >> 5;
    int tid = threadIdx.x;
    int jc = (tid & 31);
    int j = cg * 32 + jc;
    int rg = tid >> 5;                  // 0..7
    const float* base = sim + (long)p * LGN * LGN + j;
    float m = -INFINITY, s = 0.0f;
    for (int i = rg; i < LGN; i += 8) {
        float v = base[(long)i * LGN];
        if (v > m) { s = s * expf(m - v) + 1.0f; m = v; }
        else s += expf(v - m);
    }
    __shared__ float sm[8][33], ss[8][33];
    sm[rg][jc] = m; ss[rg][jc] = s;
    __syncthreads();
    if (tid < 32) {
        float M = sm[0][tid], S = ss[0][tid];
#pragma unroll
        for (int g = 1; g < 8; g++) {
            float m2 = sm[g][tid], s2 = ss[g][tid];
            if (m2 > M) { S = S * expf(M - m2) + s2; M = m2; }
            else S += s2 * expf(m2 - M);
        }
        lsec[p * LGN + cg * 32 + tid] = M + logf(S);
    }
}

__device__ __forceinline__ float lsig(float t) {
    return fminf(t, 0.0f) - log1pf(expf(-fabsf(t)));
}

__global__ void scores_k(const float* __restrict__ sim, const float* __restrict__ lser,
                         const float* __restrict__ lsec, const float* __restrict__ z,
                         float* __restrict__ out)
{
    long idx = (long)blockIdx.x * 256 + threadIdx.x;
    if (idx >= (long)NN2) return;
    int j = idx & (LGN - 1);
    long r = idx >> 10;
    int i = (int)(r & (LGN - 1));
    int p = (int)(r >> 10);
    float zq = z[(2 * p) * LGN + i];
    float zk = z[(2 * p + 1) * LGN + j];
    out[idx] = 2.0f * sim[idx] - lser[p * LGN + i] - lsec[p * LGN + j] + lsig(zq) + lsig(zk);
}

__global__ void argmax_row_k(const float* __restrict__ S, float* __restrict__ rmax,
                             int* __restrict__ m0)
{
    long i = blockIdx.x;
    const float* p = S + i * LGN;
    int tid = threadIdx.x;
    float bv = -INFINITY; int bi = 0;
    for (int j = tid; j < LGN; j += 256) {
        float v = p[j];
        if (v > bv) { bv = v; bi = j; }
    }
    __shared__ float sv[256]; __shared__ int si[256];
    sv[tid] = bv; si[tid] = bi; __syncthreads();
    for (int s = 128; s > 0; s >>= 1) {
        if (tid < s) {
            float v2 = sv[tid + s]; int i2 = si[tid + s];
            if (v2 > sv[tid] || (v2 == sv[tid] && i2 < si[tid])) { sv[tid] = v2; si[tid] = i2; }
        }
        __syncthreads();
    }
    if (tid == 0) { rmax[i] = sv[0]; m0[i] = si[0]; }
}

// Column argmax, parallel: 32 blocks x (8 row-groups x 32 cols).
__global__ void argmax_col_k(const float* __restrict__ S, int* __restrict__ m1)
{
    int cg = blockIdx.x;
    int tid = threadIdx.x;
    int jc = tid & 31;
    int j = cg * 32 + jc;
    int rg = tid >> 5;
    float bv = -INFINITY; int bi = 0;
    for (int i = rg; i < LGN; i += 8) {
        float v = S[(long)i * LGN + j];
        if (v > bv || (v == bv && i < bi)) { bv = v; bi = i; }
    }
    __shared__ float sv[8][33]; __shared__ int si[8][33];
    sv[rg][jc] = bv; si[rg][jc] = bi;
    __syncthreads();
    if (tid < 32) {
        float V = sv[0][tid]; int I = si[0][tid];
#pragma unroll
        for (int g = 1; g < 8; g++) {
            float v2 = sv[g][tid]; int i2 = si[g][tid];
            if (v2 > V || (v2 == V && i2 < I)) { V = v2; I = i2; }
        }
        m1[cg * 32 + tid] = I;
    }
}

__global__ void filter_k(const int* __restrict__ m0, const int* __restrict__ m1,
                         const float* __restrict__ rmax, float* __restrict__ out)
{
    __shared__ float vals[LGN];
    __shared__ float rv[LGN];
    __shared__ int   ri[LGN];
    int n = threadIdx.x;
    float ms = expf(rmax[n]);
    bool mutual = (m1[m0[n]] == n);
    vals[n] = (mutual && ms > 0.1f) ? ms : 0.0f;
    __syncthreads();
    for (int k = 0; k < 50; k++) {
        rv[n] = vals[n]; ri[n] = n; __syncthreads();
        for (int s = 512; s > 0; s >>= 1) {
            if (n < s) {
                float v2 = rv[n + s]; int i2 = ri[n + s];
                if (v2 > rv[n] || (v2 == rv[n] && i2 < ri[n])) { rv[n] = v2; ri[n] = i2; }
            }
            __syncthreads();
        }
        if (n == 0) {
            int bi = ri[0]; float bv = rv[0];
            out[NN2 + k * 3 + 0] = 0.0f;
            out[NN2 + k * 3 + 1] = (float)bi;
            out[NN2 + k * 3 + 2] = (float)m0[bi];
            out[NN2 + 150 + k]   = bv;
            vals[bi] = -1.0f;
        }
        __syncthreads();
    }
}

// -------------------- host-side launchers ----------------------------------
static void tgemm(bool transb, const float* A, const float* B, float* C,
                  int M, int N, int K, long sA, long sB, long sC, int xorB,
                  int batch, const float* bias, const float* res, float alpha)
{
    if (N % 128 == 0) {
        dim3 grid(N / 128, M / 128, batch);
        if (transb)
            tgemm_k<128, true><<<grid, 256>>>(A, B, C, M, N, K, sA, sB, sC, xorB, bias, res, alpha);
        else
            tgemm_k<128, false><<<grid, 256>>>(A, B, C, M, N, K, sA, sB, sC, xorB, bias, res, alpha);
    } else {
        dim3 grid(N / 64, M / 128, batch);
        if (transb)
            tgemm_k<64, true><<<grid, 256>>>(A, B, C, M, N, K, sA, sB, sC, xorB, bias, res, alpha);
        else
            tgemm_k<64, false><<<grid, 256>>>(A, B, C, M, N, K, sA, sB, sC, xorB, bias, res, alpha);
    }
}

extern "C" void kernel_launch(void* const* d_in, const int* in_sizes, int n_in,
                              void* d_out, int out_size)
{
    (void)in_sizes; (void)n_in; (void)out_size;
    const float* kpts      = (const float*)d_in[0];
    const float* desc      = (const float*)d_in[1];
    const float* posenc_Wr = (const float*)d_in[2];
    const float* sWqkv_w   = (const float*)d_in[3];
    const float* sWqkv_b   = (const float*)d_in[4];
    const float* sOut_w    = (const float*)d_in[5];
    const float* sOut_b    = (const float*)d_in[6];
    const float* sF1_w     = (const float*)d_in[7];
    const float* sF1_b     = (const float*)d_in[8];
    const float* sLN_g     = (const float*)d_in[9];
    const float* sLN_b     = (const float*)d_in[10];
    const float* sF2_w     = (const float*)d_in[11];
    const float* sF2_b     = (const float*)d_in[12];
    const float* cQK_w     = (const float*)d_in[13];
    const float* cQK_b     = (const float*)d_in[14];
    const float* cV_w      = (const float*)d_in[15];
    const float* cV_b      = (const float*)d_in[16];
    const float* cOut_w    = (const float*)d_in[17];
    const float* cOut_b    = (const float*)d_in[18];
    const float* cF1_w     = (const float*)d_in[19];
    const float* cF1_b     = (const float*)d_in[20];
    const float* cLN_g     = (const float*)d_in[21];
    const float* cLN_b     = (const float*)d_in[22];
    const float* cF2_w     = (const float*)d_in[23];
    const float* cF2_b     = (const float*)d_in[24];
    const float* fp_w      = (const float*)d_in[25];
    const float* fp_b      = (const float*)d_in[26];
    const float* match_w   = (const float*)d_in[27];
    const float* match_b   = (const float*)d_in[28];
    float* out = (float*)d_out;

    float *x, *qkv, *vb, *Q, *K, *V, *S, *ctxh, *ctx, *msg, *cat, *h1, *h2, *md, *sim, *z;
    float *lser, *lsec, *rmax;
    int *m0, *m1;
    cudaGetSymbolAddress((void**)&x,    g_x);
    cudaGetSymbolAddress((void**)&qkv,  g_qkv);
    cudaGetSymbolAddress((void**)&vb,   g_vbuf);
    cudaGetSymbolAddress((void**)&Q,    g_Q);
    cudaGetSymbolAddress((void**)&K,    g_K);
    cudaGetSymbolAddress((void**)&V,    g_V);
    cudaGetSymbolAddress((void**)&S,    g_S);
    cudaGetSymbolAddress((void**)&ctxh, g_ctxh);
    cudaGetSymbolAddress((void**)&ctx,  g_ctx);
    cudaGetSymbolAddress((void**)&msg,  g_msg);
    cudaGetSymbolAddress((void**)&cat,  g_cat);
    cudaGetSymbolAddress((void**)&h1,   g_h1);
    cudaGetSymbolAddress((void**)&h2,   g_h2);
    cudaGetSymbolAddress((void**)&md,   g_md);
    cudaGetSymbolAddress((void**)&sim,  g_sim);
    cudaGetSymbolAddress((void**)&z,    g_z);
    cudaGetSymbolAddress((void**)&lser, g_lser);
    cudaGetSymbolAddress((void**)&lsec, g_lsec);
    cudaGetSymbolAddress((void**)&rmax, g_rmax);
    cudaGetSymbolAddress((void**)&m0,   g_m0);
    cudaGetSymbolAddress((void**)&m1,   g_m1);

    const long sQKV = (long)LGN * LGHD;        // per-head stride 65536
    const long sSS  = (long)LGN * LGN;
    const float scale = 0.125f;                // 1/sqrt(64)

    copy_k<<<(M4 * LGD + 255) / 256, 256>>>(x, desc, M4 * LGD);

    for (int i = 0; i < LGL; i++) {
        // ---------------- self attention ----------------
        tgemm(true, x, sWqkv_w + (long)i * 3 * LGD * LGD, qkv, M4, 3 * LGD, LGD,
              0, 0, 0, 0, 1, sWqkv_b + (long)i * 3 * LGD, nullptr, 1.0f);
        rope_split_k<<<(LGB * LGN * 128 + 255) / 256, 256>>>(qkv, kpts, posenc_Wr, Q, K, V);
        tgemm(true, Q, K, S, LGN, LGN, LGHD, sQKV, sQKV, sSS, 0, BH, nullptr, nullptr, scale);
        softmax_rows_k<<<BH * LGN, 256>>>(S);
        tgemm(false, S, V, ctxh, LGN, LGHD, LGN, sSS, sQKV, sQKV, 0, BH, nullptr, nullptr, 1.0f);
        merge_heads_k<<<(M4 * LGD + 255) / 256, 256>>>(ctxh, ctx);
        tgemm(true, ctx, sOut_w + (long)i * LGD * LGD, msg, M4, LGD, LGD,
              0, 0, 0, 0, 1, sOut_b + (long)i * LGD, nullptr, 1.0f);
        concat_k<<<(M4 * 2 * LGD + 255) / 256, 256>>>(x, msg, cat);
        tgemm(true, cat, sF1_w + (long)i * 4 * LGD * LGD, h1, M4, 2 * LGD, 2 * LGD,
              0, 0, 0, 0, 1, sF1_b + (long)i * 2 * LGD, nullptr, 1.0f);
        lngelu_k<<<M4, 256>>>(h1, sLN_g + (long)i * 2 * LGD, sLN_b + (long)i * 2 * LGD, h2);
        tgemm(true, h2, sF2_w + (long)i * 2 * LGD * LGD, x, M4, LGD, 2 * LGD,
              0, 0, 0, 0, 1, sF2_b + (long)i * LGD, x, 1.0f);

        // ---------------- cross attention ----------------
        tgemm(true, x, cQK_w + (long)i * LGD * LGD, qkv, M4, LGD, LGD,
              0, 0, 0, 0, 1, cQK_b + (long)i * LGD, nullptr, 1.0f);
        tgemm(true, x, cV_w + (long)i * LGD * LGD, vb, M4, LGD, LGD,
              0, 0, 0, 0, 1, cV_b + (long)i * LGD, nullptr, 1.0f);
        split_heads_k<<<(M4 * LGD + 255) / 256, 256>>>(qkv, vb, Q, V);
        // keys/values come from the paired image: batch-head index XOR 4 == b^1
        tgemm(true, Q, Q, S, LGN, LGN, LGHD, sQKV, sQKV, sSS, 4, BH, nullptr, nullptr, scale);
        softmax_rows_k<<<BH * LGN, 256>>>(S);
        tgemm(false, S, V, ctxh, LGN, LGHD, LGN, sSS, sQKV, sQKV, 4, BH, nullptr, nullptr, 1.0f);
        merge_heads_k<<<(M4 * LGD + 255) / 256, 256>>>(ctxh, ctx);
        tgemm(true, ctx, cOut_w + (long)i * LGD * LGD, msg, M4, LGD, LGD,
              0, 0, 0, 0, 1, cOut_b + (long)i * LGD, nullptr, 1.0f);
        concat_k<<<(M4 * 2 * LGD + 255) / 256, 256>>>(x, msg, cat);
        tgemm(true, cat, cF1_w + (long)i * 4 * LGD * LGD, h1, M4, 2 * LGD, 2 * LGD,
              0, 0, 0, 0, 1, cF1_b + (long)i * 2 * LGD, nullptr, 1.0f);
        lngelu_k<<<M4, 256>>>(h1, cLN_g + (long)i * 2 * LGD, cLN_b + (long)i * 2 * LGD, h2);
        tgemm(true, h2, cF2_w + (long)i * 2 * LGD * LGD, x, M4, LGD, 2 * LGD,
              0, 0, 0, 0, 1, cF2_b + (long)i * LGD, x, 1.0f);
    }

    // ---------------- matching head ----------------
    tgemm(true, x, fp_w, md, M4, LGD, LGD, 0, 0, 0, 0, 1, fp_b, nullptr, 0.25f);
    tgemm(true, md, md + (long)LGN * LGD, sim, LGN, LGN, LGD,
          (long)2 * LGN * LGD, (long)2 * LGN * LGD, sSS, 0, 2, nullptr, nullptr, 1.0f);
    z_k<<<M4, 256>>>(x, match_w, match_b, z);
    lse_row_k<<<2 * LGN, 256>>>(sim, lser);
    lse_col_k<<<64, 256>>>(sim, lsec);
    scores_k<<<(NN2 + 255) / 256, 256>>>(sim, lser, lsec, z, out);

    // ---------------- filter (batch 0 only) ----------------
    argmax_row_k<<<LGN, 256>>>(out, rmax, m0);
    argmax_col_k<<<32, 256>>>(out, m1);
    filter_k<<<1, 1024>>>(m0, m1, rmax, out);
}

// round 3
// speedup vs baseline: 2.1196x; 1.5179x over previous
#include <cuda_runtime.h>
#include <cuda_bf16.h>
#include <math.h>
#include <stdint.h>

// ---------------------------------------------------------------------------
// LightGlue forward. L=9, D=256, H=4, HD=64, N=1024, B=4 (2 pairs).
// Dense GEMMs: tf32 mma.sync with cp.async double buffering.
// Attention: fused flash kernel (tf32 mma, online softmax).
// ---------------------------------------------------------------------------

#define LGB   4
#define LGN   1024
#define LGD   256
#define LGH   4
#define LGHD  64
#define LGL   9
#define M4    (LGB*LGN)          // 4096 rows
#define BH    (LGB*LGH)          // 16 batched heads
#define NN2   (2*1024*1024)      // scores elements (2 pairs)

// -------------------- scratch (device globals; no allocation) --------------
__device__ float g_x   [M4*LGD];
__device__ float g_qkv [M4*3*LGD];
__device__ float g_vbuf[M4*LGD];
__device__ float g_Q   [BH*LGN*LGHD];
__device__ float g_K   [BH*LGN*LGHD];
__device__ float g_V   [BH*LGN*LGHD];
__device__ float g_ctx [M4*LGD];
__device__ float g_cat [M4*2*LGD];
__device__ float g_h1  [M4*2*LGD];
__device__ float g_h2  [M4*2*LGD];
__device__ float g_md  [M4*LGD];
__device__ float g_sim [NN2];
__device__ float g_z   [M4];
__device__ float g_lser[2*LGN];
__device__ float g_lsec[2*LGN];
__device__ int   g_m0  [LGN];
__device__ int   g_m1  [LGN];
__device__ float g_rmax[LGN];

// -------------------- tf32 helpers -----------------------------------------
__device__ __forceinline__ uint32_t tf32u(float x) {
    uint32_t u;
    asm("cvt.rna.tf32.f32 %0, %1;" : "=r"(u) : "f"(x));
    return u;
}

__device__ __forceinline__ void mma_tf32(float (&d)[4], const uint32_t (&a)[4],
                                         const uint32_t (&b)[2]) {
    asm volatile(
        "mma.sync.aligned.m16n8k8.row.col.f32.tf32.tf32.f32 "
        "{%0,%1,%2,%3}, {%4,%5,%6,%7}, {%8,%9}, {%0,%1,%2,%3};"
        : "+f"(d[0]), "+f"(d[1]), "+f"(d[2]), "+f"(d[3])
        : "r"(a[0]), "r"(a[1]), "r"(a[2]), "r"(a[3]), "r"(b[0]), "r"(b[1]));
}

__device__ __forceinline__ void cp16(void* dst, const void* src) {
    uint32_t d = (uint32_t)__cvta_generic_to_shared(dst);
    asm volatile("cp.async.cg.shared.global [%0], [%1], 16;" :: "r"(d), "l"(src));
}
__device__ __forceinline__ void cp_commit() { asm volatile("cp.async.commit_group;"); }
template<int n> __device__ __forceinline__ void cp_wait() {
    asm volatile("cp.async.wait_group %0;" :: "n"(n));
}

// -------------------- dense tf32 GEMM (NT only) -----------------------------
// C[m,n] = alpha*( sum_k A[m,k]*B[n,k] + bias[n] ) + res[m,n]
// Block 128x128, K-step 16, double-buffered cp.async, 8 warps (64x32 warp tile).
__global__ void __launch_bounds__(256, 2) tgemm_k(
    const float* __restrict__ A, const float* __restrict__ B, float* C,
    int M, int N, int K, int ldC,
    long sA, long sB, long sC,
    const float* __restrict__ bias, const float* res, float alpha)
{
    __shared__ float As[2][128 * 20];
    __shared__ float Bs[2][128 * 20];

    int bh = blockIdx.z;
    A += (long)bh * sA;
    B += (long)bh * sB;
    C += (long)bh * sC;
    if (res) res += (long)bh * sC;

    const int tid  = threadIdx.x;
    const int warp = tid >> 5, lane = tid & 31;
    const int wm = warp >> 2, wn = warp & 3;
    const int gid = lane >> 2, tig = lane & 3;
    const int row0 = blockIdx.y * 128;
    const int col0 = blockIdx.x * 128;

    float acc[4][4][4];
#pragma unroll
    for (int i = 0; i < 4; i++)
#pragma unroll
        for (int j = 0; j < 4; j++)
#pragma unroll
            for (int q = 0; q < 4; q++) acc[i][j][q] = 0.0f;

#define LOADT(s, k0) do {                                                      \
    _Pragma("unroll")                                                          \
    for (int l = 0; l < 2; l++) {                                              \
        int v = tid + 256 * l; int r = v >> 2; int off = (v & 3) * 4;          \
        cp16(&As[s][r * 20 + off], &A[(long)(row0 + r) * K + (k0) + off]);     \
    }                                                                          \
    _Pragma("unroll")                                                          \
    for (int l = 0; l < 2; l++) {                                              \
        int v = tid + 256 * l; int r = v >> 2; int off = (v & 3) * 4;          \
        cp16(&Bs[s][r * 20 + off], &B[(long)(col0 + r) * K + (k0) + off]);     \
    }                                                                          \
    cp_commit(); } while (0)

    const int NK = K >> 4;
    LOADT(0, 0);

    for (int it = 0; it < NK; it++) {
        int cur = it & 1;
        if (it + 1 < NK) {
            LOADT(cur ^ 1, (it + 1) << 4);
            cp_wait<1>();
        } else {
            cp_wait<0>();
        }
        __syncthreads();

#pragma unroll
        for (int ks = 0; ks < 16; ks += 8) {
            uint32_t ar[4][4];
#pragma unroll
            for (int tm = 0; tm < 4; tm++) {
                int mr = (wm * 64 + tm * 16 + gid) * 20;
                ar[tm][0] = tf32u(As[cur][mr + ks + tig]);
                ar[tm][1] = tf32u(As[cur][mr + 160 + ks + tig]);
                ar[tm][2] = tf32u(As[cur][mr + ks + tig + 4]);
                ar[tm][3] = tf32u(As[cur][mr + 160 + ks + tig + 4]);
            }
            uint32_t br[4][2];
#pragma unroll
            for (int tn = 0; tn < 4; tn++) {
                int nr = (wn * 32 + tn * 8 + gid) * 20;
                br[tn][0] = tf32u(Bs[cur][nr + ks + tig]);
                br[tn][1] = tf32u(Bs[cur][nr + ks + tig + 4]);
            }
#pragma unroll
            for (int tm = 0; tm < 4; tm++)
#pragma unroll
                for (int tn = 0; tn < 4; tn++)
                    mma_tf32(acc[tm][tn], ar[tm], br[tn]);
        }
        __syncthreads();
    }
#undef LOADT

#pragma unroll
    for (int tm = 0; tm < 4; tm++) {
        int r0 = row0 + wm * 64 + tm * 16 + gid;
#pragma unroll
        for (int tn = 0; tn < 4; tn++) {
            int c = col0 + wn * 32 + tn * 8 + tig * 2;
            float b0 = bias ? bias[c] : 0.0f;
            float b1 = bias ? bias[c + 1] : 0.0f;
#pragma unroll
            for (int half = 0; half < 2; half++) {
                int r = r0 + half * 8;
                float v0 = (acc[tm][tn][half * 2 + 0] + b0) * alpha;
                float v1 = (acc[tm][tn][half * 2 + 1] + b1) * alpha;
                if (res) {
                    v0 += res[(long)r * ldC + c];
                    v1 += res[(long)r * ldC + c + 1];
                }
                *reinterpret_cast<float2*>(&C[(long)r * ldC + c]) = make_float2(v0, v1);
            }
        }
    }
}

// -------------------- fused flash attention ---------------------------------
// Q,K,V: [16 heads][1024][64]. ctx out: [B*N][256] merged-head layout.
// grid (8 q-tiles, 16 heads), 256 threads (8 warps x 16 query rows).
// Softmax scale 1/8 folded into Q (exact). Key/value head index ^= xorB.
__global__ void __launch_bounds__(256) flash_k(
    const float* __restrict__ Qg, const float* __restrict__ Kg,
    const float* __restrict__ Vg, float* __restrict__ ctx, int xorB)
{
    extern __shared__ float smf[];
    float* Ks = smf;                 // [64][68]  K[key][d]
    float* Vt = smf + 64 * 68;       // [64][68]  V^T[d][key]
    float* Ps = smf + 2 * 64 * 68;   // [128][68] Q staging, then P

    const int bh = blockIdx.y, qt = blockIdx.x;
    const float* Qh = Qg + (long)bh * (LGN * LGHD);
    const float* Kh = Kg + (long)(bh ^ xorB) * (LGN * LGHD);
    const float* Vh = Vg + (long)(bh ^ xorB) * (LGN * LGHD);

    const int tid = threadIdx.x, warp = tid >> 5, lane = tid & 31;
    const int gid = lane >> 2, tig = lane & 3;
    const int wrow = warp * 16;

    // ---- stage Q tile (128x64), extract scaled tf32 A-fragments ----
    for (int i = tid; i < 128 * 16; i += 256) {
        int r = i >> 4, c = (i & 15) * 4;
        float4 v = *(const float4*)&Qh[(long)(qt * 128 + r) * LGHD + c];
        Ps[r * 68 + c]     = v.x; Ps[r * 68 + c + 1] = v.y;
        Ps[r * 68 + c + 2] = v.z; Ps[r * 68 + c + 3] = v.w;
    }
    __syncthreads();
    uint32_t qa[8][4];
#pragma unroll
    for (int ks = 0; ks < 8; ks++) {
        int k = ks * 8;
        qa[ks][0] = tf32u(0.125f * Ps[(wrow + gid) * 68 + k + tig]);
        qa[ks][1] = tf32u(0.125f * Ps[(wrow + gid + 8) * 68 + k + tig]);
        qa[ks][2] = tf32u(0.125f * Ps[(wrow + gid) * 68 + k + tig + 4]);
        qa[ks][3] = tf32u(0.125f * Ps[(wrow + gid + 8) * 68 + k + tig + 4]);
    }
    __syncthreads();

    float oacc[8][4];
#pragma unroll
    for (int nt = 0; nt < 8; nt++)
#pragma unroll
        for (int j = 0; j < 4; j++) oacc[nt][j] = 0.0f;
    float mrow0 = -INFINITY, mrow1 = -INFINITY, lrow0 = 0.0f, lrow1 = 0.0f;

    for (int kt = 0; kt < 16; kt++) {
        // load K tile (64x64) and V tile transposed
        for (int i = tid; i < 64 * 16; i += 256) {
            int r = i >> 4, c = (i & 15) * 4;
            float4 v = *(const float4*)&Kh[(long)(kt * 64 + r) * LGHD + c];
            Ks[r * 68 + c]     = v.x; Ks[r * 68 + c + 1] = v.y;
            Ks[r * 68 + c + 2] = v.z; Ks[r * 68 + c + 3] = v.w;
        }
        for (int i = tid; i < 64 * 16; i += 256) {
            int r = i >> 4, c = (i & 15) * 4;
            float4 v = *(const float4*)&Vh[(long)(kt * 64 + r) * LGHD + c];
            Vt[(c + 0) * 68 + r] = v.x; Vt[(c + 1) * 68 + r] = v.y;
            Vt[(c + 2) * 68 + r] = v.z; Vt[(c + 3) * 68 + r] = v.w;
        }
        __syncthreads();

        // S = (Q/8) K^T : 128x64
        float sacc[8][4];
#pragma unroll
        for (int nt = 0; nt < 8; nt++)
#pragma unroll
            for (int j = 0; j < 4; j++) sacc[nt][j] = 0.0f;
#pragma unroll
        for (int ks = 0; ks < 8; ks++) {
            int k = ks * 8;
#pragma unroll
            for (int nt = 0; nt < 8; nt++) {
                uint32_t b[2];
                b[0] = tf32u(Ks[(nt * 8 + gid) * 68 + k + tig]);
                b[1] = tf32u(Ks[(nt * 8 + gid) * 68 + k + tig + 4]);
                mma_tf32(sacc[nt], qa[ks], b);
            }
        }

        // ---- online softmax (rows gid, gid+8 owned by this quad) ----
        float t0 = -INFINITY, t1 = -INFINITY;
#pragma unroll
        for (int nt = 0; nt < 8; nt++) {
            t0 = fmaxf(t0, fmaxf(sacc[nt][0], sacc[nt][1]));
            t1 = fmaxf(t1, fmaxf(sacc[nt][2], sacc[nt][3]));
        }
        t0 = fmaxf(t0, __shfl_xor_sync(0xffffffffu, t0, 1));
        t0 = fmaxf(t0, __shfl_xor_sync(0xffffffffu, t0, 2));
        t1 = fmaxf(t1, __shfl_xor_sync(0xffffffffu, t1, 1));
        t1 = fmaxf(t1, __shfl_xor_sync(0xffffffffu, t1, 2));
        float mn0 = fmaxf(mrow0, t0), mn1 = fmaxf(mrow1, t1);
        float al0 = expf(mrow0 - mn0), al1 = expf(mrow1 - mn1);
        float s0 = 0.0f, s1 = 0.0f;
#pragma unroll
        for (int nt = 0; nt < 8; nt++) {
            sacc[nt][0] = expf(sacc[nt][0] - mn0);
            sacc[nt][1] = expf(sacc[nt][1] - mn0);
            sacc[nt][2] = expf(sacc[nt][2] - mn1);
            sacc[nt][3] = expf(sacc[nt][3] - mn1);
            s0 += sacc[nt][0] + sacc[nt][1];
            s1 += sacc[nt][2] + sacc[nt][3];
        }
        s0 += __shfl_xor_sync(0xffffffffu, s0, 1);
        s0 += __shfl_xor_sync(0xffffffffu, s0, 2);
        s1 += __shfl_xor_sync(0xffffffffu, s1, 1);
        s1 += __shfl_xor_sync(0xffffffffu, s1, 2);
        lrow0 = lrow0 * al0 + s0;
        lrow1 = lrow1 * al1 + s1;
        mrow0 = mn0; mrow1 = mn1;

        // rescale O, store P (tf32-rounded) into warp-local Ps rows
#pragma unroll
        for (int nt = 0; nt < 8; nt++) {
            oacc[nt][0] *= al0; oacc[nt][1] *= al0;
            oacc[nt][2] *= al1; oacc[nt][3] *= al1;
            int c = nt * 8 + 2 * tig;
            Ps[(wrow + gid) * 68 + c]         = __uint_as_float(tf32u(sacc[nt][0]));
            Ps[(wrow + gid) * 68 + c + 1]     = __uint_as_float(tf32u(sacc[nt][1]));
            Ps[(wrow + gid + 8) * 68 + c]     = __uint_as_float(tf32u(sacc[nt][2]));
            Ps[(wrow + gid + 8) * 68 + c + 1] = __uint_as_float(tf32u(sacc[nt][3]));
        }
        __syncwarp();

        // O += P V  (k-dim = 64 keys)
#pragma unroll
        for (int ks = 0; ks < 8; ks++) {
            int k = ks * 8;
            uint32_t pa[4];
            pa[0] = __float_as_uint(Ps[(wrow + gid) * 68 + k + tig]);
            pa[1] = __float_as_uint(Ps[(wrow + gid + 8) * 68 + k + tig]);
            pa[2] = __float_as_uint(Ps[(wrow + gid) * 68 + k + tig + 4]);
            pa[3] = __float_as_uint(Ps[(wrow + gid + 8) * 68 + k + tig + 4]);
#pragma unroll
            for (int nt = 0; nt < 8; nt++) {
                uint32_t b[2];
                b[0] = tf32u(Vt[(nt * 8 + gid) * 68 + k + tig]);
                b[1] = tf32u(Vt[(nt * 8 + gid) * 68 + k + tig + 4]);
                mma_tf32(oacc[nt], pa, b);
            }
        }
        __syncthreads();
    }

    // ---- finalize: normalize, write merged-head ctx ----
    float inv0 = 1.0f / lrow0, inv1 = 1.0f / lrow1;
    int b_ = bh >> 2, h = bh & 3;
    int n0 = qt * 128 + wrow + gid;
    long base0 = ((long)(b_ * LGN + n0)) * LGD + h * 64;
    long base1 = base0 + 8L * LGD;
#pragma unroll
    for (int nt = 0; nt < 8; nt++) {
        int c = nt * 8 + 2 * tig;
        *(float2*)&ctx[base0 + c] = make_float2(oacc[nt][0] * inv0, oacc[nt][1] * inv0);
        *(float2*)&ctx[base1 + c] = make_float2(oacc[nt][2] * inv1, oacc[nt][3] * inv1);
    }
}

// -------------------- elementwise / reduction kernels ----------------------
__global__ void copy_k(float* dst, const float* src, int n) {
    int i = blockIdx.x * blockDim.x + threadIdx.x;
    if (i < n) dst[i] = src[i];
}

// copy x into the left half of cat (right half written by out-proj GEMM)
__global__ void xcat_k(const float* __restrict__ x, float* __restrict__ cat) {
    int t = blockIdx.x * blockDim.x + threadIdx.x;
    if (t >= M4 * 64) return;
    int r = t >> 6, c = t & 63;
    reinterpret_cast<float4*>(cat)[(long)r * 128 + c] =
        reinterpret_cast<const float4*>(x)[t];
}

// qkv [B,N,768] interleaved (q=3d, k=3d+1, v=3d+2) -> RoPE(q,k) -> [B*H,N,64]
__global__ void rope_split_k(const float* __restrict__ qkv,
                             const float* __restrict__ kpts,
                             const float* __restrict__ Wr,
                             float* __restrict__ Q, float* __restrict__ Kh,
                             float* __restrict__ V)
{
    int t = blockIdx.x * blockDim.x + threadIdx.x;
    if (t >= LGB * LGN * 128) return;
    int p  = t & 127;
    int bn = t >> 7;
    int n  = bn & (LGN - 1);
    int b  = bn >> 10;
    int d0 = 2 * p;
    int f  = p & 31;
    float kx = kpts[bn * 2 + 0], ky = kpts[bn * 2 + 1];
    float pr = kx * Wr[2 * f] + ky * Wr[2 * f + 1];
    float c = cosf(pr), s = sinf(pr);
    const float* q = qkv + (long)bn * 768;
    float q0 = q[3 * d0 + 0], q1 = q[3 * d0 + 3];
    float k0 = q[3 * d0 + 1], k1 = q[3 * d0 + 4];
    float v0 = q[3 * d0 + 2], v1 = q[3 * d0 + 5];
    int h = d0 >> 6, e0 = d0 & 63;
    long base = (((long)b * LGH + h) * LGN + n) * LGHD + e0;
    Q[base]      = c * q0 - s * q1;
    Q[base + 1]  = c * q1 + s * q0;
    Kh[base]     = c * k0 - s * k1;
    Kh[base + 1] = c * k1 + s * k0;
    V[base]      = v0;
    V[base + 1]  = v1;
}

__global__ void split_heads_k(const float* __restrict__ qk,
                              const float* __restrict__ v,
                              float* __restrict__ Q, float* __restrict__ V)
{
    int t = blockIdx.x * blockDim.x + threadIdx.x;
    if (t >= M4 * LGD) return;
    int d  = t & (LGD - 1);
    int bn = t >> 8;
    int n  = bn & (LGN - 1);
    int b  = bn >> 10;
    int h  = d >> 6, e = d & 63;
    long dst = (((long)b * LGH + h) * LGN + n) * LGHD + e;
    Q[dst] = qk[t];
    V[dst] = v[t];
}

// LayerNorm(512) + exact GELU
__global__ void lngelu_k(const float* __restrict__ h, const float* __restrict__ g,
                         const float* __restrict__ bb, float* __restrict__ o)
{
    long row = blockIdx.x;
    int tid = threadIdx.x;
    const float* p = h + row * 512;
    float x0 = p[tid], x1 = p[tid + 256];
    __shared__ float red[256];
    red[tid] = x0 + x1; __syncthreads();
    for (int s = 128; s > 0; s >>= 1) { if (tid < s) red[tid] += red[tid + s]; __syncthreads(); }
    float mean = red[0] * (1.0f / 512.0f);
    __syncthreads();
    red[tid] = x0 * x0 + x1 * x1; __syncthreads();
    for (int s = 128; s > 0; s >>= 1) { if (tid < s) red[tid] += red[tid + s]; __syncthreads(); }
    float var = red[0] * (1.0f / 512.0f) - mean * mean;
    float rr = rsqrtf(var + 1e-5f);
    float n0 = (x0 - mean) * rr * g[tid] + bb[tid];
    float n1 = (x1 - mean) * rr * g[tid + 256] + bb[tid + 256];
    o[row * 512 + tid]       = 0.5f * n0 * (1.0f + erff(n0 * 0.70710678118654752f));
    o[row * 512 + tid + 256] = 0.5f * n1 * (1.0f + erff(n1 * 0.70710678118654752f));
}

__global__ void z_k(const float* __restrict__ x, const float* __restrict__ w,
                    const float* __restrict__ b, float* __restrict__ z)
{
    long row = blockIdx.x;
    int tid = threadIdx.x;
    __shared__ float red[256];
    red[tid] = x[row * LGD + tid] * w[tid];
    __syncthreads();
    for (int s = 128; s > 0; s >>= 1) { if (tid < s) red[tid] += red[tid + s]; __syncthreads(); }
    if (tid == 0) z[row] = red[0] + b[0];
}

__global__ void lse_row_k(const float* __restrict__ sim, float* __restrict__ lser)
{
    long r = blockIdx.x;
    const float* p = sim + r * LGN;
    int tid = threadIdx.x;
    __shared__ float red[256];
    float m = -INFINITY;
    for (int j = tid; j < LGN; j += 256) m = fmaxf(m, p[j]);
    red[tid] = m; __syncthreads();
    for (int s = 128; s > 0; s >>= 1) { if (tid < s) red[tid] = fmaxf(red[tid], red[tid + s]); __syncthreads(); }
    m = red[0];
    __syncthreads();
    float sum = 0.0f;
    for (int j = tid; j < LGN; j += 256) sum += expf(p[j] - m);
    red[tid] = sum; __syncthreads();
    for (int s = 128; s > 0; s >>= 1) { if (tid < s) red[tid] += red[tid + s]; __syncthreads(); }
    if (tid == 0) lser[r] = m + logf(red[0]);
}

__global__ void lse_col_k(const float* __restrict__ sim, float* __restrict__ lsec)
{
    int cg = blockIdx.x & 31;
    int p  = blockIdx.x >> 5;
    int tid = threadIdx.x;
    int jc = (tid & 31);
    int j = cg * 32 + jc;
    int rg = tid >> 5;
    const float* base = sim + (long)p * LGN * LGN + j;
    float m = -INFINITY, s = 0.0f;
    for (int i = rg; i < LGN; i += 8) {
        float v = base[(long)i * LGN];
        if (v > m) { s = s * expf(m - v) + 1.0f; m = v; }
        else s += expf(v - m);
    }
    __shared__ float sm[8][33], ss[8][33];
    sm[rg][jc] = m; ss[rg][jc] = s;
    __syncthreads();
    if (tid < 32) {
        float M = sm[0][tid], S = ss[0][tid];
#pragma unroll
        for (int g = 1; g < 8; g++) {
            float m2 = sm[g][tid], s2 = ss[g][tid];
            if (m2 > M) { S = S * expf(M - m2) + s2; M = m2; }
            else S += s2 * expf(m2 - M);
        }
        lsec[p * LGN + cg * 32 + tid] = M + logf(S);
    }
}

__device__ __forceinline__ float lsig(float t) {
    return fminf(t, 0.0f) - log1pf(expf(-fabsf(t)));
}

__global__ void scores_k(const float* __restrict__ sim, const float* __restrict__ lser,
                         const float* __restrict__ lsec, const float* __restrict__ z,
                         float* __restrict__ out)
{
    long idx = (long)blockIdx.x * 256 + threadIdx.x;
    if (idx >= (long)NN2) return;
    int j = idx & (LGN - 1);
    long r = idx >> 10;
    int i = (int)(r & (LGN - 1));
    int p = (int)(r >> 10);
    float zq = z[(2 * p) * LGN + i];
    float zk = z[(2 * p + 1) * LGN + j];
    out[idx] = 2.0f * sim[idx] - lser[p * LGN + i] - lsec[p * LGN + j] + lsig(zq) + lsig(zk);
}

__global__ void argmax_row_k(const float* __restrict__ S, float* __restrict__ rmax,
                             int* __restrict__ m0)
{
    long i = blockIdx.x;
    const float* p = S + i * LGN;
    int tid = threadIdx.x;
    float bv = -INFINITY; int bi = 0;
    for (int j = tid; j < LGN; j += 256) {
        float v = p[j];
        if (v > bv) { bv = v; bi = j; }
    }
    __shared__ float sv[256]; __shared__ int si[256];
    sv[tid] = bv; si[tid] = bi; __syncthreads();
    for (int s = 128; s > 0; s >>= 1) {
        if (tid < s) {
            float v2 = sv[tid + s]; int i2 = si[tid + s];
            if (v2 > sv[tid] || (v2 == sv[tid] && i2 < si[tid])) { sv[tid] = v2; si[tid] = i2; }
        }
        __syncthreads();
    }
    if (tid == 0) { rmax[i] = sv[0]; m0[i] = si[0]; }
}

__global__ void argmax_col_k(const float* __restrict__ S, int* __restrict__ m1)
{
    int cg = blockIdx.x;
    int tid = threadIdx.x;
    int jc = tid & 31;
    int j = cg * 32 + jc;
    int rg = tid >> 5;
    float bv = -INFINITY; int bi = 0;
    for (int i = rg; i < LGN; i += 8) {
        float v = S[(long)i * LGN + j];
        if (v > bv || (v == bv && i < bi)) { bv = v; bi = i; }
    }
    __shared__ float sv[8][33]; __shared__ int si[8][33];
    sv[rg][jc] = bv; si[rg][jc] = bi;
    __syncthreads();
    if (tid < 32) {
        float V = sv[0][tid]; int I = si[0][tid];
#pragma unroll
        for (int g = 1; g < 8; g++) {
            float v2 = sv[g][tid]; int i2 = si[g][tid];
            if (v2 > V || (v2 == V && i2 < I)) { V = v2; I = i2; }
        }
        m1[cg * 32 + tid] = I;
    }
}

__global__ void filter_k(const int* __restrict__ m0, const int* __restrict__ m1,
                         const float* __restrict__ rmax, float* __restrict__ out)
{
    __shared__ float vals[LGN];
    __shared__ float rv[LGN];
    __shared__ int   ri[LGN];
    int n = threadIdx.x;
    float ms = expf(rmax[n]);
    bool mutual = (m1[m0[n]] == n);
    vals[n] = (mutual && ms > 0.1f) ? ms : 0.0f;
    __syncthreads();
    for (int k = 0; k < 50; k++) {
        rv[n] = vals[n]; ri[n] = n; __syncthreads();
        for (int s = 512; s > 0; s >>= 1) {
            if (n < s) {
                float v2 = rv[n + s]; int i2 = ri[n + s];
                if (v2 > rv[n] || (v2 == rv[n] && i2 < ri[n])) { rv[n] = v2; ri[n] = i2; }
            }
            __syncthreads();
        }
        if (n == 0) {
            int bi = ri[0]; float bv = rv[0];
            out[NN2 + k * 3 + 0] = 0.0f;
            out[NN2 + k * 3 + 1] = (float)bi;
            out[NN2 + k * 3 + 2] = (float)m0[bi];
            out[NN2 + 150 + k]   = bv;
            vals[bi] = -1.0f;
        }
        __syncthreads();
    }
}

// -------------------- host-side launchers ----------------------------------
static void tgemm(const float* A, const float* B, float* C,
                  int M, int N, int K, int ldC,
                  long sA, long sB, long sC, int batch,
                  const float* bias, const float* res, float alpha)
{
    dim3 grid(N / 128, M / 128, batch);
    tgemm_k<<<grid, 256>>>(A, B, C, M, N, K, ldC, sA, sB, sC, bias, res, alpha);
}

static const int FSMEM = (2 * 64 * 68 + 128 * 68) * 4;   // 69632 bytes

extern "C" void kernel_launch(void* const* d_in, const int* in_sizes, int n_in,
                              void* d_out, int out_size)
{
    (void)in_sizes; (void)n_in; (void)out_size;
    const float* kpts      = (const float*)d_in[0];
    const float* desc      = (const float*)d_in[1];
    const float* posenc_Wr = (const float*)d_in[2];
    const float* sWqkv_w   = (const float*)d_in[3];
    const float* sWqkv_b   = (const float*)d_in[4];
    const float* sOut_w    = (const float*)d_in[5];
    const float* sOut_b    = (const float*)d_in[6];
    const float* sF1_w     = (const float*)d_in[7];
    const float* sF1_b     = (const float*)d_in[8];
    const float* sLN_g     = (const float*)d_in[9];
    const float* sLN_b     = (const float*)d_in[10];
    const float* sF2_w     = (const float*)d_in[11];
    const float* sF2_b     = (const float*)d_in[12];
    const float* cQK_w     = (const float*)d_in[13];
    const float* cQK_b     = (const float*)d_in[14];
    const float* cV_w      = (const float*)d_in[15];
    const float* cV_b      = (const float*)d_in[16];
    const float* cOut_w    = (const float*)d_in[17];
    const float* cOut_b    = (const float*)d_in[18];
    const float* cF1_w     = (const float*)d_in[19];
    const float* cF1_b     = (const float*)d_in[20];
    const float* cLN_g     = (const float*)d_in[21];
    const float* cLN_b     = (const float*)d_in[22];
    const float* cF2_w     = (const float*)d_in[23];
    const float* cF2_b     = (const float*)d_in[24];
    const float* fp_w      = (const float*)d_in[25];
    const float* fp_b      = (const float*)d_in[26];
    const float* match_w   = (const float*)d_in[27];
    const float* match_b   = (const float*)d_in[28];
    float* out = (float*)d_out;

    float *x, *qkv, *vb, *Q, *K, *V, *ctx, *cat, *h1, *h2, *md, *sim, *z;
    float *lser, *lsec, *rmax;
    int *m0, *m1;
    cudaGetSymbolAddress((void**)&x,    g_x);
    cudaGetSymbolAddress((void**)&qkv,  g_qkv);
    cudaGetSymbolAddress((void**)&vb,   g_vbuf);
    cudaGetSymbolAddress((void**)&Q,    g_Q);
    cudaGetSymbolAddress((void**)&K,    g_K);
    cudaGetSymbolAddress((void**)&V,    g_V);
    cudaGetSymbolAddress((void**)&ctx,  g_ctx);
    cudaGetSymbolAddress((void**)&cat,  g_cat);
    cudaGetSymbolAddress((void**)&h1,   g_h1);
    cudaGetSymbolAddress((void**)&h2,   g_h2);
    cudaGetSymbolAddress((void**)&md,   g_md);
    cudaGetSymbolAddress((void**)&sim,  g_sim);
    cudaGetSymbolAddress((void**)&z,    g_z);
    cudaGetSymbolAddress((void**)&lser, g_lser);
    cudaGetSymbolAddress((void**)&lsec, g_lsec);
    cudaGetSymbolAddress((void**)&rmax, g_rmax);
    cudaGetSymbolAddress((void**)&m0,   g_m0);
    cudaGetSymbolAddress((void**)&m1,   g_m1);

    cudaFuncSetAttribute(flash_k, cudaFuncAttributeMaxDynamicSharedMemorySize, FSMEM);

    const long sSS = (long)LGN * LGN;

    copy_k<<<(M4 * LGD + 255) / 256, 256>>>(x, desc, M4 * LGD);

    for (int i = 0; i < LGL; i++) {
        // ---------------- self attention ----------------
        tgemm(x, sWqkv_w + (long)i * 3 * LGD * LGD, qkv, M4, 3 * LGD, LGD, 3 * LGD,
              0, 0, 0, 1, sWqkv_b + (long)i * 3 * LGD, nullptr, 1.0f);
        rope_split_k<<<(LGB * LGN * 128 + 255) / 256, 256>>>(qkv, kpts, posenc_Wr, Q, K, V);
        flash_k<<<dim3(8, BH), 256, FSMEM>>>(Q, K, V, ctx, 0);
        tgemm(ctx, sOut_w + (long)i * LGD * LGD, cat + LGD, M4, LGD, LGD, 2 * LGD,
              0, 0, 0, 1, sOut_b + (long)i * LGD, nullptr, 1.0f);
        xcat_k<<<(M4 * 64 + 255) / 256, 256>>>(x, cat);
        tgemm(cat, sF1_w + (long)i * 4 * LGD * LGD, h1, M4, 2 * LGD, 2 * LGD, 2 * LGD,
              0, 0, 0, 1, sF1_b + (long)i * 2 * LGD, nullptr, 1.0f);
        lngelu_k<<<M4, 256>>>(h1, sLN_g + (long)i * 2 * LGD, sLN_b + (long)i * 2 * LGD, h2);
        tgemm(h2, sF2_w + (long)i * 2 * LGD * LGD, x, M4, LGD, 2 * LGD, LGD,
              0, 0, 0, 1, sF2_b + (long)i * LGD, x, 1.0f);

        // ---------------- cross attention ----------------
        tgemm(x, cQK_w + (long)i * LGD * LGD, qkv, M4, LGD, LGD, LGD,
              0, 0, 0, 1, cQK_b + (long)i * LGD, nullptr, 1.0f);
        tgemm(x, cV_w + (long)i * LGD * LGD, vb, M4, LGD, LGD, LGD,
              0, 0, 0, 1, cV_b + (long)i * LGD, nullptr, 1.0f);
        split_heads_k<<<(M4 * LGD + 255) / 256, 256>>>(qkv, vb, Q, V);
        // keys/values from paired image: head index ^ 4 == batch ^ 1
        flash_k<<<dim3(8, BH), 256, FSMEM>>>(Q, Q, V, ctx, 4);
        tgemm(ctx, cOut_w + (long)i * LGD * LGD, cat + LGD, M4, LGD, LGD, 2 * LGD,
              0, 0, 0, 1, cOut_b + (long)i * LGD, nullptr, 1.0f);
        xcat_k<<<(M4 * 64 + 255) / 256, 256>>>(x, cat);
        tgemm(cat, cF1_w + (long)i * 4 * LGD * LGD, h1, M4, 2 * LGD, 2 * LGD, 2 * LGD,
              0, 0, 0, 1, cF1_b + (long)i * 2 * LGD, nullptr, 1.0f);
        lngelu_k<<<M4, 256>>>(h1, cLN_g + (long)i * 2 * LGD, cLN_b + (long)i * 2 * LGD, h2);
        tgemm(h2, cF2_w + (long)i * 2 * LGD * LGD, x, M4, LGD, 2 * LGD, LGD,
              0, 0, 0, 1, cF2_b + (long)i * LGD, x, 1.0f);
    }

    // ---------------- matching head ----------------
    tgemm(x, fp_w, md, M4, LGD, LGD, LGD, 0, 0, 0, 1, fp_b, nullptr, 0.25f);
    tgemm(md, md + (long)LGN * LGD, sim, LGN, LGN, LGD, LGN,
          (long)2 * LGN * LGD, (long)2 * LGN * LGD, sSS, 2, nullptr, nullptr, 1.0f);
    z_k<<<M4, 256>>>(x, match_w, match_b, z);
    lse_row_k<<<2 * LGN, 256>>>(sim, lser);
    lse_col_k<<<64, 256>>>(sim, lsec);
    scores_k<<<(NN2 + 255) / 256, 256>>>(sim, lser, lsec, z, out);

    // ---------------- filter (batch 0 only) ----------------
    argmax_row_k<<<LGN, 256>>>(out, rmax, m0);
    argmax_col_k<<<32, 256>>>(out, m1);
    filter_k<<<1, 1024>>>(m0, m1, rmax, out);
}

// round 4
// speedup vs baseline: 2.5907x; 1.2223x over previous
#include <cuda_runtime.h>
#include <cuda_bf16.h>
#include <math.h>
#include <stdint.h>

// ---------------------------------------------------------------------------
// LightGlue forward. L=9, D=256, H=4, HD=64, N=1024, B=4 (2 pairs).
// Dense GEMMs: tf32 mma.sync, K-step 32, cp.async double buffering.
// Attention: fused flash kernel, cp.async double-buffered K/V, 2 CTA/SM.
// ---------------------------------------------------------------------------

#define LGB   4
#define LGN   1024
#define LGD   256
#define LGH   4
#define LGHD  64
#define LGL   9
#define M4    (LGB*LGN)          // 4096 rows
#define BH    (LGB*LGH)          // 16 batched heads
#define NN2   (2*1024*1024)      // scores elements (2 pairs)

// -------------------- scratch (device globals; no allocation) --------------
__device__ float g_x   [M4*LGD];
__device__ float g_qkv [M4*3*LGD];
__device__ float g_vbuf[M4*LGD];
__device__ float g_Q   [BH*LGN*LGHD];
__device__ float g_K   [BH*LGN*LGHD];
__device__ float g_V   [BH*LGN*LGHD];
__device__ float g_ctx [M4*LGD];
__device__ float g_cat [M4*2*LGD];
__device__ float g_h1  [M4*2*LGD];
__device__ float g_h2  [M4*2*LGD];
__device__ float g_md  [M4*LGD];
__device__ float g_sim [NN2];
__device__ float g_z   [M4];
__device__ float g_lser[2*LGN];
__device__ float g_lsec[2*LGN];
__device__ int   g_m0  [LGN];
__device__ int   g_m1  [LGN];
__device__ float g_rmax[LGN];

// -------------------- tf32 helpers -----------------------------------------
__device__ __forceinline__ uint32_t tf32u(float x) {
    uint32_t u;
    asm("cvt.rna.tf32.f32 %0, %1;" : "=r"(u) : "f"(x));
    return u;
}

__device__ __forceinline__ void mma_tf32(float (&d)[4], const uint32_t (&a)[4],
                                         const uint32_t (&b)[2]) {
    asm volatile(
        "mma.sync.aligned.m16n8k8.row.col.f32.tf32.tf32.f32 "
        "{%0,%1,%2,%3}, {%4,%5,%6,%7}, {%8,%9}, {%0,%1,%2,%3};"
        : "+f"(d[0]), "+f"(d[1]), "+f"(d[2]), "+f"(d[3])
        : "r"(a[0]), "r"(a[1]), "r"(a[2]), "r"(a[3]), "r"(b[0]), "r"(b[1]));
}

__device__ __forceinline__ void cp16(void* dst, const void* src) {
    uint32_t d = (uint32_t)__cvta_generic_to_shared(dst);
    asm volatile("cp.async.cg.shared.global [%0], [%1], 16;" :: "r"(d), "l"(src));
}
__device__ __forceinline__ void cp_commit() { asm volatile("cp.async.commit_group;"); }
template<int n> __device__ __forceinline__ void cp_wait() {
    asm volatile("cp.async.wait_group %0;" :: "n"(n));
}

// -------------------- dense tf32 GEMM (NT only) -----------------------------
// C[m,n] = alpha*( sum_k A[m,k]*B[n,k] + bias[n] ) + res[m,n]
// Block 128x128, K-step 32, double-buffered cp.async, 8 warps (64x32 warp tile).
#define GSTR 36
#define GBUF (128*GSTR)
#define GSMEM (4*GBUF*4)          // 73728 bytes

__global__ void __launch_bounds__(256, 2) tgemm_k(
    const float* __restrict__ A, const float* __restrict__ B, float* C,
    int M, int N, int K, int ldC,
    long sA, long sB, long sC,
    const float* __restrict__ bias, const float* res, float alpha)
{
    extern __shared__ float sm[];
    float* As = sm;              // [2][128*36]
    float* Bs = sm + 2 * GBUF;   // [2][128*36]

    int bh = blockIdx.z;
    A += (long)bh * sA;
    B += (long)bh * sB;
    C += (long)bh * sC;
    if (res) res += (long)bh * sC;

    const int tid  = threadIdx.x;
    const int warp = tid >> 5, lane = tid & 31;
    const int wm = warp >> 2, wn = warp & 3;
    const int gid = lane >> 2, tig = lane & 3;
    const int row0 = blockIdx.y * 128;
    const int col0 = blockIdx.x * 128;

    float acc[4][4][4];
#pragma unroll
    for (int i = 0; i < 4; i++)
#pragma unroll
        for (int j = 0; j < 4; j++)
#pragma unroll
            for (int q = 0; q < 4; q++) acc[i][j][q] = 0.0f;

#define LOADT(s, k0) do {                                                      \
    _Pragma("unroll")                                                          \
    for (int l = 0; l < 4; l++) {                                              \
        int v = tid + 256 * l; int r = v >> 3; int off = (v & 7) * 4;          \
        cp16(&As[(s) * GBUF + r * GSTR + off],                                 \
             &A[(long)(row0 + r) * K + (k0) + off]);                           \
    }                                                                          \
    _Pragma("unroll")                                                          \
    for (int l = 0; l < 4; l++) {                                              \
        int v = tid + 256 * l; int r = v >> 3; int off = (v & 7) * 4;          \
        cp16(&Bs[(s) * GBUF + r * GSTR + off],                                 \
             &B[(long)(col0 + r) * K + (k0) + off]);                           \
    }                                                                          \
    cp_commit(); } while (0)

    const int NK = K >> 5;
    LOADT(0, 0);

    for (int it = 0; it < NK; it++) {
        int cur = it & 1;
        cp_wait<0>();
        __syncthreads();
        if (it + 1 < NK) LOADT(cur ^ 1, (it + 1) << 5);
        const float* Ab = As + cur * GBUF;
        const float* Bb = Bs + cur * GBUF;

#pragma unroll
        for (int ks = 0; ks < 32; ks += 8) {
            uint32_t ar[4][4];
#pragma unroll
            for (int tm = 0; tm < 4; tm++) {
                int mr = (wm * 64 + tm * 16 + gid) * GSTR;
                ar[tm][0] = tf32u(Ab[mr + ks + tig]);
                ar[tm][1] = tf32u(Ab[mr + 8 * GSTR + ks + tig]);
                ar[tm][2] = tf32u(Ab[mr + ks + tig + 4]);
                ar[tm][3] = tf32u(Ab[mr + 8 * GSTR + ks + tig + 4]);
            }
            uint32_t br[4][2];
#pragma unroll
            for (int tn = 0; tn < 4; tn++) {
                int nr = (wn * 32 + tn * 8 + gid) * GSTR;
                br[tn][0] = tf32u(Bb[nr + ks + tig]);
                br[tn][1] = tf32u(Bb[nr + ks + tig + 4]);
            }
#pragma unroll
            for (int tm = 0; tm < 4; tm++)
#pragma unroll
                for (int tn = 0; tn < 4; tn++)
                    mma_tf32(acc[tm][tn], ar[tm], br[tn]);
        }
        __syncthreads();
    }
#undef LOADT

#pragma unroll
    for (int tm = 0; tm < 4; tm++) {
        int r0 = row0 + wm * 64 + tm * 16 + gid;
#pragma unroll
        for (int tn = 0; tn < 4; tn++) {
            int c = col0 + wn * 32 + tn * 8 + tig * 2;
            float b0 = bias ? bias[c] : 0.0f;
            float b1 = bias ? bias[c + 1] : 0.0f;
#pragma unroll
            for (int half = 0; half < 2; half++) {
                int r = r0 + half * 8;
                float v0 = (acc[tm][tn][half * 2 + 0] + b0) * alpha;
                float v1 = (acc[tm][tn][half * 2 + 1] + b1) * alpha;
                if (res) {
                    v0 += res[(long)r * ldC + c];
                    v1 += res[(long)r * ldC + c + 1];
                }
                *reinterpret_cast<float2*>(&C[(long)r * ldC + c]) = make_float2(v0, v1);
            }
        }
    }
}

// -------------------- fused flash attention ---------------------------------
// Q,K,V: [16 heads][1024][64]. ctx out: [B*N][256] merged-head layout.
// grid (16 q-tiles of 64 rows, 16 heads), 128 threads (4 warps x 16 rows).
// cp.async double-buffered K/V. V kept [key][d] (stride 72, conflict-free).
#define FKS 68
#define FVS 72
#define FKBUF (64*FKS)
#define FVBUF (64*FVS)
#define FSMEM ((2*FKBUF + 2*FVBUF + 64*FKS) * 4)   // 89088 bytes

__global__ void __launch_bounds__(128, 2) flash_k(
    const float* __restrict__ Qg, const float* __restrict__ Kg,
    const float* __restrict__ Vg, float* __restrict__ ctx, int xorB)
{
    extern __shared__ float smf[];
    float* Ksm = smf;                       // [2][64][68]  K[key][d]
    float* Vsm = smf + 2 * FKBUF;           // [2][64][72]  V[key][d]
    float* Ps  = smf + 2 * FKBUF + 2 * FVBUF; // [64][68] Q staging, then P

    const int bh = blockIdx.y, qt = blockIdx.x;
    const float* Qh = Qg + (long)bh * (LGN * LGHD);
    const float* Kh = Kg + (long)(bh ^ xorB) * (LGN * LGHD);
    const float* Vh = Vg + (long)(bh ^ xorB) * (LGN * LGHD);

    const int tid = threadIdx.x, warp = tid >> 5, lane = tid & 31;
    const int gid = lane >> 2, tig = lane & 3;
    const int wrow = warp * 16;

    // ---- stage Q tile (64x64), extract scaled tf32 A-fragments ----
#pragma unroll
    for (int l = 0; l < 8; l++) {
        int v = tid + 128 * l;
        int r = v >> 4, c = (v & 15) * 4;
        float4 q = *(const float4*)&Qh[(long)(qt * 64 + r) * LGHD + c];
        Ps[r * FKS + c]     = q.x; Ps[r * FKS + c + 1] = q.y;
        Ps[r * FKS + c + 2] = q.z; Ps[r * FKS + c + 3] = q.w;
    }
    __syncthreads();
    uint32_t qa[8][4];
#pragma unroll
    for (int ks = 0; ks < 8; ks++) {
        int k = ks * 8;
        qa[ks][0] = tf32u(0.125f * Ps[(wrow + gid) * FKS + k + tig]);
        qa[ks][1] = tf32u(0.125f * Ps[(wrow + gid + 8) * FKS + k + tig]);
        qa[ks][2] = tf32u(0.125f * Ps[(wrow + gid) * FKS + k + tig + 4]);
        qa[ks][3] = tf32u(0.125f * Ps[(wrow + gid + 8) * FKS + k + tig + 4]);
    }

    float oacc[8][4];
#pragma unroll
    for (int nt = 0; nt < 8; nt++)
#pragma unroll
        for (int j = 0; j < 4; j++) oacc[nt][j] = 0.0f;
    float mrow0 = -INFINITY, mrow1 = -INFINITY, lrow0 = 0.0f, lrow1 = 0.0f;

#define LOADKV(s, kt) do {                                                     \
    _Pragma("unroll")                                                          \
    for (int l = 0; l < 8; l++) {                                              \
        int v = tid + 128 * l; int r = v >> 4; int c = (v & 15) * 4;           \
        cp16(&Ksm[(s) * FKBUF + r * FKS + c],                                  \
             &Kh[(long)((kt) * 64 + r) * LGHD + c]);                           \
    }                                                                          \
    _Pragma("unroll")                                                          \
    for (int l = 0; l < 8; l++) {                                              \
        int v = tid + 128 * l; int r = v >> 4; int c = (v & 15) * 4;           \
        cp16(&Vsm[(s) * FVBUF + r * FVS + c],                                  \
             &Vh[(long)((kt) * 64 + r) * LGHD + c]);                           \
    }                                                                          \
    cp_commit(); } while (0)

    LOADKV(0, 0);

    for (int kt = 0; kt < 16; kt++) {
        int cur = kt & 1;
        cp_wait<0>();
        __syncthreads();
        if (kt + 1 < 16) LOADKV(cur ^ 1, kt + 1);
        const float* K_ = Ksm + cur * FKBUF;
        const float* V_ = Vsm + cur * FVBUF;

        // S = (Q/8) K^T : 64x64
        float sacc[8][4];
#pragma unroll
        for (int nt = 0; nt < 8; nt++)
#pragma unroll
            for (int j = 0; j < 4; j++) sacc[nt][j] = 0.0f;
#pragma unroll
        for (int ks = 0; ks < 8; ks++) {
            int k = ks * 8;
#pragma unroll
            for (int nt = 0; nt < 8; nt++) {
                uint32_t b[2];
                b[0] = tf32u(K_[(nt * 8 + gid) * FKS + k + tig]);
                b[1] = tf32u(K_[(nt * 8 + gid) * FKS + k + tig + 4]);
                mma_tf32(sacc[nt], qa[ks], b);
            }
        }

        // ---- online softmax (rows gid, gid+8 owned by this quad) ----
        float t0 = -INFINITY, t1 = -INFINITY;
#pragma unroll
        for (int nt = 0; nt < 8; nt++) {
            t0 = fmaxf(t0, fmaxf(sacc[nt][0], sacc[nt][1]));
            t1 = fmaxf(t1, fmaxf(sacc[nt][2], sacc[nt][3]));
        }
        t0 = fmaxf(t0, __shfl_xor_sync(0xffffffffu, t0, 1));
        t0 = fmaxf(t0, __shfl_xor_sync(0xffffffffu, t0, 2));
        t1 = fmaxf(t1, __shfl_xor_sync(0xffffffffu, t1, 1));
        t1 = fmaxf(t1, __shfl_xor_sync(0xffffffffu, t1, 2));
        float mn0 = fmaxf(mrow0, t0), mn1 = fmaxf(mrow1, t1);
        float al0 = expf(mrow0 - mn0), al1 = expf(mrow1 - mn1);
        float s0 = 0.0f, s1 = 0.0f;
#pragma unroll
        for (int nt = 0; nt < 8; nt++) {
            sacc[nt][0] = expf(sacc[nt][0] - mn0);
            sacc[nt][1] = expf(sacc[nt][1] - mn0);
            sacc[nt][2] = expf(sacc[nt][2] - mn1);
            sacc[nt][3] = expf(sacc[nt][3] - mn1);
            s0 += sacc[nt][0] + sacc[nt][1];
            s1 += sacc[nt][2] + sacc[nt][3];
        }
        s0 += __shfl_xor_sync(0xffffffffu, s0, 1);
        s0 += __shfl_xor_sync(0xffffffffu, s0, 2);
        s1 += __shfl_xor_sync(0xffffffffu, s1, 1);
        s1 += __shfl_xor_sync(0xffffffffu, s1, 2);
        lrow0 = lrow0 * al0 + s0;
        lrow1 = lrow1 * al1 + s1;
        mrow0 = mn0; mrow1 = mn1;

        // rescale O, store P (tf32-rounded) into warp-local Ps rows
#pragma unroll
        for (int nt = 0; nt < 8; nt++) {
            oacc[nt][0] *= al0; oacc[nt][1] *= al0;
            oacc[nt][2] *= al1; oacc[nt][3] *= al1;
            int c = nt * 8 + 2 * tig;
            Ps[(wrow + gid) * FKS + c]         = __uint_as_float(tf32u(sacc[nt][0]));
            Ps[(wrow + gid) * FKS + c + 1]     = __uint_as_float(tf32u(sacc[nt][1]));
            Ps[(wrow + gid + 8) * FKS + c]     = __uint_as_float(tf32u(sacc[nt][2]));
            Ps[(wrow + gid + 8) * FKS + c + 1] = __uint_as_float(tf32u(sacc[nt][3]));
        }
        __syncwarp();

        // O += P V  (k-dim = 64 keys); V is [key][d], stride 72 (conflict-free)
#pragma unroll
        for (int ks = 0; ks < 8; ks++) {
            int k = ks * 8;
            uint32_t pa[4];
            pa[0] = __float_as_uint(Ps[(wrow + gid) * FKS + k + tig]);
            pa[1] = __float_as_uint(Ps[(wrow + gid + 8) * FKS + k + tig]);
            pa[2] = __float_as_uint(Ps[(wrow + gid) * FKS + k + tig + 4]);
            pa[3] = __float_as_uint(Ps[(wrow + gid + 8) * FKS + k + tig + 4]);
#pragma unroll
            for (int nt = 0; nt < 8; nt++) {
                uint32_t b[2];
                b[0] = tf32u(V_[(k + tig) * FVS + nt * 8 + gid]);
                b[1] = tf32u(V_[(k + tig + 4) * FVS + nt * 8 + gid]);
                mma_tf32(oacc[nt], pa, b);
            }
        }
        __syncthreads();
    }
#undef LOADKV

    // ---- finalize: normalize, write merged-head ctx ----
    float inv0 = 1.0f / lrow0, inv1 = 1.0f / lrow1;
    int b_ = bh >> 2, h = bh & 3;
    int n0 = qt * 64 + wrow + gid;
    long base0 = ((long)(b_ * LGN + n0)) * LGD + h * 64;
    long base1 = base0 + 8L * LGD;
#pragma unroll
    for (int nt = 0; nt < 8; nt++) {
        int c = nt * 8 + 2 * tig;
        *(float2*)&ctx[base0 + c] = make_float2(oacc[nt][0] * inv0, oacc[nt][1] * inv0);
        *(float2*)&ctx[base1 + c] = make_float2(oacc[nt][2] * inv1, oacc[nt][3] * inv1);
    }
}

// -------------------- elementwise / reduction kernels ----------------------
__global__ void copy_k(float* dst, const float* src, int n) {
    int i = blockIdx.x * blockDim.x + threadIdx.x;
    if (i < n) dst[i] = src[i];
}

// copy x into the left half of cat (right half written by out-proj GEMM)
__global__ void xcat_k(const float* __restrict__ x, float* __restrict__ cat) {
    int t = blockIdx.x * blockDim.x + threadIdx.x;
    if (t >= M4 * 64) return;
    int r = t >> 6, c = t & 63;
    reinterpret_cast<float4*>(cat)[(long)r * 128 + c] =
        reinterpret_cast<const float4*>(x)[t];
}

// qkv [B,N,768] interleaved (q=3d, k=3d+1, v=3d+2) -> RoPE(q,k) -> [B*H,N,64]
__global__ void rope_split_k(const float* __restrict__ qkv,
                             const float* __restrict__ kpts,
                             const float* __restrict__ Wr,
                             float* __restrict__ Q, float* __restrict__ Kh,
                             float* __restrict__ V)
{
    int t = blockIdx.x * blockDim.x + threadIdx.x;
    if (t >= LGB * LGN * 128) return;
    int p  = t & 127;
    int bn = t >> 7;
    int n  = bn & (LGN - 1);
    int b  = bn >> 10;
    int d0 = 2 * p;
    int f  = p & 31;
    float kx = kpts[bn * 2 + 0], ky = kpts[bn * 2 + 1];
    float pr = kx * Wr[2 * f] + ky * Wr[2 * f + 1];
    float c = cosf(pr), s = sinf(pr);
    const float* q = qkv + (long)bn * 768;
    float q0 = q[3 * d0 + 0], q1 = q[3 * d0 + 3];
    float k0 = q[3 * d0 + 1], k1 = q[3 * d0 + 4];
    float v0 = q[3 * d0 + 2], v1 = q[3 * d0 + 5];
    int h = d0 >> 6, e0 = d0 & 63;
    long base = (((long)b * LGH + h) * LGN + n) * LGHD + e0;
    Q[base]      = c * q0 - s * q1;
    Q[base + 1]  = c * q1 + s * q0;
    Kh[base]     = c * k0 - s * k1;
    Kh[base + 1] = c * k1 + s * k0;
    V[base]      = v0;
    V[base + 1]  = v1;
}

__global__ void split_heads_k(const float* __restrict__ qk,
                              const float* __restrict__ v,
                              float* __restrict__ Q, float* __restrict__ V)
{
    int t = blockIdx.x * blockDim.x + threadIdx.x;
    if (t >= M4 * LGD) return;
    int d  = t & (LGD - 1);
    int bn = t >> 8;
    int n  = bn & (LGN - 1);
    int b  = bn >> 10;
    int h  = d >> 6, e = d & 63;
    long dst = (((long)b * LGH + h) * LGN + n) * LGHD + e;
    Q[dst] = qk[t];
    V[dst] = v[t];
}

// LayerNorm(512) + exact GELU
__global__ void lngelu_k(const float* __restrict__ h, const float* __restrict__ g,
                         const float* __restrict__ bb, float* __restrict__ o)
{
    long row = blockIdx.x;
    int tid = threadIdx.x;
    const float* p = h + row * 512;
    float x0 = p[tid], x1 = p[tid + 256];
    __shared__ float red[256];
    red[tid] = x0 + x1; __syncthreads();
    for (int s = 128; s > 0; s >>= 1) { if (tid < s) red[tid] += red[tid + s]; __syncthreads(); }
    float mean = red[0] * (1.0f / 512.0f);
    __syncthreads();
    red[tid] = x0 * x0 + x1 * x1; __syncthreads();
    for (int s = 128; s > 0; s >>= 1) { if (tid < s) red[tid] += red[tid + s]; __syncthreads(); }
    float var = red[0] * (1.0f / 512.0f) - mean * mean;
    float rr = rsqrtf(var + 1e-5f);
    float n0 = (x0 - mean) * rr * g[tid] + bb[tid];
    float n1 = (x1 - mean) * rr * g[tid + 256] + bb[tid + 256];
    o[row * 512 + tid]       = 0.5f * n0 * (1.0f + erff(n0 * 0.70710678118654752f));
    o[row * 512 + tid + 256] = 0.5f * n1 * (1.0f + erff(n1 * 0.70710678118654752f));
}

__global__ void z_k(const float* __restrict__ x, const float* __restrict__ w,
                    const float* __restrict__ b, float* __restrict__ z)
{
    long row = blockIdx.x;
    int tid = threadIdx.x;
    __shared__ float red[256];
    red[tid] = x[row * LGD + tid] * w[tid];
    __syncthreads();
    for (int s = 128; s > 0; s >>= 1) { if (tid < s) red[tid] += red[tid + s]; __syncthreads(); }
    if (tid == 0) z[row] = red[0] + b[0];
}

__global__ void lse_row_k(const float* __restrict__ sim, float* __restrict__ lser)
{
    long r = blockIdx.x;
    const float* p = sim + r * LGN;
    int tid = threadIdx.x;
    __shared__ float red[256];
    float m = -INFINITY;
    for (int j = tid; j < LGN; j += 256) m = fmaxf(m, p[j]);
    red[tid] = m; __syncthreads();
    for (int s = 128; s > 0; s >>= 1) { if (tid < s) red[tid] = fmaxf(red[tid], red[tid + s]); __syncthreads(); }
    m = red[0];
    __syncthreads();
    float sum = 0.0f;
    for (int j = tid; j < LGN; j += 256) sum += expf(p[j] - m);
    red[tid] = sum; __syncthreads();
    for (int s = 128; s > 0; s >>= 1) { if (tid < s) red[tid] += red[tid + s]; __syncthreads(); }
    if (tid == 0) lser[r] = m + logf(red[0]);
}

__global__ void lse_col_k(const float* __restrict__ sim, float* __restrict__ lsec)
{
    int cg = blockIdx.x & 31;
    int p  = blockIdx.x >> 5;
    int tid = threadIdx.x;
    int jc = (tid & 31);
    int j = cg * 32 + jc;
    int rg = tid >> 5;
    const float* base = sim + (long)p * LGN * LGN + j;
    float m = -INFINITY, s = 0.0f;
    for (int i = rg; i < LGN; i += 8) {
        float v = base[(long)i * LGN];
        if (v > m) { s = s * expf(m - v) + 1.0f; m = v; }
        else s += expf(v - m);
    }
    __shared__ float sm[8][33], ss[8][33];
    sm[rg][jc] = m; ss[rg][jc] = s;
    __syncthreads();
    if (tid < 32) {
        float M = sm[0][tid], S = ss[0][tid];
#pragma unroll
        for (int g = 1; g < 8; g++) {
            float m2 = sm[g][tid], s2 = ss[g][tid];
            if (m2 > M) { S = S * expf(M - m2) + s2; M = m2; }
            else S += s2 * expf(m2 - M);
        }
        lsec[p * LGN + cg * 32 + tid] = M + logf(S);
    }
}

__device__ __forceinline__ float lsig(float t) {
    return fminf(t, 0.0f) - log1pf(expf(-fabsf(t)));
}

__global__ void scores_k(const float* __restrict__ sim, const float* __restrict__ lser,
                         const float* __restrict__ lsec, const float* __restrict__ z,
                         float* __restrict__ out)
{
    long idx = (long)blockIdx.x * 256 + threadIdx.x;
    if (idx >= (long)NN2) return;
    int j = idx & (LGN - 1);
    long r = idx >> 10;
    int i = (int)(r & (LGN - 1));
    int p = (int)(r >> 10);
    float zq = z[(2 * p) * LGN + i];
    float zk = z[(2 * p + 1) * LGN + j];
    out[idx] = 2.0f * sim[idx] - lser[p * LGN + i] - lsec[p * LGN + j] + lsig(zq) + lsig(zk);
}

__global__ void argmax_row_k(const float* __restrict__ S, float* __restrict__ rmax,
                             int* __restrict__ m0)
{
    long i = blockIdx.x;
    const float* p = S + i * LGN;
    int tid = threadIdx.x;
    float bv = -INFINITY; int bi = 0;
    for (int j = tid; j < LGN; j += 256) {
        float v = p[j];
        if (v > bv) { bv = v; bi = j; }
    }
    __shared__ float sv[256]; __shared__ int si[256];
    sv[tid] = bv; si[tid] = bi; __syncthreads();
    for (int s = 128; s > 0; s >>= 1) {
        if (tid < s) {
            float v2 = sv[tid + s]; int i2 = si[tid + s];
            if (v2 > sv[tid] || (v2 == sv[tid] && i2 < si[tid])) { sv[tid] = v2; si[tid] = i2; }
        }
        __syncthreads();
    }
    if (tid == 0) { rmax[i] = sv[0]; m0[i] = si[0]; }
}

__global__ void argmax_col_k(const float* __restrict__ S, int* __restrict__ m1)
{
    int cg = blockIdx.x;
    int tid = threadIdx.x;
    int jc = tid & 31;
    int j = cg * 32 + jc;
    int rg = tid >> 5;
    float bv = -INFINITY; int bi = 0;
    for (int i = rg; i < LGN; i += 8) {
        float v = S[(long)i * LGN + j];
        if (v > bv || (v == bv && i < bi)) { bv = v; bi = i; }
    }
    __shared__ float sv[8][33]; __shared__ int si[8][33];
    sv[rg][jc] = bv; si[rg][jc] = bi;
    __syncthreads();
    if (tid < 32) {
        float V = sv[0][tid]; int I = si[0][tid];
#pragma unroll
        for (int g = 1; g < 8; g++) {
            float v2 = sv[g][tid]; int i2 = si[g][tid];
            if (v2 > V || (v2 == V && i2 < I)) { V = v2; I = i2; }
        }
        m1[cg * 32 + tid] = I;
    }
}

__global__ void filter_k(const int* __restrict__ m0, const int* __restrict__ m1,
                         const float* __restrict__ rmax, float* __restrict__ out)
{
    __shared__ float vals[LGN];
    __shared__ float rv[LGN];
    __shared__ int   ri[LGN];
    int n = threadIdx.x;
    float ms = expf(rmax[n]);
    bool mutual = (m1[m0[n]] == n);
    vals[n] = (mutual && ms > 0.1f) ? ms : 0.0f;
    __syncthreads();
    for (int k = 0; k < 50; k++) {
        rv[n] = vals[n]; ri[n] = n; __syncthreads();
        for (int s = 512; s > 0; s >>= 1) {
            if (n < s) {
                float v2 = rv[n + s]; int i2 = ri[n + s];
                if (v2 > rv[n] || (v2 == rv[n] && i2 < ri[n])) { rv[n] = v2; ri[n] = i2; }
            }
            __syncthreads();
        }
        if (n == 0) {
            int bi = ri[0]; float bv = rv[0];
            out[NN2 + k * 3 + 0] = 0.0f;
            out[NN2 + k * 3 + 1] = (float)bi;
            out[NN2 + k * 3 + 2] = (float)m0[bi];
            out[NN2 + 150 + k]   = bv;
            vals[bi] = -1.0f;
        }
        __syncthreads();
    }
}

// -------------------- host-side launchers ----------------------------------
static void tgemm(const float* A, const float* B, float* C,
                  int M, int N, int K, int ldC,
                  long sA, long sB, long sC, int batch,
                  const float* bias, const float* res, float alpha)
{
    dim3 grid(N / 128, M / 128, batch);
    tgemm_k<<<grid, 256, GSMEM>>>(A, B, C, M, N, K, ldC, sA, sB, sC, bias, res, alpha);
}

extern "C" void kernel_launch(void* const* d_in, const int* in_sizes, int n_in,
                              void* d_out, int out_size)
{
    (void)in_sizes; (void)n_in; (void)out_size;
    const float* kpts      = (const float*)d_in[0];
    const float* desc      = (const float*)d_in[1];
    const float* posenc_Wr = (const float*)d_in[2];
    const float* sWqkv_w   = (const float*)d_in[3];
    const float* sWqkv_b   = (const float*)d_in[4];
    const float* sOut_w    = (const float*)d_in[5];
    const float* sOut_b    = (const float*)d_in[6];
    const float* sF1_w     = (const float*)d_in[7];
    const float* sF1_b     = (const float*)d_in[8];
    const float* sLN_g     = (const float*)d_in[9];
    const float* sLN_b     = (const float*)d_in[10];
    const float* sF2_w     = (const float*)d_in[11];
    const float* sF2_b     = (const float*)d_in[12];
    const float* cQK_w     = (const float*)d_in[13];
    const float* cQK_b     = (const float*)d_in[14];
    const float* cV_w      = (const float*)d_in[15];
    const float* cV_b      = (const float*)d_in[16];
    const float* cOut_w    = (const float*)d_in[17];
    const float* cOut_b    = (const float*)d_in[18];
    const float* cF1_w     = (const float*)d_in[19];
    const float* cF1_b     = (const float*)d_in[20];
    const float* cLN_g     = (const float*)d_in[21];
    const float* cLN_b     = (const float*)d_in[22];
    const float* cF2_w     = (const float*)d_in[23];
    const float* cF2_b     = (const float*)d_in[24];
    const float* fp_w      = (const float*)d_in[25];
    const float* fp_b      = (const float*)d_in[26];
    const float* match_w   = (const float*)d_in[27];
    const float* match_b   = (const float*)d_in[28];
    float* out = (float*)d_out;

    float *x, *qkv, *vb, *Q, *K, *V, *ctx, *cat, *h1, *h2, *md, *sim, *z;
    float *lser, *lsec, *rmax;
    int *m0, *m1;
    cudaGetSymbolAddress((void**)&x,    g_x);
    cudaGetSymbolAddress((void**)&qkv,  g_qkv);
    cudaGetSymbolAddress((void**)&vb,   g_vbuf);
    cudaGetSymbolAddress((void**)&Q,    g_Q);
    cudaGetSymbolAddress((void**)&K,    g_K);
    cudaGetSymbolAddress((void**)&V,    g_V);
    cudaGetSymbolAddress((void**)&ctx,  g_ctx);
    cudaGetSymbolAddress((void**)&cat,  g_cat);
    cudaGetSymbolAddress((void**)&h1,   g_h1);
    cudaGetSymbolAddress((void**)&h2,   g_h2);
    cudaGetSymbolAddress((void**)&md,   g_md);
    cudaGetSymbolAddress((void**)&sim,  g_sim);
    cudaGetSymbolAddress((void**)&z,    g_z);
    cudaGetSymbolAddress((void**)&lser, g_lser);
    cudaGetSymbolAddress((void**)&lsec, g_lsec);
    cudaGetSymbolAddress((void**)&rmax, g_rmax);
    cudaGetSymbolAddress((void**)&m0,   g_m0);
    cudaGetSymbolAddress((void**)&m1,   g_m1);

    cudaFuncSetAttribute(flash_k, cudaFuncAttributeMaxDynamicSharedMemorySize, FSMEM);
    cudaFuncSetAttribute(tgemm_k, cudaFuncAttributeMaxDynamicSharedMemorySize, GSMEM);

    const long sSS = (long)LGN * LGN;

    copy_k<<<(M4 * LGD + 255) / 256, 256>>>(x, desc, M4 * LGD);

    for (int i = 0; i < LGL; i++) {
        // ---------------- self attention ----------------
        tgemm(x, sWqkv_w + (long)i * 3 * LGD * LGD, qkv, M4, 3 * LGD, LGD, 3 * LGD,
              0, 0, 0, 1, sWqkv_b + (long)i * 3 * LGD, nullptr, 1.0f);
        rope_split_k<<<(LGB * LGN * 128 + 255) / 256, 256>>>(qkv, kpts, posenc_Wr, Q, K, V);
        flash_k<<<dim3(16, BH), 128, FSMEM>>>(Q, K, V, ctx, 0);
        tgemm(ctx, sOut_w + (long)i * LGD * LGD, cat + LGD, M4, LGD, LGD, 2 * LGD,
              0, 0, 0, 1, sOut_b + (long)i * LGD, nullptr, 1.0f);
        xcat_k<<<(M4 * 64 + 255) / 256, 256>>>(x, cat);
        tgemm(cat, sF1_w + (long)i * 4 * LGD * LGD, h1, M4, 2 * LGD, 2 * LGD, 2 * LGD,
              0, 0, 0, 1, sF1_b + (long)i * 2 * LGD, nullptr, 1.0f);
        lngelu_k<<<M4, 256>>>(h1, sLN_g + (long)i * 2 * LGD, sLN_b + (long)i * 2 * LGD, h2);
        tgemm(h2, sF2_w + (long)i * 2 * LGD * LGD, x, M4, LGD, 2 * LGD, LGD,
              0, 0, 0, 1, sF2_b + (long)i * LGD, x, 1.0f);

        // ---------------- cross attention ----------------
        tgemm(x, cQK_w + (long)i * LGD * LGD, qkv, M4, LGD, LGD, LGD,
              0, 0, 0, 1, cQK_b + (long)i * LGD, nullptr, 1.0f);
        tgemm(x, cV_w + (long)i * LGD * LGD, vb, M4, LGD, LGD, LGD,
              0, 0, 0, 1, cV_b + (long)i * LGD, nullptr, 1.0f);
        split_heads_k<<<(M4 * LGD + 255) / 256, 256>>>(qkv, vb, Q, V);
        // keys/values from paired image: head index ^ 4 == batch ^ 1
        flash_k<<<dim3(16, BH), 128, FSMEM>>>(Q, Q, V, ctx, 4);
        tgemm(ctx, cOut_w + (long)i * LGD * LGD, cat + LGD, M4, LGD, LGD, 2 * LGD,
              0, 0, 0, 1, cOut_b + (long)i * LGD, nullptr, 1.0f);
        xcat_k<<<(M4 * 64 + 255) / 256, 256>>>(x, cat);
        tgemm(cat, cF1_w + (long)i * 4 * LGD * LGD, h1, M4, 2 * LGD, 2 * LGD, 2 * LGD,
              0, 0, 0, 1, cF1_b + (long)i * 2 * LGD, nullptr, 1.0f);
        lngelu_k<<<M4, 256>>>(h1, cLN_g + (long)i * 2 * LGD, cLN_b + (long)i * 2 * LGD, h2);
        tgemm(h2, cF2_w + (long)i * 2 * LGD * LGD, x, M4, LGD, 2 * LGD, LGD,
              0, 0, 0, 1, cF2_b + (long)i * LGD, x, 1.0f);
    }

    // ---------------- matching head ----------------
    tgemm(x, fp_w, md, M4, LGD, LGD, LGD, 0, 0, 0, 1, fp_b, nullptr, 0.25f);
    tgemm(md, md + (long)LGN * LGD, sim, LGN, LGN, LGD, LGN,
          (long)2 * LGN * LGD, (long)2 * LGN * LGD, sSS, 2, nullptr, nullptr, 1.0f);
    z_k<<<M4, 256>>>(x, match_w, match_b, z);
    lse_row_k<<<2 * LGN, 256>>>(sim, lser);
    lse_col_k<<<64, 256>>>(sim, lsec);
    scores_k<<<(NN2 + 255) / 256, 256>>>(sim, lser, lsec, z, out);

    // ---------------- filter (batch 0 only) ----------------
    argmax_row_k<<<LGN, 256>>>(out, rmax, m0);
    argmax_col_k<<<32, 256>>>(out, m1);
    filter_k<<<1, 1024>>>(m0, m1, rmax, out);
}

// round 5
// speedup vs baseline: 2.6957x; 1.0405x over previous
#include <cuda_runtime.h>
#include <cuda_bf16.h>
#include <math.h>
#include <stdint.h>

// ---------------------------------------------------------------------------
// LightGlue forward. L=9, D=256, H=4, HD=64, N=1024, B=4 (2 pairs).
// Dense GEMMs: tf32 mma.sync, K-step 32, cp.async double buffering,
//              BM=128 (N>512) and BM=64 (N<=512) tiles.
// Attention: fused flash kernel, cp.async double-buffered K/V, no CVT in loop.
// ---------------------------------------------------------------------------

#define LGB   4
#define LGN   1024
#define LGD   256
#define LGH   4
#define LGHD  64
#define LGL   9
#define M4    (LGB*LGN)
#define BH    (LGB*LGH)
#define NN2   (2*1024*1024)

// -------------------- scratch (device globals; no allocation) --------------
__device__ float g_x   [M4*LGD];
__device__ float g_qkv [M4*3*LGD];
__device__ float g_vbuf[M4*LGD];
__device__ float g_Q   [BH*LGN*LGHD];
__device__ float g_K   [BH*LGN*LGHD];
__device__ float g_V   [BH*LGN*LGHD];
__device__ float g_ctx [M4*LGD];
__device__ float g_cat [M4*2*LGD];
__device__ float g_h1  [M4*2*LGD];
__device__ float g_h2  [M4*2*LGD];
__device__ float g_md  [M4*LGD];
__device__ float g_sim [NN2];
__device__ float g_z   [M4];
__device__ float g_lser[2*LGN];
__device__ float g_lsec[2*LGN];
__device__ int   g_m0  [LGN];
__device__ int   g_m1  [LGN];
__device__ float g_rmax[LGN];

// -------------------- tf32 helpers -----------------------------------------
__device__ __forceinline__ uint32_t tf32u(float x) {
    uint32_t u;
    asm("cvt.rna.tf32.f32 %0, %1;" : "=r"(u) : "f"(x));
    return u;
}
__device__ __forceinline__ float tf32r(float x) { return __uint_as_float(tf32u(x)); }

__device__ __forceinline__ void mma_tf32(float (&d)[4], const uint32_t (&a)[4],
                                         const uint32_t (&b)[2]) {
    asm volatile(
        "mma.sync.aligned.m16n8k8.row.col.f32.tf32.tf32.f32 "
        "{%0,%1,%2,%3}, {%4,%5,%6,%7}, {%8,%9}, {%0,%1,%2,%3};"
        : "+f"(d[0]), "+f"(d[1]), "+f"(d[2]), "+f"(d[3])
        : "r"(a[0]), "r"(a[1]), "r"(a[2]), "r"(a[3]), "r"(b[0]), "r"(b[1]));
}

__device__ __forceinline__ void cp16(void* dst, const void* src) {
    uint32_t d = (uint32_t)__cvta_generic_to_shared(dst);
    asm volatile("cp.async.cg.shared.global [%0], [%1], 16;" :: "r"(d), "l"(src));
}
__device__ __forceinline__ void cp_commit() { asm volatile("cp.async.commit_group;"); }
template<int n> __device__ __forceinline__ void cp_wait() {
    asm volatile("cp.async.wait_group %0;" :: "n"(n));
}

// -------------------- dense tf32 GEMM (NT only) -----------------------------
// C[m,n] = alpha*( sum_k A[m,k]*B[n,k] + bias[n] ) + res[m,n];  optional 2nd
// destination C2 (ld 512) for the concat fusion.
// Block BM x 128, K-step 32, double-buffered cp.async.
#define GSTR 36

template<int BM>
__global__ void __launch_bounds__(BM * 2, (BM == 128) ? 2 : 3) tgemm_k(
    const float* __restrict__ A, const float* __restrict__ B, float* C,
    int M, int N, int K, int ldC,
    long sA, long sB, long sC,
    const float* __restrict__ bias, const float* res, float alpha,
    float* C2)
{
    constexpr int THREADS = BM * 2;
    constexpr int WCNT = (BM == 128) ? 4 : 2;     // warp columns
    constexpr int TM   = BM / 32;                 // m16 tiles per warp
    constexpr int TN   = 16 / WCNT;               // n8 tiles per warp
    constexpr int ABUF = BM * GSTR;
    constexpr int BBUF = 128 * GSTR;

    extern __shared__ float sm[];
    float* As = sm;                   // [2][BM*36]
    float* Bs = sm + 2 * ABUF;        // [2][128*36]

    int bh = blockIdx.z;
    A += (long)bh * sA;
    B += (long)bh * sB;
    C += (long)bh * sC;
    if (res) res += (long)bh * sC;

    const int tid  = threadIdx.x;
    const int warp = tid >> 5, lane = tid & 31;
    const int wm = warp / WCNT, wn = warp % WCNT;
    const int gid = lane >> 2, tig = lane & 3;
    const int row0 = blockIdx.y * BM;
    const int col0 = blockIdx.x * 128;

    float acc[TM][TN][4];
#pragma unroll
    for (int i = 0; i < TM; i++)
#pragma unroll
        for (int j = 0; j < TN; j++)
#pragma unroll
            for (int q = 0; q < 4; q++) acc[i][j][q] = 0.0f;

#define LOADT(s, k0) do {                                                      \
    _Pragma("unroll")                                                          \
    for (int l = 0; l < BM * 8 / THREADS; l++) {                               \
        int v = tid + THREADS * l; int r = v >> 3; int off = (v & 7) * 4;      \
        cp16(&As[(s) * ABUF + r * GSTR + off],                                 \
             &A[(long)(row0 + r) * K + (k0) + off]);                           \
    }                                                                          \
    _Pragma("unroll")                                                          \
    for (int l = 0; l < 1024 / THREADS; l++) {                                 \
        int v = tid + THREADS * l; int r = v >> 3; int off = (v & 7) * 4;      \
        cp16(&Bs[(s) * BBUF + r * GSTR + off],                                 \
             &B[(long)(col0 + r) * K + (k0) + off]);                           \
    }                                                                          \
    cp_commit(); } while (0)

    const int NK = K >> 5;
    LOADT(0, 0);

    for (int it = 0; it < NK; it++) {
        int cur = it & 1;
        cp_wait<0>();
        __syncthreads();
        if (it + 1 < NK) LOADT(cur ^ 1, (it + 1) << 5);
        const float* Ab = As + cur * ABUF;
        const float* Bb = Bs + cur * BBUF;

#pragma unroll
        for (int ks = 0; ks < 32; ks += 8) {
            uint32_t ar[TM][4];
#pragma unroll
            for (int tm = 0; tm < TM; tm++) {
                int mr = (wm * (TM * 16) + tm * 16 + gid) * GSTR;
                ar[tm][0] = tf32u(Ab[mr + ks + tig]);
                ar[tm][1] = tf32u(Ab[mr + 8 * GSTR + ks + tig]);
                ar[tm][2] = tf32u(Ab[mr + ks + tig + 4]);
                ar[tm][3] = tf32u(Ab[mr + 8 * GSTR + ks + tig + 4]);
            }
            uint32_t br[TN][2];
#pragma unroll
            for (int tn = 0; tn < TN; tn++) {
                int nr = (wn * (TN * 8) + tn * 8 + gid) * GSTR;
                br[tn][0] = tf32u(Bb[nr + ks + tig]);
                br[tn][1] = tf32u(Bb[nr + ks + tig + 4]);
            }
#pragma unroll
            for (int tm = 0; tm < TM; tm++)
#pragma unroll
                for (int tn = 0; tn < TN; tn++)
                    mma_tf32(acc[tm][tn], ar[tm], br[tn]);
        }
        __syncthreads();
    }
#undef LOADT

#pragma unroll
    for (int tm = 0; tm < TM; tm++) {
        int r0 = row0 + wm * (TM * 16) + tm * 16 + gid;
#pragma unroll
        for (int tn = 0; tn < TN; tn++) {
            int c = col0 + wn * (TN * 8) + tn * 8 + tig * 2;
            float b0 = bias ? bias[c] : 0.0f;
            float b1 = bias ? bias[c + 1] : 0.0f;
#pragma unroll
            for (int half = 0; half < 2; half++) {
                int r = r0 + half * 8;
                float v0 = (acc[tm][tn][half * 2 + 0] + b0) * alpha;
                float v1 = (acc[tm][tn][half * 2 + 1] + b1) * alpha;
                if (res) {
                    v0 += res[(long)r * ldC + c];
                    v1 += res[(long)r * ldC + c + 1];
                }
                *reinterpret_cast<float2*>(&C[(long)r * ldC + c]) = make_float2(v0, v1);
                if (C2)
                    *reinterpret_cast<float2*>(&C2[(long)r * 512 + c]) = make_float2(v0, v1);
            }
        }
    }
}

// -------------------- fused flash attention ---------------------------------
// Q,K,V: [16 heads][1024][64], PRE-ROUNDED to tf32 by producers.
// ctx out: [B*N][256] merged-head layout.
// grid (16 q-tiles of 64 rows, 16 heads), 128 threads (4 warps x 16 rows).
#define FKS 68
#define FVS 72
#define FKBUF (64*FKS)
#define FVBUF (64*FVS)
#define FSMEM ((2*FKBUF + 2*FVBUF + 64*FKS) * 4)   // 89088 bytes

__global__ void __launch_bounds__(128, 2) flash_k(
    const float* __restrict__ Qg, const float* __restrict__ Kg,
    const float* __restrict__ Vg, float* __restrict__ ctx, int xorB)
{
    extern __shared__ float smf[];
    float* Ksm = smf;                         // [2][64][68]
    float* Vsm = smf + 2 * FKBUF;             // [2][64][72]
    float* Ps  = smf + 2 * FKBUF + 2 * FVBUF; // [64][68]

    const int bh = blockIdx.y, qt = blockIdx.x;
    const float* Qh = Qg + (long)bh * (LGN * LGHD);
    const float* Kh = Kg + (long)(bh ^ xorB) * (LGN * LGHD);
    const float* Vh = Vg + (long)(bh ^ xorB) * (LGN * LGHD);

    const int tid = threadIdx.x, warp = tid >> 5, lane = tid & 31;
    const int gid = lane >> 2, tig = lane & 3;
    const int wrow = warp * 16;

    // ---- stage Q tile (64x64) pre-scaled by 1/8 (exact) ----
#pragma unroll
    for (int l = 0; l < 8; l++) {
        int v = tid + 128 * l;
        int r = v >> 4, c = (v & 15) * 4;
        float4 q = *(const float4*)&Qh[(long)(qt * 64 + r) * LGHD + c];
        Ps[r * FKS + c]     = 0.125f * q.x; Ps[r * FKS + c + 1] = 0.125f * q.y;
        Ps[r * FKS + c + 2] = 0.125f * q.z; Ps[r * FKS + c + 3] = 0.125f * q.w;
    }
    __syncthreads();
    uint32_t qa[8][4];
#pragma unroll
    for (int ks = 0; ks < 8; ks++) {
        int k = ks * 8;
        qa[ks][0] = __float_as_uint(Ps[(wrow + gid) * FKS + k + tig]);
        qa[ks][1] = __float_as_uint(Ps[(wrow + gid + 8) * FKS + k + tig]);
        qa[ks][2] = __float_as_uint(Ps[(wrow + gid) * FKS + k + tig + 4]);
        qa[ks][3] = __float_as_uint(Ps[(wrow + gid + 8) * FKS + k + tig + 4]);
    }

    float oacc[8][4];
#pragma unroll
    for (int nt = 0; nt < 8; nt++)
#pragma unroll
        for (int j = 0; j < 4; j++) oacc[nt][j] = 0.0f;
    float mrow0 = -INFINITY, mrow1 = -INFINITY, lrow0 = 0.0f, lrow1 = 0.0f;

#define LOADKV(s, kt) do {                                                     \
    _Pragma("unroll")                                                          \
    for (int l = 0; l < 8; l++) {                                              \
        int v = tid + 128 * l; int r = v >> 4; int c = (v & 15) * 4;           \
        cp16(&Ksm[(s) * FKBUF + r * FKS + c],                                  \
             &Kh[(long)((kt) * 64 + r) * LGHD + c]);                           \
    }                                                                          \
    _Pragma("unroll")                                                          \
    for (int l = 0; l < 8; l++) {                                              \
        int v = tid + 128 * l; int r = v >> 4; int c = (v & 15) * 4;           \
        cp16(&Vsm[(s) * FVBUF + r * FVS + c],                                  \
             &Vh[(long)((kt) * 64 + r) * LGHD + c]);                           \
    }                                                                          \
    cp_commit(); } while (0)

    LOADKV(0, 0);

    for (int kt = 0; kt < 16; kt++) {
        int cur = kt & 1;
        cp_wait<0>();
        __syncthreads();
        if (kt + 1 < 16) LOADKV(cur ^ 1, kt + 1);
        const float* K_ = Ksm + cur * FKBUF;
        const float* V_ = Vsm + cur * FVBUF;

        // S = (Q/8) K^T : 64x64
        float sacc[8][4];
#pragma unroll
        for (int nt = 0; nt < 8; nt++)
#pragma unroll
            for (int j = 0; j < 4; j++) sacc[nt][j] = 0.0f;
#pragma unroll
        for (int ks = 0; ks < 8; ks++) {
            int k = ks * 8;
#pragma unroll
            for (int nt = 0; nt < 8; nt++) {
                uint32_t b[2];
                b[0] = __float_as_uint(K_[(nt * 8 + gid) * FKS + k + tig]);
                b[1] = __float_as_uint(K_[(nt * 8 + gid) * FKS + k + tig + 4]);
                mma_tf32(sacc[nt], qa[ks], b);
            }
        }

        // ---- online softmax (rows gid, gid+8 owned by this quad) ----
        float t0 = -INFINITY, t1 = -INFINITY;
#pragma unroll
        for (int nt = 0; nt < 8; nt++) {
            t0 = fmaxf(t0, fmaxf(sacc[nt][0], sacc[nt][1]));
            t1 = fmaxf(t1, fmaxf(sacc[nt][2], sacc[nt][3]));
        }
        t0 = fmaxf(t0, __shfl_xor_sync(0xffffffffu, t0, 1));
        t0 = fmaxf(t0, __shfl_xor_sync(0xffffffffu, t0, 2));
        t1 = fmaxf(t1, __shfl_xor_sync(0xffffffffu, t1, 1));
        t1 = fmaxf(t1, __shfl_xor_sync(0xffffffffu, t1, 2));
        float mn0 = fmaxf(mrow0, t0), mn1 = fmaxf(mrow1, t1);
        float al0 = expf(mrow0 - mn0), al1 = expf(mrow1 - mn1);
        float s0 = 0.0f, s1 = 0.0f;
#pragma unroll
        for (int nt = 0; nt < 8; nt++) {
            sacc[nt][0] = expf(sacc[nt][0] - mn0);
            sacc[nt][1] = expf(sacc[nt][1] - mn0);
            sacc[nt][2] = expf(sacc[nt][2] - mn1);
            sacc[nt][3] = expf(sacc[nt][3] - mn1);
            s0 += sacc[nt][0] + sacc[nt][1];
            s1 += sacc[nt][2] + sacc[nt][3];
        }
        s0 += __shfl_xor_sync(0xffffffffu, s0, 1);
        s0 += __shfl_xor_sync(0xffffffffu, s0, 2);
        s1 += __shfl_xor_sync(0xffffffffu, s1, 1);
        s1 += __shfl_xor_sync(0xffffffffu, s1, 2);
        lrow0 = lrow0 * al0 + s0;
        lrow1 = lrow1 * al1 + s1;
        mrow0 = mn0; mrow1 = mn1;

        // rescale O, store P (tf32-rounded) into warp-local Ps rows
#pragma unroll
        for (int nt = 0; nt < 8; nt++) {
            oacc[nt][0] *= al0; oacc[nt][1] *= al0;
            oacc[nt][2] *= al1; oacc[nt][3] *= al1;
            int c = nt * 8 + 2 * tig;
            Ps[(wrow + gid) * FKS + c]         = __uint_as_float(tf32u(sacc[nt][0]));
            Ps[(wrow + gid) * FKS + c + 1]     = __uint_as_float(tf32u(sacc[nt][1]));
            Ps[(wrow + gid + 8) * FKS + c]     = __uint_as_float(tf32u(sacc[nt][2]));
            Ps[(wrow + gid + 8) * FKS + c + 1] = __uint_as_float(tf32u(sacc[nt][3]));
        }
        __syncwarp();

        // O += P V  (V is [key][d], stride 72, pre-rounded)
#pragma unroll
        for (int ks = 0; ks < 8; ks++) {
            int k = ks * 8;
            uint32_t pa[4];
            pa[0] = __float_as_uint(Ps[(wrow + gid) * FKS + k + tig]);
            pa[1] = __float_as_uint(Ps[(wrow + gid + 8) * FKS + k + tig]);
            pa[2] = __float_as_uint(Ps[(wrow + gid) * FKS + k + tig + 4]);
            pa[3] = __float_as_uint(Ps[(wrow + gid + 8) * FKS + k + tig + 4]);
#pragma unroll
            for (int nt = 0; nt < 8; nt++) {
                uint32_t b[2];
                b[0] = __float_as_uint(V_[(k + tig) * FVS + nt * 8 + gid]);
                b[1] = __float_as_uint(V_[(k + tig + 4) * FVS + nt * 8 + gid]);
                mma_tf32(oacc[nt], pa, b);
            }
        }
        __syncthreads();
    }
#undef LOADKV

    // ---- finalize: normalize, write merged-head ctx ----
    float inv0 = 1.0f / lrow0, inv1 = 1.0f / lrow1;
    int b_ = bh >> 2, h = bh & 3;
    int n0 = qt * 64 + wrow + gid;
    long base0 = ((long)(b_ * LGN + n0)) * LGD + h * 64;
    long base1 = base0 + 8L * LGD;
#pragma unroll
    for (int nt = 0; nt < 8; nt++) {
        int c = nt * 8 + 2 * tig;
        *(float2*)&ctx[base0 + c] = make_float2(oacc[nt][0] * inv0, oacc[nt][1] * inv0);
        *(float2*)&ctx[base1 + c] = make_float2(oacc[nt][2] * inv1, oacc[nt][3] * inv1);
    }
}

// -------------------- elementwise / reduction kernels ----------------------
// initial copy: x and cat-left
__global__ void copy2_k(const float* __restrict__ src, float* __restrict__ x,
                        float* __restrict__ cat) {
    int i = blockIdx.x * blockDim.x + threadIdx.x;
    if (i >= M4 * LGD) return;
    float v = src[i];
    x[i] = v;
    int r = i >> 8, c = i & 255;
    cat[(long)r * 512 + c] = v;
}

// qkv [B,N,768] interleaved -> RoPE(q,k) -> [B*H,N,64], tf32-rounded outputs
__global__ void rope_split_k(const float* __restrict__ qkv,
                             const float* __restrict__ kpts,
                             const float* __restrict__ Wr,
                             float* __restrict__ Q, float* __restrict__ Kh,
                             float* __restrict__ V)
{
    int t = blockIdx.x * blockDim.x + threadIdx.x;
    if (t >= LGB * LGN * 128) return;
    int p  = t & 127;
    int bn = t >> 7;
    int n  = bn & (LGN - 1);
    int b  = bn >> 10;
    int d0 = 2 * p;
    int f  = p & 31;
    float kx = kpts[bn * 2 + 0], ky = kpts[bn * 2 + 1];
    float pr = kx * Wr[2 * f] + ky * Wr[2 * f + 1];
    float c = cosf(pr), s = sinf(pr);
    const float* q = qkv + (long)bn * 768;
    float q0 = q[3 * d0 + 0], q1 = q[3 * d0 + 3];
    float k0 = q[3 * d0 + 1], k1 = q[3 * d0 + 4];
    float v0 = q[3 * d0 + 2], v1 = q[3 * d0 + 5];
    int h = d0 >> 6, e0 = d0 & 63;
    long base = (((long)b * LGH + h) * LGN + n) * LGHD + e0;
    Q[base]      = tf32r(c * q0 - s * q1);
    Q[base + 1]  = tf32r(c * q1 + s * q0);
    Kh[base]     = tf32r(c * k0 - s * k1);
    Kh[base + 1] = tf32r(c * k1 + s * k0);
    V[base]      = tf32r(v0);
    V[base + 1]  = tf32r(v1);
}

__global__ void split_heads_k(const float* __restrict__ qk,
                              const float* __restrict__ v,
                              float* __restrict__ Q, float* __restrict__ V)
{
    int t = blockIdx.x * blockDim.x + threadIdx.x;
    if (t >= M4 * LGD) return;
    int d  = t & (LGD - 1);
    int bn = t >> 8;
    int n  = bn & (LGN - 1);
    int b  = bn >> 10;
    int h  = d >> 6, e = d & 63;
    long dst = (((long)b * LGH + h) * LGN + n) * LGHD + e;
    Q[dst] = tf32r(qk[t]);
    V[dst] = tf32r(v[t]);
}

// LayerNorm(512) + exact GELU
__global__ void lngelu_k(const float* __restrict__ h, const float* __restrict__ g,
                         const float* __restrict__ bb, float* __restrict__ o)
{
    long row = blockIdx.x;
    int tid = threadIdx.x;
    const float* p = h + row * 512;
    float x0 = p[tid], x1 = p[tid + 256];
    __shared__ float red[256];
    red[tid] = x0 + x1; __syncthreads();
    for (int s = 128; s > 0; s >>= 1) { if (tid < s) red[tid] += red[tid + s]; __syncthreads(); }
    float mean = red[0] * (1.0f / 512.0f);
    __syncthreads();
    red[tid] = x0 * x0 + x1 * x1; __syncthreads();
    for (int s = 128; s > 0; s >>= 1) { if (tid < s) red[tid] += red[tid + s]; __syncthreads(); }
    float var = red[0] * (1.0f / 512.0f) - mean * mean;
    float rr = rsqrtf(var + 1e-5f);
    float n0 = (x0 - mean) * rr * g[tid] + bb[tid];
    float n1 = (x1 - mean) * rr * g[tid + 256] + bb[tid + 256];
    o[row * 512 + tid]       = 0.5f * n0 * (1.0f + erff(n0 * 0.70710678118654752f));
    o[row * 512 + tid + 256] = 0.5f * n1 * (1.0f + erff(n1 * 0.70710678118654752f));
}

__global__ void z_k(const float* __restrict__ x, const float* __restrict__ w,
                    const float* __restrict__ b, float* __restrict__ z)
{
    long row = blockIdx.x;
    int tid = threadIdx.x;
    __shared__ float red[256];
    red[tid] = x[row * LGD + tid] * w[tid];
    __syncthreads();
    for (int s = 128; s > 0; s >>= 1) { if (tid < s) red[tid] += red[tid + s]; __syncthreads(); }
    if (tid == 0) z[row] = red[0] + b[0];
}

__global__ void lse_row_k(const float* __restrict__ sim, float* __restrict__ lser)
{
    long r = blockIdx.x;
    const float* p = sim + r * LGN;
    int tid = threadIdx.x;
    __shared__ float red[256];
    float m = -INFINITY;
    for (int j = tid; j < LGN; j += 256) m = fmaxf(m, p[j]);
    red[tid] = m; __syncthreads();
    for (int s = 128; s > 0; s >>= 1) { if (tid < s) red[tid] = fmaxf(red[tid], red[tid + s]); __syncthreads(); }
    m = red[0];
    __syncthreads();
    float sum = 0.0f;
    for (int j = tid; j < LGN; j += 256) sum += expf(p[j] - m);
    red[tid] = sum; __syncthreads();
    for (int s = 128; s > 0; s >>= 1) { if (tid < s) red[tid] += red[tid + s]; __syncthreads(); }
    if (tid == 0) lser[r] = m + logf(red[0]);
}

__global__ void lse_col_k(const float* __restrict__ sim, float* __restrict__ lsec)
{
    int cg = blockIdx.x & 31;
    int p  = blockIdx.x >> 5;
    int tid = threadIdx.x;
    int jc = (tid & 31);
    int j = cg * 32 + jc;
    int rg = tid >> 5;
    const float* base = sim + (long)p * LGN * LGN + j;
    float m = -INFINITY, s = 0.0f;
    for (int i = rg; i < LGN; i += 8) {
        float v = base[(long)i * LGN];
        if (v > m) { s = s * expf(m - v) + 1.0f; m = v; }
        else s += expf(v - m);
    }
    __shared__ float sm[8][33], ss[8][33];
    sm[rg][jc] = m; ss[rg][jc] = s;
    __syncthreads();
    if (tid < 32) {
        float M = sm[0][tid], S = ss[0][tid];
#pragma unroll
        for (int g = 1; g < 8; g++) {
            float m2 = sm[g][tid], s2 = ss[g][tid];
            if (m2 > M) { S = S * expf(M - m2) + s2; M = m2; }
            else S += s2 * expf(m2 - M);
        }
        lsec[p * LGN + cg * 32 + tid] = M + logf(S);
    }
}

__device__ __forceinline__ float lsig(float t) {
    return fminf(t, 0.0f) - log1pf(expf(-fabsf(t)));
}

__global__ void scores_k(const float* __restrict__ sim, const float* __restrict__ lser,
                         const float* __restrict__ lsec, const float* __restrict__ z,
                         float* __restrict__ out)
{
    long idx = (long)blockIdx.x * 256 + threadIdx.x;
    if (idx >= (long)NN2) return;
    int j = idx & (LGN - 1);
    long r = idx >> 10;
    int i = (int)(r & (LGN - 1));
    int p = (int)(r >> 10);
    float zq = z[(2 * p) * LGN + i];
    float zk = z[(2 * p + 1) * LGN + j];
    out[idx] = 2.0f * sim[idx] - lser[p * LGN + i] - lsec[p * LGN + j] + lsig(zq) + lsig(zk);
}

__global__ void argmax_row_k(const float* __restrict__ S, float* __restrict__ rmax,
                             int* __restrict__ m0)
{
    long i = blockIdx.x;
    const float* p = S + i * LGN;
    int tid = threadIdx.x;
    float bv = -INFINITY; int bi = 0;
    for (int j = tid; j < LGN; j += 256) {
        float v = p[j];
        if (v > bv) { bv = v; bi = j; }
    }
    __shared__ float sv[256]; __shared__ int si[256];
    sv[tid] = bv; si[tid] = bi; __syncthreads();
    for (int s = 128; s > 0; s >>= 1) {
        if (tid < s) {
            float v2 = sv[tid + s]; int i2 = si[tid + s];
            if (v2 > sv[tid] || (v2 == sv[tid] && i2 < si[tid])) { sv[tid] = v2; si[tid] = i2; }
        }
        __syncthreads();
    }
    if (tid == 0) { rmax[i] = sv[0]; m0[i] = si[0]; }
}

__global__ void argmax_col_k(const float* __restrict__ S, int* __restrict__ m1)
{
    int cg = blockIdx.x;
    int tid = threadIdx.x;
    int jc = tid & 31;
    int j = cg * 32 + jc;
    int rg = tid >> 5;
    float bv = -INFINITY; int bi = 0;
    for (int i = rg; i < LGN; i += 8) {
        float v = S[(long)i * LGN + j];
        if (v > bv || (v == bv && i < bi)) { bv = v; bi = i; }
    }
    __shared__ float sv[8][33]; __shared__ int si[8][33];
    sv[rg][jc] = bv; si[rg][jc] = bi;
    __syncthreads();
    if (tid < 32) {
        float V = sv[0][tid]; int I = si[0][tid];
#pragma unroll
        for (int g = 1; g < 8; g++) {
            float v2 = sv[g][tid]; int i2 = si[g][tid];
            if (v2 > V || (v2 == V && i2 < I)) { V = v2; I = i2; }
        }
        m1[cg * 32 + tid] = I;
    }
}

__global__ void filter_k(const int* __restrict__ m0, const int* __restrict__ m1,
                         const float* __restrict__ rmax, float* __restrict__ out)
{
    __shared__ float vals[LGN];
    __shared__ float rv[LGN];
    __shared__ int   ri[LGN];
    int n = threadIdx.x;
    float ms = expf(rmax[n]);
    bool mutual = (m1[m0[n]] == n);
    vals[n] = (mutual && ms > 0.1f) ? ms : 0.0f;
    __syncthreads();
    for (int k = 0; k < 50; k++) {
        rv[n] = vals[n]; ri[n] = n; __syncthreads();
        for (int s = 512; s > 0; s >>= 1) {
            if (n < s) {
                float v2 = rv[n + s]; int i2 = ri[n + s];
                if (v2 > rv[n] || (v2 == rv[n] && i2 < ri[n])) { rv[n] = v2; ri[n] = i2; }
            }
            __syncthreads();
        }
        if (n == 0) {
            int bi = ri[0]; float bv = rv[0];
            out[NN2 + k * 3 + 0] = 0.0f;
            out[NN2 + k * 3 + 1] = (float)bi;
            out[NN2 + k * 3 + 2] = (float)m0[bi];
            out[NN2 + 150 + k]   = bv;
            vals[bi] = -1.0f;
        }
        __syncthreads();
    }
}

// -------------------- host-side launchers ----------------------------------
#define GSMEM128 ((128 + 128) * GSTR * 2 * 4)   // 73728
#define GSMEM64  ((64 + 128) * GSTR * 2 * 4)    // 55296

static void tgemm(const float* A, const float* B, float* C,
                  int M, int N, int K, int ldC,
                  long sA, long sB, long sC, int batch,
                  const float* bias, const float* res, float alpha,
                  float* C2 = nullptr)
{
    if (N > 512) {
        dim3 grid(N / 128, M / 128, batch);
        tgemm_k<128><<<grid, 256, GSMEM128>>>(A, B, C, M, N, K, ldC, sA, sB, sC,
                                              bias, res, alpha, C2);
    } else {
        dim3 grid(N / 128, M / 64, batch);
        tgemm_k<64><<<grid, 128, GSMEM64>>>(A, B, C, M, N, K, ldC, sA, sB, sC,
                                            bias, res, alpha, C2);
    }
}

extern "C" void kernel_launch(void* const* d_in, const int* in_sizes, int n_in,
                              void* d_out, int out_size)
{
    (void)in_sizes; (void)n_in; (void)out_size;
    const float* kpts      = (const float*)d_in[0];
    const float* desc      = (const float*)d_in[1];
    const float* posenc_Wr = (const float*)d_in[2];
    const float* sWqkv_w   = (const float*)d_in[3];
    const float* sWqkv_b   = (const float*)d_in[4];
    const float* sOut_w    = (const float*)d_in[5];
    const float* sOut_b    = (const float*)d_in[6];
    const float* sF1_w     = (const float*)d_in[7];
    const float* sF1_b     = (const float*)d_in[8];
    const float* sLN_g     = (const float*)d_in[9];
    const float* sLN_b     = (const float*)d_in[10];
    const float* sF2_w     = (const float*)d_in[11];
    const float* sF2_b     = (const float*)d_in[12];
    const float* cQK_w     = (const float*)d_in[13];
    const float* cQK_b     = (const float*)d_in[14];
    const float* cV_w      = (const float*)d_in[15];
    const float* cV_b      = (const float*)d_in[16];
    const float* cOut_w    = (const float*)d_in[17];
    const float* cOut_b    = (const float*)d_in[18];
    const float* cF1_w     = (const float*)d_in[19];
    const float* cF1_b     = (const float*)d_in[20];
    const float* cLN_g     = (const float*)d_in[21];
    const float* cLN_b     = (const float*)d_in[22];
    const float* cF2_w     = (const float*)d_in[23];
    const float* cF2_b     = (const float*)d_in[24];
    const float* fp_w      = (const float*)d_in[25];
    const float* fp_b      = (const float*)d_in[26];
    const float* match_w   = (const float*)d_in[27];
    const float* match_b   = (const float*)d_in[28];
    float* out = (float*)d_out;

    float *x, *qkv, *vb, *Q, *K, *V, *ctx, *cat, *h1, *h2, *md, *sim, *z;
    float *lser, *lsec, *rmax;
    int *m0, *m1;
    cudaGetSymbolAddress((void**)&x,    g_x);
    cudaGetSymbolAddress((void**)&qkv,  g_qkv);
    cudaGetSymbolAddress((void**)&vb,   g_vbuf);
    cudaGetSymbolAddress((void**)&Q,    g_Q);
    cudaGetSymbolAddress((void**)&K,    g_K);
    cudaGetSymbolAddress((void**)&V,    g_V);
    cudaGetSymbolAddress((void**)&ctx,  g_ctx);
    cudaGetSymbolAddress((void**)&cat,  g_cat);
    cudaGetSymbolAddress((void**)&h1,   g_h1);
    cudaGetSymbolAddress((void**)&h2,   g_h2);
    cudaGetSymbolAddress((void**)&md,   g_md);
    cudaGetSymbolAddress((void**)&sim,  g_sim);
    cudaGetSymbolAddress((void**)&z,    g_z);
    cudaGetSymbolAddress((void**)&lser, g_lser);
    cudaGetSymbolAddress((void**)&lsec, g_lsec);
    cudaGetSymbolAddress((void**)&rmax, g_rmax);
    cudaGetSymbolAddress((void**)&m0,   g_m0);
    cudaGetSymbolAddress((void**)&m1,   g_m1);

    cudaFuncSetAttribute(flash_k, cudaFuncAttributeMaxDynamicSharedMemorySize, FSMEM);
    cudaFuncSetAttribute(tgemm_k<128>, cudaFuncAttributeMaxDynamicSharedMemorySize, GSMEM128);
    cudaFuncSetAttribute(tgemm_k<64>,  cudaFuncAttributeMaxDynamicSharedMemorySize, GSMEM64);

    const long sSS = (long)LGN * LGN;

    copy2_k<<<(M4 * LGD + 255) / 256, 256>>>(desc, x, cat);

    for (int i = 0; i < LGL; i++) {
        // ---------------- self attention ----------------
        tgemm(x, sWqkv_w + (long)i * 3 * LGD * LGD, qkv, M4, 3 * LGD, LGD, 3 * LGD,
              0, 0, 0, 1, sWqkv_b + (long)i * 3 * LGD, nullptr, 1.0f);
        rope_split_k<<<(LGB * LGN * 128 + 255) / 256, 256>>>(qkv, kpts, posenc_Wr, Q, K, V);
        flash_k<<<dim3(16, BH), 128, FSMEM>>>(Q, K, V, ctx, 0);
        tgemm(ctx, sOut_w + (long)i * LGD * LGD, cat + LGD, M4, LGD, LGD, 2 * LGD,
              0, 0, 0, 1, sOut_b + (long)i * LGD, nullptr, 1.0f);
        tgemm(cat, sF1_w + (long)i * 4 * LGD * LGD, h1, M4, 2 * LGD, 2 * LGD, 2 * LGD,
              0, 0, 0, 1, sF1_b + (long)i * 2 * LGD, nullptr, 1.0f);
        lngelu_k<<<M4, 256>>>(h1, sLN_g + (long)i * 2 * LGD, sLN_b + (long)i * 2 * LGD, h2);
        // x += F2(h2); also write new x into cat-left for the cross FFN
        tgemm(h2, sF2_w + (long)i * 2 * LGD * LGD, x, M4, LGD, 2 * LGD, LGD,
              0, 0, 0, 1, sF2_b + (long)i * LGD, x, 1.0f, cat);

        // ---------------- cross attention ----------------
        tgemm(x, cQK_w + (long)i * LGD * LGD, qkv, M4, LGD, LGD, LGD,
              0, 0, 0, 1, cQK_b + (long)i * LGD, nullptr, 1.0f);
        tgemm(x, cV_w + (long)i * LGD * LGD, vb, M4, LGD, LGD, LGD,
              0, 0, 0, 1, cV_b + (long)i * LGD, nullptr, 1.0f);
        split_heads_k<<<(M4 * LGD + 255) / 256, 256>>>(qkv, vb, Q, V);
        flash_k<<<dim3(16, BH), 128, FSMEM>>>(Q, Q, V, ctx, 4);
        tgemm(ctx, cOut_w + (long)i * LGD * LGD, cat + LGD, M4, LGD, LGD, 2 * LGD,
              0, 0, 0, 1, cOut_b + (long)i * LGD, nullptr, 1.0f);
        tgemm(cat, cF1_w + (long)i * 4 * LGD * LGD, h1, M4, 2 * LGD, 2 * LGD, 2 * LGD,
              0, 0, 0, 1, cF1_b + (long)i * 2 * LGD, nullptr, 1.0f);
        lngelu_k<<<M4, 256>>>(h1, cLN_g + (long)i * 2 * LGD, cLN_b + (long)i * 2 * LGD, h2);
        tgemm(h2, cF2_w + (long)i * 2 * LGD * LGD, x, M4, LGD, 2 * LGD, LGD,
              0, 0, 0, 1, cF2_b + (long)i * LGD, x, 1.0f, cat);
    }

    // ---------------- matching head ----------------
    tgemm(x, fp_w, md, M4, LGD, LGD, LGD, 0, 0, 0, 1, fp_b, nullptr, 0.25f);
    tgemm(md, md + (long)LGN * LGD, sim, LGN, LGN, LGD, LGN,
          (long)2 * LGN * LGD, (long)2 * LGN * LGD, sSS, 2, nullptr, nullptr, 1.0f);
    z_k<<<M4, 256>>>(x, match_w, match_b, z);
    lse_row_k<<<2 * LGN, 256>>>(sim, lser);
    lse_col_k<<<64, 256>>>(sim, lsec);
    scores_k<<<(NN2 + 255) / 256, 256>>>(sim, lser, lsec, z, out);

    // ---------------- filter (batch 0 only) ----------------
    argmax_row_k<<<LGN, 256>>>(out, rmax, m0);
    argmax_col_k<<<32, 256>>>(out, m1);
    filter_k<<<1, 1024>>>(m0, m1, rmax, out);
}

// round 7
// speedup vs baseline: 2.7196x; 1.0089x over previous
#include <cuda_runtime.h>
#include <cuda_bf16.h>
#include <math.h>
#include <stdint.h>

// ---------------------------------------------------------------------------
// LightGlue forward. L=9, D=256, H=4, HD=64, N=1024, B=4 (2 pairs).
// GEMM operands pre-rounded to tf32 where bit-identical to round-at-read;
// residual stream x kept full fp32 (discrete outputs are tie-sensitive).
// ---------------------------------------------------------------------------

#define LGB   4
#define LGN   1024
#define LGD   256
#define LGH   4
#define LGHD  64
#define LGL   9
#define M4    (LGB*LGN)
#define BH    (LGB*LGH)
#define NN2   (2*1024*1024)

// -------------------- scratch (device globals; no allocation) --------------
__device__ float g_x   [M4*LGD];
__device__ float g_qkv [M4*3*LGD];
__device__ float g_vbuf[M4*LGD];
__device__ float g_Q   [BH*LGN*LGHD];
__device__ float g_K   [BH*LGN*LGHD];
__device__ float g_V   [BH*LGN*LGHD];
__device__ float g_ctx [M4*LGD];
__device__ float g_cat [M4*2*LGD];
__device__ float g_h1  [M4*2*LGD];
__device__ float g_h2  [M4*2*LGD];
__device__ float g_md  [M4*LGD];
__device__ float g_sim [NN2];
__device__ float g_z   [M4];
__device__ float g_lser[2*LGN];
__device__ float g_lsec[2*LGN];
__device__ int   g_m0  [LGN];
__device__ int   g_m1  [LGN];
__device__ float g_rmax[LGN];
__device__ float g_wr  [11272192];        // tf32-rounded weights (45 MB)

// -------------------- tf32 helpers -----------------------------------------
__device__ __forceinline__ uint32_t tf32u(float x) {
    uint32_t u;
    asm("cvt.rna.tf32.f32 %0, %1;" : "=r"(u) : "f"(x));
    return u;
}
__device__ __forceinline__ float tf32r(float x) { return __uint_as_float(tf32u(x)); }

__device__ __forceinline__ void mma_tf32(float (&d)[4], const uint32_t (&a)[4],
                                         const uint32_t (&b)[2]) {
    asm volatile(
        "mma.sync.aligned.m16n8k8.row.col.f32.tf32.tf32.f32 "
        "{%0,%1,%2,%3}, {%4,%5,%6,%7}, {%8,%9}, {%0,%1,%2,%3};"
        : "+f"(d[0]), "+f"(d[1]), "+f"(d[2]), "+f"(d[3])
        : "r"(a[0]), "r"(a[1]), "r"(a[2]), "r"(a[3]), "r"(b[0]), "r"(b[1]));
}

__device__ __forceinline__ void cp16(void* dst, const void* src) {
    uint32_t d = (uint32_t)__cvta_generic_to_shared(dst);
    asm volatile("cp.async.cg.shared.global [%0], [%1], 16;" :: "r"(d), "l"(src));
}
__device__ __forceinline__ void cp_commit() { asm volatile("cp.async.commit_group;"); }
template<int n> __device__ __forceinline__ void cp_wait() {
    asm volatile("cp.async.wait_group %0;" :: "n"(n));
}

// -------------------- weight pre-rounding -----------------------------------
__global__ void roundw4_k(const float4* __restrict__ src, float4* __restrict__ dst,
                          int n4) {
    int i = blockIdx.x * blockDim.x + threadIdx.x;
    if (i >= n4) return;
    float4 v = src[i];
    v.x = tf32r(v.x); v.y = tf32r(v.y); v.z = tf32r(v.z); v.w = tf32r(v.w);
    dst[i] = v;
}

// -------------------- dense tf32 GEMM (NT only) -----------------------------
// B MUST be pre-rounded. A pre-rounded iff RNDA==0 (else cvt at fragment read).
// rnd: bit0 = round C output to tf32; bit1 = round only the C2 copy.
#define GSTR 36

template<int BM, int RNDA>
__global__ void __launch_bounds__(BM * 2, (BM == 128) ? 2 : 3) tgemm_k(
    const float* __restrict__ A, const float* __restrict__ B, float* C,
    int M, int N, int K, int ldC,
    long sA, long sB, long sC,
    const float* __restrict__ bias, const float* res, float alpha,
    float* C2, int rnd)
{
    constexpr int THREADS = BM * 2;
    constexpr int WCNT = (BM == 128) ? 4 : 2;
    constexpr int TM   = BM / 32;
    constexpr int TN   = 16 / WCNT;
    constexpr int ABUF = BM * GSTR;
    constexpr int BBUF = 128 * GSTR;

    extern __shared__ float sm[];
    float* As = sm;
    float* Bs = sm + 2 * ABUF;

    int bh = blockIdx.z;
    A += (long)bh * sA;
    B += (long)bh * sB;
    C += (long)bh * sC;
    if (res) res += (long)bh * sC;

    const int tid  = threadIdx.x;
    const int warp = tid >> 5, lane = tid & 31;
    const int wm = warp / WCNT, wn = warp % WCNT;
    const int gid = lane >> 2, tig = lane & 3;
    const int row0 = blockIdx.y * BM;
    const int col0 = blockIdx.x * 128;

    float acc[TM][TN][4];
#pragma unroll
    for (int i = 0; i < TM; i++)
#pragma unroll
        for (int j = 0; j < TN; j++)
#pragma unroll
            for (int q = 0; q < 4; q++) acc[i][j][q] = 0.0f;

#define LOADT(s, k0) do {                                                      \
    _Pragma("unroll")                                                          \
    for (int l = 0; l < BM * 8 / THREADS; l++) {                               \
        int v = tid + THREADS * l; int r = v >> 3; int off = (v & 7) * 4;      \
        cp16(&As[(s) * ABUF + r * GSTR + off],                                 \
             &A[(long)(row0 + r) * K + (k0) + off]);                           \
    }                                                                          \
    _Pragma("unroll")                                                          \
    for (int l = 0; l < 1024 / THREADS; l++) {                                 \
        int v = tid + THREADS * l; int r = v >> 3; int off = (v & 7) * 4;      \
        cp16(&Bs[(s) * BBUF + r * GSTR + off],                                 \
             &B[(long)(col0 + r) * K + (k0) + off]);                           \
    }                                                                          \
    cp_commit(); } while (0)

    const int NK = K >> 5;
    LOADT(0, 0);

    for (int it = 0; it < NK; it++) {
        int cur = it & 1;
        cp_wait<0>();
        __syncthreads();
        if (it + 1 < NK) LOADT(cur ^ 1, (it + 1) << 5);
        const float* Ab = As + cur * ABUF;
        const float* Bb = Bs + cur * BBUF;

#pragma unroll
        for (int ks = 0; ks < 32; ks += 8) {
            uint32_t ar[TM][4];
#pragma unroll
            for (int tm = 0; tm < TM; tm++) {
                int mr = (wm * (TM * 16) + tm * 16 + gid) * GSTR;
                if (RNDA) {
                    ar[tm][0] = tf32u(Ab[mr + ks + tig]);
                    ar[tm][1] = tf32u(Ab[mr + 8 * GSTR + ks + tig]);
                    ar[tm][2] = tf32u(Ab[mr + ks + tig + 4]);
                    ar[tm][3] = tf32u(Ab[mr + 8 * GSTR + ks + tig + 4]);
                } else {
                    ar[tm][0] = __float_as_uint(Ab[mr + ks + tig]);
                    ar[tm][1] = __float_as_uint(Ab[mr + 8 * GSTR + ks + tig]);
                    ar[tm][2] = __float_as_uint(Ab[mr + ks + tig + 4]);
                    ar[tm][3] = __float_as_uint(Ab[mr + 8 * GSTR + ks + tig + 4]);
                }
            }
            uint32_t br[TN][2];
#pragma unroll
            for (int tn = 0; tn < TN; tn++) {
                int nr = (wn * (TN * 8) + tn * 8 + gid) * GSTR;
                br[tn][0] = __float_as_uint(Bb[nr + ks + tig]);
                br[tn][1] = __float_as_uint(Bb[nr + ks + tig + 4]);
            }
#pragma unroll
            for (int tm = 0; tm < TM; tm++)
#pragma unroll
                for (int tn = 0; tn < TN; tn++)
                    mma_tf32(acc[tm][tn], ar[tm], br[tn]);
        }
        __syncthreads();
    }
#undef LOADT

#pragma unroll
    for (int tm = 0; tm < TM; tm++) {
        int r0 = row0 + wm * (TM * 16) + tm * 16 + gid;
#pragma unroll
        for (int tn = 0; tn < TN; tn++) {
            int c = col0 + wn * (TN * 8) + tn * 8 + tig * 2;
            float b0 = bias ? bias[c] : 0.0f;
            float b1 = bias ? bias[c + 1] : 0.0f;
#pragma unroll
            for (int half = 0; half < 2; half++) {
                int r = r0 + half * 8;
                float v0 = (acc[tm][tn][half * 2 + 0] + b0) * alpha;
                float v1 = (acc[tm][tn][half * 2 + 1] + b1) * alpha;
                if (res) {
                    v0 += res[(long)r * ldC + c];
                    v1 += res[(long)r * ldC + c + 1];
                }
                float u0 = v0, u1 = v1;
                if (rnd & 1) { v0 = tf32r(v0); v1 = tf32r(v1); }
                *reinterpret_cast<float2*>(&C[(long)r * ldC + c]) = make_float2(v0, v1);
                if (C2) {
                    if (rnd & 2) { u0 = tf32r(u0); u1 = tf32r(u1); }
                    else         { u0 = v0; u1 = v1; }
                    *reinterpret_cast<float2*>(&C2[(long)r * 512 + c]) = make_float2(u0, u1);
                }
            }
        }
    }
}

// -------------------- fused flash attention ---------------------------------
// Q,K,V pre-rounded to tf32. ctx out rounded (only consumer: out-proj GEMM).
#define FKS 68
#define FVS 72
#define FKBUF (64*FKS)
#define FVBUF (64*FVS)
#define FSMEM ((2*FKBUF + 2*FVBUF + 64*FKS) * 4)   // 89088 bytes

__global__ void __launch_bounds__(128, 2) flash_k(
    const float* __restrict__ Qg, const float* __restrict__ Kg,
    const float* __restrict__ Vg, float* __restrict__ ctx, int xorB)
{
    extern __shared__ float smf[];
    float* Ksm = smf;
    float* Vsm = smf + 2 * FKBUF;
    float* Ps  = smf + 2 * FKBUF + 2 * FVBUF;

    const int bh = blockIdx.y, qt = blockIdx.x;
    const float* Qh = Qg + (long)bh * (LGN * LGHD);
    const float* Kh = Kg + (long)(bh ^ xorB) * (LGN * LGHD);
    const float* Vh = Vg + (long)(bh ^ xorB) * (LGN * LGHD);

    const int tid = threadIdx.x, warp = tid >> 5, lane = tid & 31;
    const int gid = lane >> 2, tig = lane & 3;
    const int wrow = warp * 16;

#pragma unroll
    for (int l = 0; l < 8; l++) {
        int v = tid + 128 * l;
        int r = v >> 4, c = (v & 15) * 4;
        float4 q = *(const float4*)&Qh[(long)(qt * 64 + r) * LGHD + c];
        Ps[r * FKS + c]     = 0.125f * q.x; Ps[r * FKS + c + 1] = 0.125f * q.y;
        Ps[r * FKS + c + 2] = 0.125f * q.z; Ps[r * FKS + c + 3] = 0.125f * q.w;
    }
    __syncthreads();
    uint32_t qa[8][4];
#pragma unroll
    for (int ks = 0; ks < 8; ks++) {
        int k = ks * 8;
        qa[ks][0] = __float_as_uint(Ps[(wrow + gid) * FKS + k + tig]);
        qa[ks][1] = __float_as_uint(Ps[(wrow + gid + 8) * FKS + k + tig]);
        qa[ks][2] = __float_as_uint(Ps[(wrow + gid) * FKS + k + tig + 4]);
        qa[ks][3] = __float_as_uint(Ps[(wrow + gid + 8) * FKS + k + tig + 4]);
    }

    float oacc[8][4];
#pragma unroll
    for (int nt = 0; nt < 8; nt++)
#pragma unroll
        for (int j = 0; j < 4; j++) oacc[nt][j] = 0.0f;
    float mrow0 = -INFINITY, mrow1 = -INFINITY, lrow0 = 0.0f, lrow1 = 0.0f;

#define LOADKV(s, kt) do {                                                     \
    _Pragma("unroll")                                                          \
    for (int l = 0; l < 8; l++) {                                              \
        int v = tid + 128 * l; int r = v >> 4; int c = (v & 15) * 4;           \
        cp16(&Ksm[(s) * FKBUF + r * FKS + c],                                  \
             &Kh[(long)((kt) * 64 + r) * LGHD + c]);                           \
    }                                                                          \
    _Pragma("unroll")                                                          \
    for (int l = 0; l < 8; l++) {                                              \
        int v = tid + 128 * l; int r = v >> 4; int c = (v & 15) * 4;           \
        cp16(&Vsm[(s) * FVBUF + r * FVS + c],                                  \
             &Vh[(long)((kt) * 64 + r) * LGHD + c]);                           \
    }                                                                          \
    cp_commit(); } while (0)

    LOADKV(0, 0);

    for (int kt = 0; kt < 16; kt++) {
        int cur = kt & 1;
        cp_wait<0>();
        __syncthreads();
        if (kt + 1 < 16) LOADKV(cur ^ 1, kt + 1);
        const float* K_ = Ksm + cur * FKBUF;
        const float* V_ = Vsm + cur * FVBUF;

        float sacc[8][4];
#pragma unroll
        for (int nt = 0; nt < 8; nt++)
#pragma unroll
            for (int j = 0; j < 4; j++) sacc[nt][j] = 0.0f;
#pragma unroll
        for (int ks = 0; ks < 8; ks++) {
            int k = ks * 8;
#pragma unroll
            for (int nt = 0; nt < 8; nt++) {
                uint32_t b[2];
                b[0] = __float_as_uint(K_[(nt * 8 + gid) * FKS + k + tig]);
                b[1] = __float_as_uint(K_[(nt * 8 + gid) * FKS + k + tig + 4]);
                mma_tf32(sacc[nt], qa[ks], b);
            }
        }

        float t0 = -INFINITY, t1 = -INFINITY;
#pragma unroll
        for (int nt = 0; nt < 8; nt++) {
            t0 = fmaxf(t0, fmaxf(sacc[nt][0], sacc[nt][1]));
            t1 = fmaxf(t1, fmaxf(sacc[nt][2], sacc[nt][3]));
        }
        t0 = fmaxf(t0, __shfl_xor_sync(0xffffffffu, t0, 1));
        t0 = fmaxf(t0, __shfl_xor_sync(0xffffffffu, t0, 2));
        t1 = fmaxf(t1, __shfl_xor_sync(0xffffffffu, t1, 1));
        t1 = fmaxf(t1, __shfl_xor_sync(0xffffffffu, t1, 2));
        float mn0 = fmaxf(mrow0, t0), mn1 = fmaxf(mrow1, t1);
        float al0 = __expf(mrow0 - mn0), al1 = __expf(mrow1 - mn1);
        float s0 = 0.0f, s1 = 0.0f;
#pragma unroll
        for (int nt = 0; nt < 8; nt++) {
            sacc[nt][0] = __expf(sacc[nt][0] - mn0);
            sacc[nt][1] = __expf(sacc[nt][1] - mn0);
            sacc[nt][2] = __expf(sacc[nt][2] - mn1);
            sacc[nt][3] = __expf(sacc[nt][3] - mn1);
            s0 += sacc[nt][0] + sacc[nt][1];
            s1 += sacc[nt][2] + sacc[nt][3];
        }
        s0 += __shfl_xor_sync(0xffffffffu, s0, 1);
        s0 += __shfl_xor_sync(0xffffffffu, s0, 2);
        s1 += __shfl_xor_sync(0xffffffffu, s1, 1);
        s1 += __shfl_xor_sync(0xffffffffu, s1, 2);
        lrow0 = lrow0 * al0 + s0;
        lrow1 = lrow1 * al1 + s1;
        mrow0 = mn0; mrow1 = mn1;

#pragma unroll
        for (int nt = 0; nt < 8; nt++) {
            oacc[nt][0] *= al0; oacc[nt][1] *= al0;
            oacc[nt][2] *= al1; oacc[nt][3] *= al1;
            int c = nt * 8 + 2 * tig;
            Ps[(wrow + gid) * FKS + c]         = __uint_as_float(tf32u(sacc[nt][0]));
            Ps[(wrow + gid) * FKS + c + 1]     = __uint_as_float(tf32u(sacc[nt][1]));
            Ps[(wrow + gid + 8) * FKS + c]     = __uint_as_float(tf32u(sacc[nt][2]));
            Ps[(wrow + gid + 8) * FKS + c + 1] = __uint_as_float(tf32u(sacc[nt][3]));
        }
        __syncwarp();

#pragma unroll
        for (int ks = 0; ks < 8; ks++) {
            int k = ks * 8;
            uint32_t pa[4];
            pa[0] = __float_as_uint(Ps[(wrow + gid) * FKS + k + tig]);
            pa[1] = __float_as_uint(Ps[(wrow + gid + 8) * FKS + k + tig]);
            pa[2] = __float_as_uint(Ps[(wrow + gid) * FKS + k + tig + 4]);
            pa[3] = __float_as_uint(Ps[(wrow + gid + 8) * FKS + k + tig + 4]);
#pragma unroll
            for (int nt = 0; nt < 8; nt++) {
                uint32_t b[2];
                b[0] = __float_as_uint(V_[(k + tig) * FVS + nt * 8 + gid]);
                b[1] = __float_as_uint(V_[(k + tig + 4) * FVS + nt * 8 + gid]);
                mma_tf32(oacc[nt], pa, b);
            }
        }
        __syncthreads();
    }
#undef LOADKV

    // ctx rounded at store: bit-identical to rounding at out-proj read.
    float inv0 = 1.0f / lrow0, inv1 = 1.0f / lrow1;
    int b_ = bh >> 2, h = bh & 3;
    int n0 = qt * 64 + wrow + gid;
    long base0 = ((long)(b_ * LGN + n0)) * LGD + h * 64;
    long base1 = base0 + 8L * LGD;
#pragma unroll
    for (int nt = 0; nt < 8; nt++) {
        int c = nt * 8 + 2 * tig;
        *(float2*)&ctx[base0 + c] =
            make_float2(tf32r(oacc[nt][0] * inv0), tf32r(oacc[nt][1] * inv0));
        *(float2*)&ctx[base1 + c] =
            make_float2(tf32r(oacc[nt][2] * inv1), tf32r(oacc[nt][3] * inv1));
    }
}

// -------------------- elementwise / reduction kernels ----------------------
// x keeps full fp32; cat copy rounded (cat only feeds the F1 GEMM).
__global__ void copy2_k(const float* __restrict__ src, float* __restrict__ x,
                        float* __restrict__ cat) {
    int i = blockIdx.x * blockDim.x + threadIdx.x;
    if (i >= M4 * LGD) return;
    float v = src[i];
    x[i] = v;
    int r = i >> 8, c = i & 255;
    cat[(long)r * 512 + c] = tf32r(v);
}

__global__ void rope_split_k(const float* __restrict__ qkv,
                             const float* __restrict__ kpts,
                             const float* __restrict__ Wr,
                             float* __restrict__ Q, float* __restrict__ Kh,
                             float* __restrict__ V)
{
    int t = blockIdx.x * blockDim.x + threadIdx.x;
    if (t >= LGB * LGN * 128) return;
    int p  = t & 127;
    int bn = t >> 7;
    int n  = bn & (LGN - 1);
    int b  = bn >> 10;
    int d0 = 2 * p;
    int f  = p & 31;
    float kx = kpts[bn * 2 + 0], ky = kpts[bn * 2 + 1];
    float pr = kx * Wr[2 * f] + ky * Wr[2 * f + 1];
    float c = cosf(pr), s = sinf(pr);
    const float* q = qkv + (long)bn * 768;
    float q0 = q[3 * d0 + 0], q1 = q[3 * d0 + 3];
    float k0 = q[3 * d0 + 1], k1 = q[3 * d0 + 4];
    float v0 = q[3 * d0 + 2], v1 = q[3 * d0 + 5];
    int h = d0 >> 6, e0 = d0 & 63;
    long base = (((long)b * LGH + h) * LGN + n) * LGHD + e0;
    Q[base]      = tf32r(c * q0 - s * q1);
    Q[base + 1]  = tf32r(c * q1 + s * q0);
    Kh[base]     = tf32r(c * k0 - s * k1);
    Kh[base + 1] = tf32r(c * k1 + s * k0);
    V[base]      = tf32r(v0);
    V[base + 1]  = tf32r(v1);
}

__global__ void split_heads_k(const float* __restrict__ qk,
                              const float* __restrict__ v,
                              float* __restrict__ Q, float* __restrict__ V)
{
    int t = blockIdx.x * blockDim.x + threadIdx.x;
    if (t >= M4 * LGD) return;
    int d  = t & (LGD - 1);
    int bn = t >> 8;
    int n  = bn & (LGN - 1);
    int b  = bn >> 10;
    int h  = d >> 6, e = d & 63;
    long dst = (((long)b * LGH + h) * LGN + n) * LGHD + e;
    Q[dst] = tf32r(qk[t]);
    V[dst] = tf32r(v[t]);
}

// LayerNorm(512) + exact GELU; output rounded (only consumer: F2 GEMM).
__global__ void lngelu_k(const float* __restrict__ h, const float* __restrict__ g,
                         const float* __restrict__ bb, float* __restrict__ o)
{
    long row = blockIdx.x;
    int tid = threadIdx.x;
    const float* p = h + row * 512;
    float x0 = p[tid], x1 = p[tid + 256];
    __shared__ float red[256];
    red[tid] = x0 + x1; __syncthreads();
    for (int s = 128; s > 0; s >>= 1) { if (tid < s) red[tid] += red[tid + s]; __syncthreads(); }
    float mean = red[0] * (1.0f / 512.0f);
    __syncthreads();
    red[tid] = x0 * x0 + x1 * x1; __syncthreads();
    for (int s = 128; s > 0; s >>= 1) { if (tid < s) red[tid] += red[tid + s]; __syncthreads(); }
    float var = red[0] * (1.0f / 512.0f) - mean * mean;
    float rr = rsqrtf(var + 1e-5f);
    float n0 = (x0 - mean) * rr * g[tid] + bb[tid];
    float n1 = (x1 - mean) * rr * g[tid + 256] + bb[tid + 256];
    o[row * 512 + tid]       = tf32r(0.5f * n0 * (1.0f + erff(n0 * 0.70710678118654752f)));
    o[row * 512 + tid + 256] = tf32r(0.5f * n1 * (1.0f + erff(n1 * 0.70710678118654752f)));
}

__global__ void z_k(const float* __restrict__ x, const float* __restrict__ w,
                    const float* __restrict__ b, float* __restrict__ z)
{
    long row = blockIdx.x;
    int tid = threadIdx.x;
    __shared__ float red[256];
    red[tid] = x[row * LGD + tid] * w[tid];
    __syncthreads();
    for (int s = 128; s > 0; s >>= 1) { if (tid < s) red[tid] += red[tid + s]; __syncthreads(); }
    if (tid == 0) z[row] = red[0] + b[0];
}

__global__ void lse_row_k(const float* __restrict__ sim, float* __restrict__ lser)
{
    long r = blockIdx.x;
    const float* p = sim + r * LGN;
    int tid = threadIdx.x;
    __shared__ float red[256];
    float m = -INFINITY;
    for (int j = tid; j < LGN; j += 256) m = fmaxf(m, p[j]);
    red[tid] = m; __syncthreads();
    for (int s = 128; s > 0; s >>= 1) { if (tid < s) red[tid] = fmaxf(red[tid], red[tid + s]); __syncthreads(); }
    m = red[0];
    __syncthreads();
    float sum = 0.0f;
    for (int j = tid; j < LGN; j += 256) sum += expf(p[j] - m);
    red[tid] = sum; __syncthreads();
    for (int s = 128; s > 0; s >>= 1) { if (tid < s) red[tid] += red[tid + s]; __syncthreads(); }
    if (tid == 0) lser[r] = m + logf(red[0]);
}

__global__ void lse_col_k(const float* __restrict__ sim, float* __restrict__ lsec)
{
    int cg = blockIdx.x & 31;
    int p  = blockIdx.x >> 5;
    int tid = threadIdx.x;
    int jc = (tid & 31);
    int j = cg * 32 + jc;
    int rg = tid >> 5;
    const float* base = sim + (long)p * LGN * LGN + j;
    float m = -INFINITY, s = 0.0f;
    for (int i = rg; i < LGN; i += 8) {
        float v = base[(long)i * LGN];
        if (v > m) { s = s * expf(m - v) + 1.0f; m = v; }
        else s += expf(v - m);
    }
    __shared__ float sm[8][33], ss[8][33];
    sm[rg][jc] = m; ss[rg][jc] = s;
    __syncthreads();
    if (tid < 32) {
        float M = sm[0][tid], S = ss[0][tid];
#pragma unroll
        for (int g = 1; g < 8; g++) {
            float m2 = sm[g][tid], s2 = ss[g][tid];
            if (m2 > M) { S = S * expf(M - m2) + s2; M = m2; }
            else S += s2 * expf(m2 - M);
        }
        lsec[p * LGN + cg * 32 + tid] = M + logf(S);
    }
}

__device__ __forceinline__ float lsig(float t) {
    return fminf(t, 0.0f) - log1pf(expf(-fabsf(t)));
}

__global__ void scores_k(const float* __restrict__ sim, const float* __restrict__ lser,
                         const float* __restrict__ lsec, const float* __restrict__ z,
                         float* __restrict__ out)
{
    long idx = (long)blockIdx.x * 256 + threadIdx.x;
    if (idx >= (long)NN2) return;
    int j = idx & (LGN - 1);
    long r = idx >> 10;
    int i = (int)(r & (LGN - 1));
    int p = (int)(r >> 10);
    float zq = z[(2 * p) * LGN + i];
    float zk = z[(2 * p + 1) * LGN + j];
    out[idx] = 2.0f * sim[idx] - lser[p * LGN + i] - lsec[p * LGN + j] + lsig(zq) + lsig(zk);
}

__global__ void argmax_row_k(const float* __restrict__ S, float* __restrict__ rmax,
                             int* __restrict__ m0)
{
    long i = blockIdx.x;
    const float* p = S + i * LGN;
    int tid = threadIdx.x;
    float bv = -INFINITY; int bi = 0;
    for (int j = tid; j < LGN; j += 256) {
        float v = p[j];
        if (v > bv) { bv = v; bi = j; }
    }
    __shared__ float sv[256]; __shared__ int si[256];
    sv[tid] = bv; si[tid] = bi; __syncthreads();
    for (int s = 128; s > 0; s >>= 1) {
        if (tid < s) {
            float v2 = sv[tid + s]; int i2 = si[tid + s];
            if (v2 > sv[tid] || (v2 == sv[tid] && i2 < si[tid])) { sv[tid] = v2; si[tid] = i2; }
        }
        __syncthreads();
    }
    if (tid == 0) { rmax[i] = sv[0]; m0[i] = si[0]; }
}

__global__ void argmax_col_k(const float* __restrict__ S, int* __restrict__ m1)
{
    int cg = blockIdx.x;
    int tid = threadIdx.x;
    int jc = tid & 31;
    int j = cg * 32 + jc;
    int rg = tid >> 5;
    float bv = -INFINITY; int bi = 0;
    for (int i = rg; i < LGN; i += 8) {
        float v = S[(long)i * LGN + j];
        if (v > bv || (v == bv && i < bi)) { bv = v; bi = i; }
    }
    __shared__ float sv[8][33]; __shared__ int si[8][33];
    sv[rg][jc] = bv; si[rg][jc] = bi;
    __syncthreads();
    if (tid < 32) {
        float V = sv[0][tid]; int I = si[0][tid];
#pragma unroll
        for (int g = 1; g < 8; g++) {
            float v2 = sv[g][tid]; int i2 = si[g][tid];
            if (v2 > V || (v2 == V && i2 < I)) { V = v2; I = i2; }
        }
        m1[cg * 32 + tid] = I;
    }
}

__global__ void filter_k(const int* __restrict__ m0, const int* __restrict__ m1,
                         const float* __restrict__ rmax, float* __restrict__ out)
{
    __shared__ float vals[LGN];
    __shared__ float rv[LGN];
    __shared__ int   ri[LGN];
    int n = threadIdx.x;
    float ms = expf(rmax[n]);
    bool mutual = (m1[m0[n]] == n);
    vals[n] = (mutual && ms > 0.1f) ? ms : 0.0f;
    __syncthreads();
    for (int k = 0; k < 50; k++) {
        rv[n] = vals[n]; ri[n] = n; __syncthreads();
        for (int s = 512; s > 0; s >>= 1) {
            if (n < s) {
                float v2 = rv[n + s]; int i2 = ri[n + s];
                if (v2 > rv[n] || (v2 == rv[n] && i2 < ri[n])) { rv[n] = v2; ri[n] = i2; }
            }
            __syncthreads();
        }
        if (n == 0) {
            int bi = ri[0]; float bv = rv[0];
            out[NN2 + k * 3 + 0] = 0.0f;
            out[NN2 + k * 3 + 1] = (float)bi;
            out[NN2 + k * 3 + 2] = (float)m0[bi];
            out[NN2 + 150 + k]   = bv;
            vals[bi] = -1.0f;
        }
        __syncthreads();
    }
}

// -------------------- host-side launchers ----------------------------------
#define GSMEM128 ((128 + 128) * GSTR * 2 * 4)
#define GSMEM64  ((64 + 128) * GSTR * 2 * 4)

static void tgemm(const float* A, const float* B, float* C,
                  int M, int N, int K, int ldC,
                  long sA, long sB, long sC, int batch,
                  const float* bias, const float* res, float alpha,
                  float* C2, int rnd, int rndA)
{
    if (N > 512) {
        dim3 grid(N / 128, M / 128, batch);
        if (rndA)
            tgemm_k<128, 1><<<grid, 256, GSMEM128>>>(A, B, C, M, N, K, ldC, sA, sB, sC,
                                                     bias, res, alpha, C2, rnd);
        else
            tgemm_k<128, 0><<<grid, 256, GSMEM128>>>(A, B, C, M, N, K, ldC, sA, sB, sC,
                                                     bias, res, alpha, C2, rnd);
    } else {
        dim3 grid(N / 128, M / 64, batch);
        if (rndA)
            tgemm_k<64, 1><<<grid, 128, GSMEM64>>>(A, B, C, M, N, K, ldC, sA, sB, sC,
                                                   bias, res, alpha, C2, rnd);
        else
            tgemm_k<64, 0><<<grid, 128, GSMEM64>>>(A, B, C, M, N, K, ldC, sA, sB, sC,
                                                   bias, res, alpha, C2, rnd);
    }
}

extern "C" void kernel_launch(void* const* d_in, const int* in_sizes, int n_in,
                              void* d_out, int out_size)
{
    (void)in_sizes; (void)n_in; (void)out_size;
    const float* kpts      = (const float*)d_in[0];
    const float* desc      = (const float*)d_in[1];
    const float* posenc_Wr = (const float*)d_in[2];
    const float* sWqkv_w   = (const float*)d_in[3];
    const float* sWqkv_b   = (const float*)d_in[4];
    const float* sOut_w    = (const float*)d_in[5];
    const float* sOut_b    = (const float*)d_in[6];
    const float* sF1_w     = (const float*)d_in[7];
    const float* sF1_b     = (const float*)d_in[8];
    const float* sLN_g     = (const float*)d_in[9];
    const float* sLN_b     = (const float*)d_in[10];
    const float* sF2_w     = (const float*)d_in[11];
    const float* sF2_b     = (const float*)d_in[12];
    const float* cQK_w     = (const float*)d_in[13];
    const float* cQK_b     = (const float*)d_in[14];
    const float* cV_w      = (const float*)d_in[15];
    const float* cV_b      = (const float*)d_in[16];
    const float* cOut_w    = (const float*)d_in[17];
    const float* cOut_b    = (const float*)d_in[18];
    const float* cF1_w     = (const float*)d_in[19];
    const float* cF1_b     = (const float*)d_in[20];
    const float* cLN_g     = (const float*)d_in[21];
    const float* cLN_b     = (const float*)d_in[22];
    const float* cF2_w     = (const float*)d_in[23];
    const float* cF2_b     = (const float*)d_in[24];
    const float* fp_w      = (const float*)d_in[25];
    const float* fp_b      = (const float*)d_in[26];
    const float* match_w   = (const float*)d_in[27];
    const float* match_b   = (const float*)d_in[28];
    float* out = (float*)d_out;

    float *x, *qkv, *vb, *Q, *K, *V, *ctx, *cat, *h1, *h2, *md, *sim, *z;
    float *lser, *lsec, *rmax, *wr;
    int *m0, *m1;
    cudaGetSymbolAddress((void**)&x,    g_x);
    cudaGetSymbolAddress((void**)&qkv,  g_qkv);
    cudaGetSymbolAddress((void**)&vb,   g_vbuf);
    cudaGetSymbolAddress((void**)&Q,    g_Q);
    cudaGetSymbolAddress((void**)&K,    g_K);
    cudaGetSymbolAddress((void**)&V,    g_V);
    cudaGetSymbolAddress((void**)&ctx,  g_ctx);
    cudaGetSymbolAddress((void**)&cat,  g_cat);
    cudaGetSymbolAddress((void**)&h1,   g_h1);
    cudaGetSymbolAddress((void**)&h2,   g_h2);
    cudaGetSymbolAddress((void**)&md,   g_md);
    cudaGetSymbolAddress((void**)&sim,  g_sim);
    cudaGetSymbolAddress((void**)&z,    g_z);
    cudaGetSymbolAddress((void**)&lser, g_lser);
    cudaGetSymbolAddress((void**)&lsec, g_lsec);
    cudaGetSymbolAddress((void**)&rmax, g_rmax);
    cudaGetSymbolAddress((void**)&m0,   g_m0);
    cudaGetSymbolAddress((void**)&m1,   g_m1);
    cudaGetSymbolAddress((void**)&wr,   g_wr);

    cudaFuncSetAttribute(flash_k, cudaFuncAttributeMaxDynamicSharedMemorySize, FSMEM);
    cudaFuncSetAttribute(tgemm_k<128, 0>, cudaFuncAttributeMaxDynamicSharedMemorySize, GSMEM128);
    cudaFuncSetAttribute(tgemm_k<128, 1>, cudaFuncAttributeMaxDynamicSharedMemorySize, GSMEM128);
    cudaFuncSetAttribute(tgemm_k<64, 0>,  cudaFuncAttributeMaxDynamicSharedMemorySize, GSMEM64);
    cudaFuncSetAttribute(tgemm_k<64, 1>,  cudaFuncAttributeMaxDynamicSharedMemorySize, GSMEM64);

    // ---- pre-round all weights to tf32 (idempotent wrt in-GEMM cvt) ----
    long off = 0;
    auto prep = [&](const float* src, long n) -> float* {
        float* d = wr + off; off += n;
        roundw4_k<<<(int)((n / 4 + 255) / 256), 256>>>((const float4*)src, (float4*)d,
                                                       (int)(n / 4));
        return d;
    };
    float* rsWqkv = prep(sWqkv_w, (long)LGL * 3 * LGD * LGD);
    float* rsOut  = prep(sOut_w,  (long)LGL * LGD * LGD);
    float* rsF1   = prep(sF1_w,   (long)LGL * 4 * LGD * LGD);
    float* rsF2   = prep(sF2_w,   (long)LGL * 2 * LGD * LGD);
    float* rcQK   = prep(cQK_w,   (long)LGL * LGD * LGD);
    float* rcV    = prep(cV_w,    (long)LGL * LGD * LGD);
    float* rcOut  = prep(cOut_w,  (long)LGL * LGD * LGD);
    float* rcF1   = prep(cF1_w,   (long)LGL * 4 * LGD * LGD);
    float* rcF2   = prep(cF2_w,   (long)LGL * 2 * LGD * LGD);
    float* rfp    = prep(fp_w,    (long)LGD * LGD);

    const long sSS = (long)LGN * LGN;

    copy2_k<<<(M4 * LGD + 255) / 256, 256>>>(desc, x, cat);

    for (int i = 0; i < LGL; i++) {
        // ---------------- self attention ----------------
        // A = x (fp32) -> cvt at read
        tgemm(x, rsWqkv + (long)i * 3 * LGD * LGD, qkv, M4, 3 * LGD, LGD, 3 * LGD,
              0, 0, 0, 1, sWqkv_b + (long)i * 3 * LGD, nullptr, 1.0f, nullptr, 0, 1);
        rope_split_k<<<(LGB * LGN * 128 + 255) / 256, 256>>>(qkv, kpts, posenc_Wr, Q, K, V);
        flash_k<<<dim3(16, BH), 128, FSMEM>>>(Q, K, V, ctx, 0);
        // A = ctx (pre-rounded); C -> cat-right, rounded (only feeds F1)
        tgemm(ctx, rsOut + (long)i * LGD * LGD, cat + LGD, M4, LGD, LGD, 2 * LGD,
              0, 0, 0, 1, sOut_b + (long)i * LGD, nullptr, 1.0f, nullptr, 1, 0);
        // A = cat (pre-rounded)
        tgemm(cat, rsF1 + (long)i * 4 * LGD * LGD, h1, M4, 2 * LGD, 2 * LGD, 2 * LGD,
              0, 0, 0, 1, sF1_b + (long)i * 2 * LGD, nullptr, 1.0f, nullptr, 0, 0);
        lngelu_k<<<M4, 256>>>(h1, sLN_g + (long)i * 2 * LGD, sLN_b + (long)i * 2 * LGD, h2);
        // A = h2 (pre-rounded); C = x fp32 (no round), C2 = cat-left rounded
        tgemm(h2, rsF2 + (long)i * 2 * LGD * LGD, x, M4, LGD, 2 * LGD, LGD,
              0, 0, 0, 1, sF2_b + (long)i * LGD, x, 1.0f, cat, 2, 0);

        // ---------------- cross attention ----------------
        tgemm(x, rcQK + (long)i * LGD * LGD, qkv, M4, LGD, LGD, LGD,
              0, 0, 0, 1, cQK_b + (long)i * LGD, nullptr, 1.0f, nullptr, 0, 1);
        tgemm(x, rcV + (long)i * LGD * LGD, vb, M4, LGD, LGD, LGD,
              0, 0, 0, 1, cV_b + (long)i * LGD, nullptr, 1.0f, nullptr, 0, 1);
        split_heads_k<<<(M4 * LGD + 255) / 256, 256>>>(qkv, vb, Q, V);
        flash_k<<<dim3(16, BH), 128, FSMEM>>>(Q, Q, V, ctx, 4);
        tgemm(ctx, rcOut + (long)i * LGD * LGD, cat + LGD, M4, LGD, LGD, 2 * LGD,
              0, 0, 0, 1, cOut_b + (long)i * LGD, nullptr, 1.0f, nullptr, 1, 0);
        tgemm(cat, rcF1 + (long)i * 4 * LGD * LGD, h1, M4, 2 * LGD, 2 * LGD, 2 * LGD,
              0, 0, 0, 1, cF1_b + (long)i * 2 * LGD, nullptr, 1.0f, nullptr, 0, 0);
        lngelu_k<<<M4, 256>>>(h1, cLN_g + (long)i * 2 * LGD, cLN_b + (long)i * 2 * LGD, h2);
        tgemm(h2, rcF2 + (long)i * 2 * LGD * LGD, x, M4, LGD, 2 * LGD, LGD,
              0, 0, 0, 1, cF2_b + (long)i * LGD, x, 1.0f, cat, 2, 0);
    }

    // ---------------- matching head ----------------
    // md rounded at store (only feeds sim, both operands)
    tgemm(x, rfp, md, M4, LGD, LGD, LGD, 0, 0, 0, 1, fp_b, nullptr, 0.25f,
          nullptr, 1, 1);
    tgemm(md, md + (long)LGN * LGD, sim, LGN, LGN, LGD, LGN,
          (long)2 * LGN * LGD, (long)2 * LGN * LGD, sSS, 2, nullptr, nullptr, 1.0f,
          nullptr, 0, 0);
    z_k<<<M4, 256>>>(x, match_w, match_b, z);
    lse_row_k<<<2 * LGN, 256>>>(sim, lser);
    lse_col_k<<<64, 256>>>(sim, lsec);
    scores_k<<<(NN2 + 255) / 256, 256>>>(sim, lser, lsec, z, out);

    // ---------------- filter (batch 0 only) ----------------
    argmax_row_k<<<LGN, 256>>>(out, rmax, m0);
    argmax_col_k<<<32, 256>>>(out, m1);
    filter_k<<<1, 1024>>>(m0, m1, rmax, out);
}

// round 8
// speedup vs baseline: 2.8649x; 1.0534x over previous
#include <cuda_runtime.h>
#include <cuda_bf16.h>
#include <math.h>
#include <stdint.h>

// ---------------------------------------------------------------------------
// LightGlue forward. L=9, D=256, H=4, HD=64, N=1024, B=4 (2 pairs).
// tf32 mma dense GEMMs with fused RoPE-split / head-split epilogues.
// ---------------------------------------------------------------------------

#define LGB   4
#define LGN   1024
#define LGD   256
#define LGH   4
#define LGHD  64
#define LGL   9
#define M4    (LGB*LGN)
#define BH    (LGB*LGH)
#define NN2   (2*1024*1024)

// -------------------- scratch (device globals; no allocation) --------------
__device__ float g_x   [M4*LGD];
__device__ float g_Q   [BH*LGN*LGHD];
__device__ float g_K   [BH*LGN*LGHD];
__device__ float g_V   [BH*LGN*LGHD];
__device__ float g_ctx [M4*LGD];
__device__ float g_cat [M4*2*LGD];
__device__ float g_h1  [M4*2*LGD];
__device__ float g_h2  [M4*2*LGD];
__device__ float g_md  [M4*LGD];
__device__ float g_sim [NN2];
__device__ float g_z   [M4];
__device__ float g_lser[2*LGN];
__device__ float g_lsec[2*LGN];
__device__ int   g_m0  [LGN];
__device__ int   g_m1  [LGN];
__device__ float g_rmax[LGN];
__device__ float g_wr  [11283712];        // tf32-rounded weights + biases

// -------------------- tf32 helpers -----------------------------------------
__device__ __forceinline__ uint32_t tf32u(float x) {
    uint32_t u;
    asm("cvt.rna.tf32.f32 %0, %1;" : "=r"(u) : "f"(x));
    return u;
}
__device__ __forceinline__ float tf32r(float x) { return __uint_as_float(tf32u(x)); }

__device__ __forceinline__ void mma_tf32(float (&d)[4], const uint32_t (&a)[4],
                                         const uint32_t (&b)[2]) {
    asm volatile(
        "mma.sync.aligned.m16n8k8.row.col.f32.tf32.tf32.f32 "
        "{%0,%1,%2,%3}, {%4,%5,%6,%7}, {%8,%9}, {%0,%1,%2,%3};"
        : "+f"(d[0]), "+f"(d[1]), "+f"(d[2]), "+f"(d[3])
        : "r"(a[0]), "r"(a[1]), "r"(a[2]), "r"(a[3]), "r"(b[0]), "r"(b[1]));
}

__device__ __forceinline__ void cp16(void* dst, const void* src) {
    uint32_t d = (uint32_t)__cvta_generic_to_shared(dst);
    asm volatile("cp.async.cg.shared.global [%0], [%1], 16;" :: "r"(d), "l"(src));
}
__device__ __forceinline__ void cp_commit() { asm volatile("cp.async.commit_group;"); }
template<int n> __device__ __forceinline__ void cp_wait() {
    asm volatile("cp.async.wait_group %0;" :: "n"(n));
}

// -------------------- weight prep kernels -----------------------------------
__global__ void roundw4_k(const float4* __restrict__ src, float4* __restrict__ dst,
                          int n4) {
    int i = blockIdx.x * blockDim.x + threadIdx.x;
    if (i >= n4) return;
    float4 v = src[i];
    v.x = tf32r(v.x); v.y = tf32r(v.y); v.z = tf32r(v.z); v.w = tf32r(v.w);
    dst[i] = v;
}

// qkv weight permute+round: src rows interleaved (out = 3d+sec) -> [q|k|v]
__global__ void permqkv_k(const float4* __restrict__ src, float4* __restrict__ dst) {
    int i = blockIdx.x * blockDim.x + threadIdx.x;       // LGL*768*64
    if (i >= LGL * 768 * 64) return;
    int k4 = i & 63;
    int row = (i >> 6) % 768;
    int l = i / (768 * 64);
    int sec = row >> 8, d = row & 255;
    float4 v = src[((long)l * 768 + 3 * d + sec) * 64 + k4];
    v.x = tf32r(v.x); v.y = tf32r(v.y); v.z = tf32r(v.z); v.w = tf32r(v.w);
    dst[i] = v;
}
__global__ void permqkvb_k(const float* __restrict__ src, float* __restrict__ dst) {
    int i = blockIdx.x * blockDim.x + threadIdx.x;       // LGL*768
    if (i >= LGL * 768) return;
    int row = i % 768, l = i / 768;
    int sec = row >> 8, d = row & 255;
    dst[i] = src[l * 768 + 3 * d + sec];
}

// pack cQK / cV weights into [qk|v] per layer, rounded
__global__ void pack2_k(const float4* __restrict__ a, const float4* __restrict__ b,
                        float4* __restrict__ dst) {
    int i = blockIdx.x * blockDim.x + threadIdx.x;       // LGL*512*64
    if (i >= LGL * 512 * 64) return;
    int k4 = i & 63;
    int row = (i >> 6) % 512;
    int l = i / (512 * 64);
    int sec = row >> 8, r = row & 255;
    const float4* s = sec ? b : a;
    float4 v = s[((long)l * 256 + r) * 64 + k4];
    v.x = tf32r(v.x); v.y = tf32r(v.y); v.z = tf32r(v.z); v.w = tf32r(v.w);
    dst[i] = v;
}
__global__ void pack2b_k(const float* __restrict__ a, const float* __restrict__ b,
                         float* __restrict__ dst) {
    int i = blockIdx.x * blockDim.x + threadIdx.x;       // LGL*512
    if (i >= LGL * 512) return;
    int row = i % 512, l = i / 512;
    dst[i] = (row >= 256) ? b[l * 256 + row - 256] : a[l * 256 + row];
}

// -------------------- dense tf32 GEMM (NT only) -----------------------------
// B pre-rounded. A pre-rounded iff RNDA==0.
// EPI=0: normal epilogue (C, optional C2, rnd).  alpha/res supported.
// EPI=1: qkv+RoPE epilogue -> writes Qo/Ko/Vo split-head, tf32-rounded.
// EPI=2: packed qk|v epilogue -> writes Qo/Vo split-head, tf32-rounded.
#define GSTR 36

template<int BM, int RNDA, int EPI>
__global__ void __launch_bounds__(BM * 2, (BM == 128) ? 2 : 3) tgemm_k(
    const float* __restrict__ A, const float* __restrict__ B, float* C,
    int M, int N, int K, int ldC,
    long sA, long sB, long sC,
    const float* __restrict__ bias, const float* res, float alpha,
    float* C2, int rnd,
    float* Qo, float* Ko, float* Vo,
    const float* __restrict__ kpts, const float* __restrict__ Wr)
{
    constexpr int THREADS = BM * 2;
    constexpr int WCNT = (BM == 128) ? 4 : 2;
    constexpr int TM   = BM / 32;
    constexpr int TN   = 16 / WCNT;
    constexpr int ABUF = BM * GSTR;
    constexpr int BBUF = 128 * GSTR;

    extern __shared__ float sm[];
    float* As = sm;
    float* Bs = sm + 2 * ABUF;

    int bh = blockIdx.z;
    A += (long)bh * sA;
    B += (long)bh * sB;
    if (EPI == 0) {
        C += (long)bh * sC;
        if (res) res += (long)bh * sC;
    }

    const int tid  = threadIdx.x;
    const int warp = tid >> 5, lane = tid & 31;
    const int wm = warp / WCNT, wn = warp % WCNT;
    const int gid = lane >> 2, tig = lane & 3;
    const int row0 = blockIdx.y * BM;
    const int col0 = blockIdx.x * 128;

    float acc[TM][TN][4];
#pragma unroll
    for (int i = 0; i < TM; i++)
#pragma unroll
        for (int j = 0; j < TN; j++)
#pragma unroll
            for (int q = 0; q < 4; q++) acc[i][j][q] = 0.0f;

#define LOADT(s, k0) do {                                                      \
    _Pragma("unroll")                                                          \
    for (int l = 0; l < BM * 8 / THREADS; l++) {                               \
        int v = tid + THREADS * l; int r = v >> 3; int off = (v & 7) * 4;      \
        cp16(&As[(s) * ABUF + r * GSTR + off],                                 \
             &A[(long)(row0 + r) * K + (k0) + off]);                           \
    }                                                                          \
    _Pragma("unroll")                                                          \
    for (int l = 0; l < 1024 / THREADS; l++) {                                 \
        int v = tid + THREADS * l; int r = v >> 3; int off = (v & 7) * 4;      \
        cp16(&Bs[(s) * BBUF + r * GSTR + off],                                 \
             &B[(long)(col0 + r) * K + (k0) + off]);                           \
    }                                                                          \
    cp_commit(); } while (0)

    const int NK = K >> 5;
    LOADT(0, 0);

    for (int it = 0; it < NK; it++) {
        int cur = it & 1;
        cp_wait<0>();
        __syncthreads();
        if (it + 1 < NK) LOADT(cur ^ 1, (it + 1) << 5);
        const float* Ab = As + cur * ABUF;
        const float* Bb = Bs + cur * BBUF;

#pragma unroll
        for (int ks = 0; ks < 32; ks += 8) {
            uint32_t ar[TM][4];
#pragma unroll
            for (int tm = 0; tm < TM; tm++) {
                int mr = (wm * (TM * 16) + tm * 16 + gid) * GSTR;
                if (RNDA) {
                    ar[tm][0] = tf32u(Ab[mr + ks + tig]);
                    ar[tm][1] = tf32u(Ab[mr + 8 * GSTR + ks + tig]);
                    ar[tm][2] = tf32u(Ab[mr + ks + tig + 4]);
                    ar[tm][3] = tf32u(Ab[mr + 8 * GSTR + ks + tig + 4]);
                } else {
                    ar[tm][0] = __float_as_uint(Ab[mr + ks + tig]);
                    ar[tm][1] = __float_as_uint(Ab[mr + 8 * GSTR + ks + tig]);
                    ar[tm][2] = __float_as_uint(Ab[mr + ks + tig + 4]);
                    ar[tm][3] = __float_as_uint(Ab[mr + 8 * GSTR + ks + tig + 4]);
                }
            }
            uint32_t br[TN][2];
#pragma unroll
            for (int tn = 0; tn < TN; tn++) {
                int nr = (wn * (TN * 8) + tn * 8 + gid) * GSTR;
                br[tn][0] = __float_as_uint(Bb[nr + ks + tig]);
                br[tn][1] = __float_as_uint(Bb[nr + ks + tig + 4]);
            }
#pragma unroll
            for (int tm = 0; tm < TM; tm++)
#pragma unroll
                for (int tn = 0; tn < TN; tn++)
                    mma_tf32(acc[tm][tn], ar[tm], br[tn]);
        }
        __syncthreads();
    }
#undef LOADT

    if (EPI == 0) {
#pragma unroll
        for (int tm = 0; tm < TM; tm++) {
            int r0 = row0 + wm * (TM * 16) + tm * 16 + gid;
#pragma unroll
            for (int tn = 0; tn < TN; tn++) {
                int c = col0 + wn * (TN * 8) + tn * 8 + tig * 2;
                float b0 = bias ? bias[c] : 0.0f;
                float b1 = bias ? bias[c + 1] : 0.0f;
#pragma unroll
                for (int half = 0; half < 2; half++) {
                    int r = r0 + half * 8;
                    float v0 = (acc[tm][tn][half * 2 + 0] + b0) * alpha;
                    float v1 = (acc[tm][tn][half * 2 + 1] + b1) * alpha;
                    if (res) {
                        v0 += res[(long)r * ldC + c];
                        v1 += res[(long)r * ldC + c + 1];
                    }
                    float u0 = v0, u1 = v1;
                    if (rnd & 1) { v0 = tf32r(v0); v1 = tf32r(v1); }
                    *reinterpret_cast<float2*>(&C[(long)r * ldC + c]) = make_float2(v0, v1);
                    if (C2) {
                        if (rnd & 2) { u0 = tf32r(u0); u1 = tf32r(u1); }
                        else         { u0 = v0; u1 = v1; }
                        *reinterpret_cast<float2*>(&C2[(long)r * 512 + c]) = make_float2(u0, u1);
                    }
                }
            }
        }
    } else {
        // split-head (+RoPE for EPI=1) epilogue
#pragma unroll
        for (int tm = 0; tm < TM; tm++) {
            int r0 = row0 + wm * (TM * 16) + tm * 16 + gid;
#pragma unroll
            for (int tn = 0; tn < TN; tn++) {
                int c = col0 + wn * (TN * 8) + tn * 8 + tig * 2;
                int sec = c >> 8;
                int d = c & 255;
                int h = d >> 6, e = d & 63;
                float b0 = bias[c], b1 = bias[c + 1];
                float w0 = 0.0f, w1 = 0.0f;
                if (EPI == 1 && sec < 2) {
                    int f = e >> 1;
                    w0 = Wr[2 * f]; w1 = Wr[2 * f + 1];
                }
#pragma unroll
                for (int half = 0; half < 2; half++) {
                    int r = r0 + half * 8;
                    float v0 = acc[tm][tn][half * 2 + 0] + b0;
                    float v1 = acc[tm][tn][half * 2 + 1] + b1;
                    int b_ = r >> 10, n = r & (LGN - 1);
                    long base = (((long)(b_ * LGH + h)) * LGN + n) * LGHD + e;
                    if (EPI == 1) {
                        if (sec < 2) {
                            float kx = kpts[r * 2], ky = kpts[r * 2 + 1];
                            float pr = kx * w0 + ky * w1;
                            float co = cosf(pr), si = sinf(pr);
                            float* dst = (sec == 0) ? Qo : Ko;
                            dst[base]     = tf32r(co * v0 - si * v1);
                            dst[base + 1] = tf32r(co * v1 + si * v0);
                        } else {
                            Vo[base]     = tf32r(v0);
                            Vo[base + 1] = tf32r(v1);
                        }
                    } else {
                        float* dst = (sec == 0) ? Qo : Vo;
                        dst[base]     = tf32r(v0);
                        dst[base + 1] = tf32r(v1);
                    }
                }
            }
        }
    }
}

// -------------------- fused flash attention ---------------------------------
#define FKS 68
#define FVS 72
#define FKBUF (64*FKS)
#define FVBUF (64*FVS)
#define FSMEM ((2*FKBUF + 2*FVBUF + 64*FKS) * 4)   // 89088 bytes

__global__ void __launch_bounds__(128, 2) flash_k(
    const float* __restrict__ Qg, const float* __restrict__ Kg,
    const float* __restrict__ Vg, float* __restrict__ ctx, int xorB)
{
    extern __shared__ float smf[];
    float* Ksm = smf;
    float* Vsm = smf + 2 * FKBUF;
    float* Ps  = smf + 2 * FKBUF + 2 * FVBUF;

    const int bh = blockIdx.y, qt = blockIdx.x;
    const float* Qh = Qg + (long)bh * (LGN * LGHD);
    const float* Kh = Kg + (long)(bh ^ xorB) * (LGN * LGHD);
    const float* Vh = Vg + (long)(bh ^ xorB) * (LGN * LGHD);

    const int tid = threadIdx.x, warp = tid >> 5, lane = tid & 31;
    const int gid = lane >> 2, tig = lane & 3;
    const int wrow = warp * 16;

#pragma unroll
    for (int l = 0; l < 8; l++) {
        int v = tid + 128 * l;
        int r = v >> 4, c = (v & 15) * 4;
        float4 q = *(const float4*)&Qh[(long)(qt * 64 + r) * LGHD + c];
        Ps[r * FKS + c]     = 0.125f * q.x; Ps[r * FKS + c + 1] = 0.125f * q.y;
        Ps[r * FKS + c + 2] = 0.125f * q.z; Ps[r * FKS + c + 3] = 0.125f * q.w;
    }
    __syncthreads();
    uint32_t qa[8][4];
#pragma unroll
    for (int ks = 0; ks < 8; ks++) {
        int k = ks * 8;
        qa[ks][0] = __float_as_uint(Ps[(wrow + gid) * FKS + k + tig]);
        qa[ks][1] = __float_as_uint(Ps[(wrow + gid + 8) * FKS + k + tig]);
        qa[ks][2] = __float_as_uint(Ps[(wrow + gid) * FKS + k + tig + 4]);
        qa[ks][3] = __float_as_uint(Ps[(wrow + gid + 8) * FKS + k + tig + 4]);
    }

    float oacc[8][4];
#pragma unroll
    for (int nt = 0; nt < 8; nt++)
#pragma unroll
        for (int j = 0; j < 4; j++) oacc[nt][j] = 0.0f;
    float mrow0 = -INFINITY, mrow1 = -INFINITY, lrow0 = 0.0f, lrow1 = 0.0f;

#define LOADKV(s, kt) do {                                                     \
    _Pragma("unroll")                                                          \
    for (int l = 0; l < 8; l++) {                                              \
        int v = tid + 128 * l; int r = v >> 4; int c = (v & 15) * 4;           \
        cp16(&Ksm[(s) * FKBUF + r * FKS + c],                                  \
             &Kh[(long)((kt) * 64 + r) * LGHD + c]);                           \
    }                                                                          \
    _Pragma("unroll")                                                          \
    for (int l = 0; l < 8; l++) {                                              \
        int v = tid + 128 * l; int r = v >> 4; int c = (v & 15) * 4;           \
        cp16(&Vsm[(s) * FVBUF + r * FVS + c],                                  \
             &Vh[(long)((kt) * 64 + r) * LGHD + c]);                           \
    }                                                                          \
    cp_commit(); } while (0)

    LOADKV(0, 0);

    for (int kt = 0; kt < 16; kt++) {
        int cur = kt & 1;
        cp_wait<0>();
        __syncthreads();
        if (kt + 1 < 16) LOADKV(cur ^ 1, kt + 1);
        const float* K_ = Ksm + cur * FKBUF;
        const float* V_ = Vsm + cur * FVBUF;

        float sacc[8][4];
#pragma unroll
        for (int nt = 0; nt < 8; nt++)
#pragma unroll
            for (int j = 0; j < 4; j++) sacc[nt][j] = 0.0f;
#pragma unroll
        for (int ks = 0; ks < 8; ks++) {
            int k = ks * 8;
#pragma unroll
            for (int nt = 0; nt < 8; nt++) {
                uint32_t b[2];
                b[0] = __float_as_uint(K_[(nt * 8 + gid) * FKS + k + tig]);
                b[1] = __float_as_uint(K_[(nt * 8 + gid) * FKS + k + tig + 4]);
                mma_tf32(sacc[nt], qa[ks], b);
            }
        }

        float t0 = -INFINITY, t1 = -INFINITY;
#pragma unroll
        for (int nt = 0; nt < 8; nt++) {
            t0 = fmaxf(t0, fmaxf(sacc[nt][0], sacc[nt][1]));
            t1 = fmaxf(t1, fmaxf(sacc[nt][2], sacc[nt][3]));
        }
        t0 = fmaxf(t0, __shfl_xor_sync(0xffffffffu, t0, 1));
        t0 = fmaxf(t0, __shfl_xor_sync(0xffffffffu, t0, 2));
        t1 = fmaxf(t1, __shfl_xor_sync(0xffffffffu, t1, 1));
        t1 = fmaxf(t1, __shfl_xor_sync(0xffffffffu, t1, 2));
        float mn0 = fmaxf(mrow0, t0), mn1 = fmaxf(mrow1, t1);
        float al0 = __expf(mrow0 - mn0), al1 = __expf(mrow1 - mn1);
        float s0 = 0.0f, s1 = 0.0f;
#pragma unroll
        for (int nt = 0; nt < 8; nt++) {
            sacc[nt][0] = __expf(sacc[nt][0] - mn0);
            sacc[nt][1] = __expf(sacc[nt][1] - mn0);
            sacc[nt][2] = __expf(sacc[nt][2] - mn1);
            sacc[nt][3] = __expf(sacc[nt][3] - mn1);
            s0 += sacc[nt][0] + sacc[nt][1];
            s1 += sacc[nt][2] + sacc[nt][3];
        }
        s0 += __shfl_xor_sync(0xffffffffu, s0, 1);
        s0 += __shfl_xor_sync(0xffffffffu, s0, 2);
        s1 += __shfl_xor_sync(0xffffffffu, s1, 1);
        s1 += __shfl_xor_sync(0xffffffffu, s1, 2);
        lrow0 = lrow0 * al0 + s0;
        lrow1 = lrow1 * al1 + s1;
        mrow0 = mn0; mrow1 = mn1;

#pragma unroll
        for (int nt = 0; nt < 8; nt++) {
            oacc[nt][0] *= al0; oacc[nt][1] *= al0;
            oacc[nt][2] *= al1; oacc[nt][3] *= al1;
            int c = nt * 8 + 2 * tig;
            Ps[(wrow + gid) * FKS + c]         = __uint_as_float(tf32u(sacc[nt][0]));
            Ps[(wrow + gid) * FKS + c + 1]     = __uint_as_float(tf32u(sacc[nt][1]));
            Ps[(wrow + gid + 8) * FKS + c]     = __uint_as_float(tf32u(sacc[nt][2]));
            Ps[(wrow + gid + 8) * FKS + c + 1] = __uint_as_float(tf32u(sacc[nt][3]));
        }
        __syncwarp();

#pragma unroll
        for (int ks = 0; ks < 8; ks++) {
            int k = ks * 8;
            uint32_t pa[4];
            pa[0] = __float_as_uint(Ps[(wrow + gid) * FKS + k + tig]);
            pa[1] = __float_as_uint(Ps[(wrow + gid + 8) * FKS + k + tig]);
            pa[2] = __float_as_uint(Ps[(wrow + gid) * FKS + k + tig + 4]);
            pa[3] = __float_as_uint(Ps[(wrow + gid + 8) * FKS + k + tig + 4]);
#pragma unroll
            for (int nt = 0; nt < 8; nt++) {
                uint32_t b[2];
                b[0] = __float_as_uint(V_[(k + tig) * FVS + nt * 8 + gid]);
                b[1] = __float_as_uint(V_[(k + tig + 4) * FVS + nt * 8 + gid]);
                mma_tf32(oacc[nt], pa, b);
            }
        }
        __syncthreads();
    }
#undef LOADKV

    float inv0 = 1.0f / lrow0, inv1 = 1.0f / lrow1;
    int b_ = bh >> 2, h = bh & 3;
    int n0 = qt * 64 + wrow + gid;
    long base0 = ((long)(b_ * LGN + n0)) * LGD + h * 64;
    long base1 = base0 + 8L * LGD;
#pragma unroll
    for (int nt = 0; nt < 8; nt++) {
        int c = nt * 8 + 2 * tig;
        *(float2*)&ctx[base0 + c] =
            make_float2(tf32r(oacc[nt][0] * inv0), tf32r(oacc[nt][1] * inv0));
        *(float2*)&ctx[base1 + c] =
            make_float2(tf32r(oacc[nt][2] * inv1), tf32r(oacc[nt][3] * inv1));
    }
}

// -------------------- elementwise / reduction kernels ----------------------
__global__ void copy2_k(const float* __restrict__ src, float* __restrict__ x,
                        float* __restrict__ cat) {
    int i = blockIdx.x * blockDim.x + threadIdx.x;
    if (i >= M4 * LGD) return;
    float v = src[i];
    x[i] = v;
    int r = i >> 8, c = i & 255;
    cat[(long)r * 512 + c] = tf32r(v);
}

// LayerNorm(512) + exact GELU; output rounded (only consumer: F2 GEMM).
__global__ void lngelu_k(const float* __restrict__ h, const float* __restrict__ g,
                         const float* __restrict__ bb, float* __restrict__ o)
{
    long row = blockIdx.x;
    int tid = threadIdx.x;
    const float* p = h + row * 512;
    float x0 = p[tid], x1 = p[tid + 256];
    __shared__ float red[256];
    red[tid] = x0 + x1; __syncthreads();
    for (int s = 128; s > 0; s >>= 1) { if (tid < s) red[tid] += red[tid + s]; __syncthreads(); }
    float mean = red[0] * (1.0f / 512.0f);
    __syncthreads();
    red[tid] = x0 * x0 + x1 * x1; __syncthreads();
    for (int s = 128; s > 0; s >>= 1) { if (tid < s) red[tid] += red[tid + s]; __syncthreads(); }
    float var = red[0] * (1.0f / 512.0f) - mean * mean;
    float rr = rsqrtf(var + 1e-5f);
    float n0 = (x0 - mean) * rr * g[tid] + bb[tid];
    float n1 = (x1 - mean) * rr * g[tid + 256] + bb[tid + 256];
    o[row * 512 + tid]       = tf32r(0.5f * n0 * (1.0f + erff(n0 * 0.70710678118654752f)));
    o[row * 512 + tid + 256] = tf32r(0.5f * n1 * (1.0f + erff(n1 * 0.70710678118654752f)));
}

__global__ void z_k(const float* __restrict__ x, const float* __restrict__ w,
                    const float* __restrict__ b, float* __restrict__ z)
{
    long row = blockIdx.x;
    int tid = threadIdx.x;
    __shared__ float red[256];
    red[tid] = x[row * LGD + tid] * w[tid];
    __syncthreads();
    for (int s = 128; s > 0; s >>= 1) { if (tid < s) red[tid] += red[tid + s]; __syncthreads(); }
    if (tid == 0) z[row] = red[0] + b[0];
}

__global__ void lse_row_k(const float* __restrict__ sim, float* __restrict__ lser)
{
    long r = blockIdx.x;
    const float* p = sim + r * LGN;
    int tid = threadIdx.x;
    __shared__ float red[256];
    float m = -INFINITY;
    for (int j = tid; j < LGN; j += 256) m = fmaxf(m, p[j]);
    red[tid] = m; __syncthreads();
    for (int s = 128; s > 0; s >>= 1) { if (tid < s) red[tid] = fmaxf(red[tid], red[tid + s]); __syncthreads(); }
    m = red[0];
    __syncthreads();
    float sum = 0.0f;
    for (int j = tid; j < LGN; j += 256) sum += expf(p[j] - m);
    red[tid] = sum; __syncthreads();
    for (int s = 128; s > 0; s >>= 1) { if (tid < s) red[tid] += red[tid + s]; __syncthreads(); }
    if (tid == 0) lser[r] = m + logf(red[0]);
}

__global__ void lse_col_k(const float* __restrict__ sim, float* __restrict__ lsec)
{
    int cg = blockIdx.x & 31;
    int p  = blockIdx.x >> 5;
    int tid = threadIdx.x;
    int jc = (tid & 31);
    int j = cg * 32 + jc;
    int rg = tid >> 5;
    const float* base = sim + (long)p * LGN * LGN + j;
    float m = -INFINITY, s = 0.0f;
    for (int i = rg; i < LGN; i += 8) {
        float v = base[(long)i * LGN];
        if (v > m) { s = s * expf(m - v) + 1.0f; m = v; }
        else s += expf(v - m);
    }
    __shared__ float sm[8][33], ss[8][33];
    sm[rg][jc] = m; ss[rg][jc] = s;
    __syncthreads();
    if (tid < 32) {
        float M = sm[0][tid], S = ss[0][tid];
#pragma unroll
        for (int g = 1; g < 8; g++) {
            float m2 = sm[g][tid], s2 = ss[g][tid];
            if (m2 > M) { S = S * expf(M - m2) + s2; M = m2; }
            else S += s2 * expf(m2 - M);
        }
        lsec[p * LGN + cg * 32 + tid] = M + logf(S);
    }
}

__device__ __forceinline__ float lsig(float t) {
    return fminf(t, 0.0f) - log1pf(expf(-fabsf(t)));
}

__global__ void scores_k(const float* __restrict__ sim, const float* __restrict__ lser,
                         const float* __restrict__ lsec, const float* __restrict__ z,
                         float* __restrict__ out)
{
    long idx = (long)blockIdx.x * 256 + threadIdx.x;
    if (idx >= (long)NN2) return;
    int j = idx & (LGN - 1);
    long r = idx >> 10;
    int i = (int)(r & (LGN - 1));
    int p = (int)(r >> 10);
    float zq = z[(2 * p) * LGN + i];
    float zk = z[(2 * p + 1) * LGN + j];
    out[idx] = 2.0f * sim[idx] - lser[p * LGN + i] - lsec[p * LGN + j] + lsig(zq) + lsig(zk);
}

__global__ void argmax_row_k(const float* __restrict__ S, float* __restrict__ rmax,
                             int* __restrict__ m0)
{
    long i = blockIdx.x;
    const float* p = S + i * LGN;
    int tid = threadIdx.x;
    float bv = -INFINITY; int bi = 0;
    for (int j = tid; j < LGN; j += 256) {
        float v = p[j];
        if (v > bv) { bv = v; bi = j; }
    }
    __shared__ float sv[256]; __shared__ int si[256];
    sv[tid] = bv; si[tid] = bi; __syncthreads();
    for (int s = 128; s > 0; s >>= 1) {
        if (tid < s) {
            float v2 = sv[tid + s]; int i2 = si[tid + s];
            if (v2 > sv[tid] || (v2 == sv[tid] && i2 < si[tid])) { sv[tid] = v2; si[tid] = i2; }
        }
        __syncthreads();
    }
    if (tid == 0) { rmax[i] = sv[0]; m0[i] = si[0]; }
}

__global__ void argmax_col_k(const float* __restrict__ S, int* __restrict__ m1)
{
    int cg = blockIdx.x;
    int tid = threadIdx.x;
    int jc = tid & 31;
    int j = cg * 32 + jc;
    int rg = tid >> 5;
    float bv = -INFINITY; int bi = 0;
    for (int i = rg; i < LGN; i += 8) {
        float v = S[(long)i * LGN + j];
        if (v > bv || (v == bv && i < bi)) { bv = v; bi = i; }
    }
    __shared__ float sv[8][33]; __shared__ int si[8][33];
    sv[rg][jc] = bv; si[rg][jc] = bi;
    __syncthreads();
    if (tid < 32) {
        float V = sv[0][tid]; int I = si[0][tid];
#pragma unroll
        for (int g = 1; g < 8; g++) {
            float v2 = sv[g][tid]; int i2 = si[g][tid];
            if (v2 > V || (v2 == V && i2 < I)) { V = v2; I = i2; }
        }
        m1[cg * 32 + tid] = I;
    }
}

__global__ void filter_k(const int* __restrict__ m0, const int* __restrict__ m1,
                         const float* __restrict__ rmax, float* __restrict__ out)
{
    __shared__ float vals[LGN];
    __shared__ float rv[LGN];
    __shared__ int   ri[LGN];
    int n = threadIdx.x;
    float ms = expf(rmax[n]);
    bool mutual = (m1[m0[n]] == n);
    vals[n] = (mutual && ms > 0.1f) ? ms : 0.0f;
    __syncthreads();
    for (int k = 0; k < 50; k++) {
        rv[n] = vals[n]; ri[n] = n; __syncthreads();
        for (int s = 512; s > 0; s >>= 1) {
            if (n < s) {
                float v2 = rv[n + s]; int i2 = ri[n + s];
                if (v2 > rv[n] || (v2 == rv[n] && i2 < ri[n])) { rv[n] = v2; ri[n] = i2; }
            }
            __syncthreads();
        }
        if (n == 0) {
            int bi = ri[0]; float bv = rv[0];
            out[NN2 + k * 3 + 0] = 0.0f;
            out[NN2 + k * 3 + 1] = (float)bi;
            out[NN2 + k * 3 + 2] = (float)m0[bi];
            out[NN2 + 150 + k]   = bv;
            vals[bi] = -1.0f;
        }
        __syncthreads();
    }
}

// -------------------- host-side launchers ----------------------------------
#define GSMEM128 ((128 + 128) * GSTR * 2 * 4)
#define GSMEM64  ((64 + 128) * GSTR * 2 * 4)

static void tgemm(const float* A, const float* B, float* C,
                  int M, int N, int K, int ldC,
                  long sA, long sB, long sC, int batch,
                  const float* bias, const float* res, float alpha,
                  float* C2, int rnd, int rndA)
{
    if (N > 512) {
        dim3 grid(N / 128, M / 128, batch);
        if (rndA)
            tgemm_k<128, 1, 0><<<grid, 256, GSMEM128>>>(A, B, C, M, N, K, ldC, sA, sB, sC,
                bias, res, alpha, C2, rnd, nullptr, nullptr, nullptr, nullptr, nullptr);
        else
            tgemm_k<128, 0, 0><<<grid, 256, GSMEM128>>>(A, B, C, M, N, K, ldC, sA, sB, sC,
                bias, res, alpha, C2, rnd, nullptr, nullptr, nullptr, nullptr, nullptr);
    } else {
        dim3 grid(N / 128, M / 64, batch);
        if (rndA)
            tgemm_k<64, 1, 0><<<grid, 128, GSMEM64>>>(A, B, C, M, N, K, ldC, sA, sB, sC,
                bias, res, alpha, C2, rnd, nullptr, nullptr, nullptr, nullptr, nullptr);
        else
            tgemm_k<64, 0, 0><<<grid, 128, GSMEM64>>>(A, B, C, M, N, K, ldC, sA, sB, sC,
                bias, res, alpha, C2, rnd, nullptr, nullptr, nullptr, nullptr, nullptr);
    }
}

extern "C" void kernel_launch(void* const* d_in, const int* in_sizes, int n_in,
                              void* d_out, int out_size)
{
    (void)in_sizes; (void)n_in; (void)out_size;
    const float* kpts      = (const float*)d_in[0];
    const float* desc      = (const float*)d_in[1];
    const float* posenc_Wr = (const float*)d_in[2];
    const float* sWqkv_w   = (const float*)d_in[3];
    const float* sWqkv_b   = (const float*)d_in[4];
    const float* sOut_w    = (const float*)d_in[5];
    const float* sOut_b    = (const float*)d_in[6];
    const float* sF1_w     = (const float*)d_in[7];
    const float* sF1_b     = (const float*)d_in[8];
    const float* sLN_g     = (const float*)d_in[9];
    const float* sLN_b     = (const float*)d_in[10];
    const float* sF2_w     = (const float*)d_in[11];
    const float* sF2_b     = (const float*)d_in[12];
    const float* cQK_w     = (const float*)d_in[13];
    const float* cQK_b     = (const float*)d_in[14];
    const float* cV_w      = (const float*)d_in[15];
    const float* cV_b      = (const float*)d_in[16];
    const float* cOut_w    = (const float*)d_in[17];
    const float* cOut_b    = (const float*)d_in[18];
    const float* cF1_w     = (const float*)d_in[19];
    const float* cF1_b     = (const float*)d_in[20];
    const float* cLN_g     = (const float*)d_in[21];
    const float* cLN_b     = (const float*)d_in[22];
    const float* cF2_w     = (const float*)d_in[23];
    const float* cF2_b     = (const float*)d_in[24];
    const float* fp_w      = (const float*)d_in[25];
    const float* fp_b      = (const float*)d_in[26];
    const float* match_w   = (const float*)d_in[27];
    const float* match_b   = (const float*)d_in[28];
    float* out = (float*)d_out;

    float *x, *Q, *K, *V, *ctx, *cat, *h1, *h2, *md, *sim, *z;
    float *lser, *lsec, *rmax, *wr;
    int *m0, *m1;
    cudaGetSymbolAddress((void**)&x,    g_x);
    cudaGetSymbolAddress((void**)&Q,    g_Q);
    cudaGetSymbolAddress((void**)&K,    g_K);
    cudaGetSymbolAddress((void**)&V,    g_V);
    cudaGetSymbolAddress((void**)&ctx,  g_ctx);
    cudaGetSymbolAddress((void**)&cat,  g_cat);
    cudaGetSymbolAddress((void**)&h1,   g_h1);
    cudaGetSymbolAddress((void**)&h2,   g_h2);
    cudaGetSymbolAddress((void**)&md,   g_md);
    cudaGetSymbolAddress((void**)&sim,  g_sim);
    cudaGetSymbolAddress((void**)&z,    g_z);
    cudaGetSymbolAddress((void**)&lser, g_lser);
    cudaGetSymbolAddress((void**)&lsec, g_lsec);
    cudaGetSymbolAddress((void**)&rmax, g_rmax);
    cudaGetSymbolAddress((void**)&m0,   g_m0);
    cudaGetSymbolAddress((void**)&m1,   g_m1);
    cudaGetSymbolAddress((void**)&wr,   g_wr);

    cudaFuncSetAttribute(flash_k, cudaFuncAttributeMaxDynamicSharedMemorySize, FSMEM);
    cudaFuncSetAttribute(tgemm_k<128, 0, 0>, cudaFuncAttributeMaxDynamicSharedMemorySize, GSMEM128);
    cudaFuncSetAttribute(tgemm_k<128, 1, 0>, cudaFuncAttributeMaxDynamicSharedMemorySize, GSMEM128);
    cudaFuncSetAttribute(tgemm_k<128, 1, 1>, cudaFuncAttributeMaxDynamicSharedMemorySize, GSMEM128);
    cudaFuncSetAttribute(tgemm_k<64, 0, 0>,  cudaFuncAttributeMaxDynamicSharedMemorySize, GSMEM64);
    cudaFuncSetAttribute(tgemm_k<64, 1, 0>,  cudaFuncAttributeMaxDynamicSharedMemorySize, GSMEM64);
    cudaFuncSetAttribute(tgemm_k<64, 1, 2>,  cudaFuncAttributeMaxDynamicSharedMemorySize, GSMEM64);

    // ---- weight prep: rounded (and permuted/packed) copies ----
    long off = 0;
    auto prep = [&](const float* src, long n) -> float* {
        float* d = wr + off; off += n;
        roundw4_k<<<(int)((n / 4 + 255) / 256), 256>>>((const float4*)src, (float4*)d,
                                                       (int)(n / 4));
        return d;
    };
    // permuted qkv weight [q|k|v]
    float* rqkvW = wr + off; off += (long)LGL * 768 * LGD;
    permqkv_k<<<(LGL * 768 * 64 + 255) / 256, 256>>>((const float4*)sWqkv_w,
                                                     (float4*)rqkvW);
    float* rsOut  = prep(sOut_w,  (long)LGL * LGD * LGD);
    float* rsF1   = prep(sF1_w,   (long)LGL * 4 * LGD * LGD);
    float* rsF2   = prep(sF2_w,   (long)LGL * 2 * LGD * LGD);
    // packed cross qk|v weight
    float* rcqkvW = wr + off; off += (long)LGL * 512 * LGD;
    pack2_k<<<(LGL * 512 * 64 + 255) / 256, 256>>>((const float4*)cQK_w,
                                                   (const float4*)cV_w,
                                                   (float4*)rcqkvW);
    float* rcOut  = prep(cOut_w,  (long)LGL * LGD * LGD);
    float* rcF1   = prep(cF1_w,   (long)LGL * 4 * LGD * LGD);
    float* rcF2   = prep(cF2_w,   (long)LGL * 2 * LGD * LGD);
    float* rfp    = prep(fp_w,    (long)LGD * LGD);
    // permuted / packed biases (raw fp32)
    float* rqkvB = wr + off; off += (long)LGL * 768;
    permqkvb_k<<<(LGL * 768 + 255) / 256, 256>>>(sWqkv_b, rqkvB);
    float* rcqkvB = wr + off; off += (long)LGL * 512;
    pack2b_k<<<(LGL * 512 + 255) / 256, 256>>>(cQK_b, cV_b, rcqkvB);

    const long sSS = (long)LGN * LGN;

    copy2_k<<<(M4 * LGD + 255) / 256, 256>>>(desc, x, cat);

    for (int i = 0; i < LGL; i++) {
        // ---------------- self attention ----------------
        // fused qkv GEMM + RoPE + head-split -> Q, K, V
        {
            dim3 grid(768 / 128, M4 / 128, 1);
            tgemm_k<128, 1, 1><<<grid, 256, GSMEM128>>>(
                x, rqkvW + (long)i * 768 * LGD, nullptr, M4, 768, LGD, 0,
                0, 0, 0, rqkvB + (long)i * 768, nullptr, 1.0f, nullptr, 0,
                Q, K, V, kpts, posenc_Wr);
        }
        flash_k<<<dim3(16, BH), 128, FSMEM>>>(Q, K, V, ctx, 0);
        tgemm(ctx, rsOut + (long)i * LGD * LGD, cat + LGD, M4, LGD, LGD, 2 * LGD,
              0, 0, 0, 1, sOut_b + (long)i * LGD, nullptr, 1.0f, nullptr, 1, 0);
        tgemm(cat, rsF1 + (long)i * 4 * LGD * LGD, h1, M4, 2 * LGD, 2 * LGD, 2 * LGD,
              0, 0, 0, 1, sF1_b + (long)i * 2 * LGD, nullptr, 1.0f, nullptr, 0, 0);
        lngelu_k<<<M4, 256>>>(h1, sLN_g + (long)i * 2 * LGD, sLN_b + (long)i * 2 * LGD, h2);
        tgemm(h2, rsF2 + (long)i * 2 * LGD * LGD, x, M4, LGD, 2 * LGD, LGD,
              0, 0, 0, 1, sF2_b + (long)i * LGD, x, 1.0f, cat, 2, 0);

        // ---------------- cross attention ----------------
        // fused packed qk|v GEMM + head-split -> Q, V
        {
            dim3 grid(512 / 128, M4 / 64, 1);
            tgemm_k<64, 1, 2><<<grid, 128, GSMEM64>>>(
                x, rcqkvW + (long)i * 512 * LGD, nullptr, M4, 512, LGD, 0,
                0, 0, 0, rcqkvB + (long)i * 512, nullptr, 1.0f, nullptr, 0,
                Q, nullptr, V, nullptr, nullptr);
        }
        flash_k<<<dim3(16, BH), 128, FSMEM>>>(Q, Q, V, ctx, 4);
        tgemm(ctx, rcOut + (long)i * LGD * LGD, cat + LGD, M4, LGD, LGD, 2 * LGD,
              0, 0, 0, 1, cOut_b + (long)i * LGD, nullptr, 1.0f, nullptr, 1, 0);
        tgemm(cat, rcF1 + (long)i * 4 * LGD * LGD, h1, M4, 2 * LGD, 2 * LGD, 2 * LGD,
              0, 0, 0, 1, cF1_b + (long)i * 2 * LGD, nullptr, 1.0f, nullptr, 0, 0);
        lngelu_k<<<M4, 256>>>(h1, cLN_g + (long)i * 2 * LGD, cLN_b + (long)i * 2 * LGD, h2);
        tgemm(h2, rcF2 + (long)i * 2 * LGD * LGD, x, M4, LGD, 2 * LGD, LGD,
              0, 0, 0, 1, cF2_b + (long)i * LGD, x, 1.0f, cat, 2, 0);
    }

    // ---------------- matching head ----------------
    tgemm(x, rfp, md, M4, LGD, LGD, LGD, 0, 0, 0, 1, fp_b, nullptr, 0.25f,
          nullptr, 1, 1);
    tgemm(md, md + (long)LGN * LGD, sim, LGN, LGN, LGD, LGN,
          (long)2 * LGN * LGD, (long)2 * LGN * LGD, sSS, 2, nullptr, nullptr, 1.0f,
          nullptr, 0, 0);
    z_k<<<M4, 256>>>(x, match_w, match_b, z);
    lse_row_k<<<2 * LGN, 256>>>(sim, lser);
    lse_col_k<<<64, 256>>>(sim, lsec);
    scores_k<<<(NN2 + 255) / 256, 256>>>(sim, lser, lsec, z, out);

    // ---------------- filter (batch 0 only) ----------------
    argmax_row_k<<<LGN, 256>>>(out, rmax, m0);
    argmax_col_k<<<32, 256>>>(out, m1);
    filter_k<<<1, 1024>>>(m0, m1, rmax, out);
}